// round 1
// baseline (speedup 1.0000x reference)
#include <cuda_runtime.h>
#include <cstdint>

#define BATCH 4
#define VOX   4096
#define DIM   256
#define HIDN  64
#define KNN_N 10
#define TOPK_N 4
#define GTOT  (BATCH*VOX)   // 16384

// ---------------- device scratch (single symbol, offsets) ----------------
// floats:
//  A    : tok@W1a + b1          [16384*64]       off 0
//  B    : tok@W1b               [16384*64]       off 1048576
//  Q    : tok@Wq + bq           [16384*256]      off 2097152
//  K    : tok@Wk + bk           [16384*256]      off 6291456
//  V    : tok@Wv + bv           [16384*256]      off 10485760
//  ctx  : attention output      [16384*256]      off 14680064
//  knn  : int [16384*10]                         off 18874368
//  sel  : int [16384*4]                          off 19038208
#define OFF_A    0
#define OFF_B    1048576
#define OFF_Q    2097152
#define OFF_K    6291456
#define OFF_V    10485760
#define OFF_CTX  14680064
#define OFF_KNN  18874368
#define OFF_SEL  19038208
#define BUF_TOTAL 19103744

static __device__ float g_buf[BUF_TOTAL];

// ---------------- KNN kernel ----------------
// grid: (64, 4) blocks, 256 threads. Block handles 64 rows of one batch,
// one warp handles 8 rows. Coords staged in smem (48KB).
__global__ void knn_kernel(const float* __restrict__ coords, int* __restrict__ knn_out) {
    __shared__ float sx[VOX], sy[VOX], sz[VOX];
    const int b = blockIdx.y;
    const float* coo = coords + (size_t)b * VOX * 3;
    for (int j = threadIdx.x; j < VOX; j += blockDim.x) {
        sx[j] = coo[3*j+0];
        sy[j] = coo[3*j+1];
        sz[j] = coo[3*j+2];
    }
    __syncthreads();

    const int warp = threadIdx.x >> 5;
    const int lane = threadIdx.x & 31;

    for (int r = 0; r < 8; r++) {
        const int i = blockIdx.x * 64 + warp * 8 + r;
        const float xi = sx[i], yi = sy[i], zi = sz[i];
        const float sqi = xi*xi + yi*yi + zi*zi;

        float ld[KNN_N];
        int   li[KNN_N];
#pragma unroll
        for (int k = 0; k < KNN_N; k++) { ld[k] = 1e30f; li[k] = 0x7fffffff; }

        for (int j = lane; j < VOX; j += 32) {
            const float xj = sx[j], yj = sy[j], zj = sz[j];
            const float sqj = xj*xj + yj*yj + zj*zj;
            const float dot = xi*xj + yi*yj + zi*zj;
            const float d = sqi + sqj - 2.0f * dot;
            if (j == i) continue;
            if (d < ld[KNN_N-1] || (d == ld[KNN_N-1] && j < li[KNN_N-1])) {
                float cd = d; int ci = j;
#pragma unroll
                for (int k = 0; k < KNN_N; k++) {
                    const bool better = (cd < ld[k]) || (cd == ld[k] && ci < li[k]);
                    const float td = better ? ld[k] : cd;
                    const int   ti = better ? li[k] : ci;
                    ld[k] = better ? cd : ld[k];
                    li[k] = better ? ci : li[k];
                    cd = td; ci = ti;
                }
            }
        }

        // warp merge: 10 rounds of argmin + shift-down in the winning lane
        const int out_base = ((b << 12) + i) * KNN_N;
        for (int rr = 0; rr < KNN_N; rr++) {
            const float myd = ld[0];
            const int   myi = li[0];
            float bd = myd; int bi = myi;
#pragma unroll
            for (int off = 16; off; off >>= 1) {
                const float od = __shfl_xor_sync(0xffffffffu, bd, off);
                const int   oi = __shfl_xor_sync(0xffffffffu, bi, off);
                if (od < bd || (od == bd && oi < bi)) { bd = od; bi = oi; }
            }
            if (bi == myi && bd == myd) {  // unique winner (indices unique per lane)
#pragma unroll
                for (int k = 0; k < KNN_N-1; k++) { ld[k] = ld[k+1]; li[k] = li[k+1]; }
                ld[KNN_N-1] = 1e30f; li[KNN_N-1] = 0x7fffffff;
            }
            if (lane == 0) knn_out[out_base + rr] = bi;
        }
    }
}

// ---------------- generic fp32 GEMM: C[M,N] = A[M,K] @ W[K,N](ld=ldw) + bias ----------------
// tile 128x64, 256 threads, micro-tile 8x4, K-step 16. M%128==0, N%64==0, K%16==0.
__global__ void gemm_kernel(const float* __restrict__ A, const float* __restrict__ W,
                            const float* __restrict__ bias, float* __restrict__ C,
                            int K, int N, int ldw) {
    __shared__ float As[16][132];   // padded
    __shared__ float Bs[16][64];

    const int t  = threadIdx.x;
    const int tx = t & 15;
    const int ty = t >> 4;
    const int m0 = blockIdx.x * 128;
    const int n0 = blockIdx.y * 64;

    float acc[8][4];
#pragma unroll
    for (int i = 0; i < 8; i++)
#pragma unroll
        for (int j = 0; j < 4; j++) acc[i][j] = 0.0f;

    const float* Ab = A + (size_t)m0 * K;

    for (int k0 = 0; k0 < K; k0 += 16) {
        // load A tile: 128 rows x 16 k
        {
            const int kq = (t & 3) * 4;
            const int m  = t >> 2;           // 0..63
            float4 v  = *(const float4*)(Ab + (size_t)m * K + k0 + kq);
            As[kq+0][m] = v.x; As[kq+1][m] = v.y; As[kq+2][m] = v.z; As[kq+3][m] = v.w;
            float4 v2 = *(const float4*)(Ab + (size_t)(m + 64) * K + k0 + kq);
            As[kq+0][m+64] = v2.x; As[kq+1][m+64] = v2.y; As[kq+2][m+64] = v2.z; As[kq+3][m+64] = v2.w;
        }
        // load B tile: 16 k x 64 n
        {
            const int k = t >> 4;            // 0..15
            const int n = (t & 15) * 4;
            *(float4*)&Bs[k][n] = *(const float4*)(W + (size_t)(k0 + k) * ldw + n0 + n);
        }
        __syncthreads();

#pragma unroll
        for (int k = 0; k < 16; k++) {
            float ra[8], rb[4];
            float4 a0 = *(const float4*)&As[k][ty*8];
            float4 a1 = *(const float4*)&As[k][ty*8+4];
            ra[0]=a0.x; ra[1]=a0.y; ra[2]=a0.z; ra[3]=a0.w;
            ra[4]=a1.x; ra[5]=a1.y; ra[6]=a1.z; ra[7]=a1.w;
            float4 b4 = *(const float4*)&Bs[k][tx*4];
            rb[0]=b4.x; rb[1]=b4.y; rb[2]=b4.z; rb[3]=b4.w;
#pragma unroll
            for (int i = 0; i < 8; i++)
#pragma unroll
                for (int j = 0; j < 4; j++)
                    acc[i][j] += ra[i] * rb[j];
        }
        __syncthreads();
    }

    float4 bv = make_float4(0.f, 0.f, 0.f, 0.f);
    if (bias) bv = *(const float4*)(bias + n0 + tx*4);
#pragma unroll
    for (int i = 0; i < 8; i++) {
        const int row = m0 + ty*8 + i;
        float4 o;
        o.x = acc[i][0] + bv.x;
        o.y = acc[i][1] + bv.y;
        o.z = acc[i][2] + bv.z;
        o.w = acc[i][3] + bv.w;
        *(float4*)(C + (size_t)row * N + n0 + tx*4) = o;
    }
}

// ---------------- score + top-4 select ----------------
// warp per voxel; grid 2048 x 256 threads
__global__ void score_kernel(const float* __restrict__ coords,
                             const float* __restrict__ W1,   // [515,64]
                             const float* __restrict__ W2,   // [64,1]
                             const int* __restrict__ knn,
                             const float* __restrict__ gA,
                             const float* __restrict__ gB,
                             int* __restrict__ sel) {
    __shared__ float sW1c[3][64];
    __shared__ float sW2[64];
    const int t = threadIdx.x;
    if (t < 64) {
        sW2[t]     = W2[t];
        sW1c[0][t] = W1[512*64 + t];
        sW1c[1][t] = W1[513*64 + t];
        sW1c[2][t] = W1[514*64 + t];
    }
    __syncthreads();

    const int warp = t >> 5, lane = t & 31;
    const int g = blockIdx.x * 8 + warp;           // 0..16383
    const int b = g >> 12;
    const int i = g & 4095;
    const float* coo = coords + (size_t)b * VOX * 3;
    const float xi = coo[3*i+0], yi = coo[3*i+1], zi = coo[3*i+2];

    const float a0  = gA[(size_t)g*64 + lane];
    const float a1  = gA[(size_t)g*64 + lane + 32];
    const float w2a = sW2[lane], w2b = sW2[lane + 32];
    const float c0a = sW1c[0][lane], c0b = sW1c[0][lane+32];
    const float c1a = sW1c[1][lane], c1b = sW1c[1][lane+32];
    const float c2a = sW1c[2][lane], c2b = sW1c[2][lane+32];

    float bs[TOPK_N] = {-1e30f, -1e30f, -1e30f, -1e30f};
    int   bp[TOPK_N] = {0, 0, 0, 0};

    for (int nb = 0; nb < KNN_N; nb++) {
        const int j = knn[g*KNN_N + nb];
        const float rx = coo[3*j+0] - xi;
        const float ry = coo[3*j+1] - yi;
        const float rz = coo[3*j+2] - zi;
        const float* Bj = gB + ((size_t)(b << 12) + j) * 64;
        float h0 = a0 + Bj[lane]      + rx*c0a + ry*c1a + rz*c2a;
        float h1 = a1 + Bj[lane + 32] + rx*c0b + ry*c1b + rz*c2b;
        h0 = fmaxf(h0, 0.0f);
        h1 = fmaxf(h1, 0.0f);
        float p = h0 * w2a + h1 * w2b;
#pragma unroll
        for (int off = 16; off; off >>= 1) p += __shfl_xor_sync(0xffffffffu, p, off);
        // insert (p, nb), descending, strict > (later ties lose, matching top_k)
        float cs = p; int cp = nb;
#pragma unroll
        for (int k = 0; k < TOPK_N; k++) {
            const bool better = cs > bs[k];
            const float ts = better ? bs[k] : cs;
            const int   tp = better ? bp[k] : cp;
            bs[k] = better ? cs : bs[k];
            bp[k] = better ? cp : bp[k];
            cs = ts; cp = tp;
        }
    }
    if (lane == 0) {
#pragma unroll
        for (int r = 0; r < TOPK_N; r++)
            sel[g*TOPK_N + r] = (b << 12) + knn[g*KNN_N + bp[r]];   // global token index
    }
}

// ---------------- attention (4 heads x 4 neighbors) ----------------
// warp per voxel, lane l handles channels [8l, 8l+8); head = l/8
__global__ void attn_kernel(const int* __restrict__ sel,
                            const float* __restrict__ gQ,
                            const float* __restrict__ gK,
                            const float* __restrict__ gV,
                            float* __restrict__ gctx) {
    const int t = threadIdx.x;
    const int warp = t >> 5, lane = t & 31;
    const int g = blockIdx.x * 8 + warp;
    const size_t base = (size_t)g * DIM + lane * 8;

    const float4 q0 = *(const float4*)(gQ + base);
    const float4 q1 = *(const float4*)(gQ + base + 4);

    int js[TOPK_N];
    float att[TOPK_N];
#pragma unroll
    for (int s = 0; s < TOPK_N; s++) {
        js[s] = sel[g*TOPK_N + s];
        const float4* Kp = (const float4*)(gK + (size_t)js[s] * DIM + lane * 8);
        const float4 k0 = Kp[0], k1 = Kp[1];
        float p = q0.x*k0.x + q0.y*k0.y + q0.z*k0.z + q0.w*k0.w
                + q1.x*k1.x + q1.y*k1.y + q1.z*k1.z + q1.w*k1.w;
        // reduce over the 8 lanes of this head
        p += __shfl_xor_sync(0xffffffffu, p, 4);
        p += __shfl_xor_sync(0xffffffffu, p, 2);
        p += __shfl_xor_sync(0xffffffffu, p, 1);
        att[s] = p * 0.125f;    // 1/sqrt(64)
    }
    float m = fmaxf(fmaxf(att[0], att[1]), fmaxf(att[2], att[3]));
    float e[TOPK_N], ssum = 0.0f;
#pragma unroll
    for (int s = 0; s < TOPK_N; s++) { e[s] = expf(att[s] - m); ssum += e[s]; }
    const float inv = 1.0f / ssum;

    float4 c0 = make_float4(0.f,0.f,0.f,0.f);
    float4 c1 = make_float4(0.f,0.f,0.f,0.f);
#pragma unroll
    for (int s = 0; s < TOPK_N; s++) {
        const float w = e[s] * inv;
        const float4* Vp = (const float4*)(gV + (size_t)js[s] * DIM + lane * 8);
        const float4 v0 = Vp[0], v1 = Vp[1];
        c0.x += w*v0.x; c0.y += w*v0.y; c0.z += w*v0.z; c0.w += w*v0.w;
        c1.x += w*v1.x; c1.y += w*v1.y; c1.z += w*v1.z; c1.w += w*v1.w;
    }
    *(float4*)(gctx + base)     = c0;
    *(float4*)(gctx + base + 4) = c1;
}

// ---------------- launch ----------------
extern "C" void kernel_launch(void* const* d_in, const int* in_sizes, int n_in,
                              void* d_out, int out_size) {
    const float* tok    = (const float*)d_in[0];
    const float* coords = (const float*)d_in[1];
    // d_in[2] = mask (unused by reference)
    const float* W1 = (const float*)d_in[3];
    const float* b1 = (const float*)d_in[4];
    const float* W2 = (const float*)d_in[5];
    // d_in[6] = b2 (shift-invariant for selection; unused)
    const float* Wq = (const float*)d_in[7];
    const float* bq = (const float*)d_in[8];
    const float* Wk = (const float*)d_in[9];
    const float* bk = (const float*)d_in[10];
    const float* Wv = (const float*)d_in[11];
    const float* bv = (const float*)d_in[12];
    const float* Wo = (const float*)d_in[13];
    const float* bo = (const float*)d_in[14];
    float* out = (float*)d_out;

    void* bufp = nullptr;
    cudaGetSymbolAddress(&bufp, g_buf);
    float* buf = (float*)bufp;
    float* gA   = buf + OFF_A;
    float* gB   = buf + OFF_B;
    float* gQ   = buf + OFF_Q;
    float* gK   = buf + OFF_K;
    float* gV   = buf + OFF_V;
    float* gctx = buf + OFF_CTX;
    int*   gknn = (int*)(buf + OFF_KNN);
    int*   gsel = (int*)(buf + OFF_SEL);

    knn_kernel<<<dim3(64, 4), 256>>>(coords, gknn);

    // A = tok @ W1[0:256] + b1 ; B = tok @ W1[256:512]
    gemm_kernel<<<dim3(GTOT/128, 1), 256>>>(tok, W1,            b1,      gA, DIM, HIDN, HIDN);
    gemm_kernel<<<dim3(GTOT/128, 1), 256>>>(tok, W1 + 256*HIDN, nullptr, gB, DIM, HIDN, HIDN);

    gemm_kernel<<<dim3(GTOT/128, DIM/64), 256>>>(tok, Wq, bq, gQ, DIM, DIM, DIM);
    gemm_kernel<<<dim3(GTOT/128, DIM/64), 256>>>(tok, Wk, bk, gK, DIM, DIM, DIM);
    gemm_kernel<<<dim3(GTOT/128, DIM/64), 256>>>(tok, Wv, bv, gV, DIM, DIM, DIM);

    score_kernel<<<GTOT/8, 256>>>(coords, W1, W2, gknn, gA, gB, gsel);
    attn_kernel<<<GTOT/8, 256>>>(gsel, gQ, gK, gV, gctx);

    gemm_kernel<<<dim3(GTOT/128, DIM/64), 256>>>(gctx, Wo, bo, out, DIM, DIM, DIM);
}

// round 2
// speedup vs baseline: 1.0280x; 1.0280x over previous
#include <cuda_runtime.h>
#include <cstdint>

#define BATCH 4
#define VOX   4096
#define DIM   256
#define HIDN  64
#define KNN_N 10
#define TOPK_N 4
#define GTOT  (BATCH*VOX)   // 16384

// ---------------- device scratch ----------------
#define OFF_A    0
#define OFF_B    1048576
#define OFF_Q    2097152
#define OFF_K    6291456
#define OFF_V    10485760
#define OFF_CTX  14680064
#define OFF_KNN  18874368
#define BUF_TOTAL 19038208

static __device__ float g_buf[BUF_TOTAL];

// ---------------- KNN kernel ----------------
__global__ void knn_kernel(const float* __restrict__ coords, int* __restrict__ knn_out) {
    __shared__ float sx[VOX], sy[VOX], sz[VOX];
    const int b = blockIdx.y;
    const float* coo = coords + (size_t)b * VOX * 3;
    for (int j = threadIdx.x; j < VOX; j += blockDim.x) {
        sx[j] = coo[3*j+0];
        sy[j] = coo[3*j+1];
        sz[j] = coo[3*j+2];
    }
    __syncthreads();

    const int warp = threadIdx.x >> 5;
    const int lane = threadIdx.x & 31;

    for (int r = 0; r < 8; r++) {
        const int i = blockIdx.x * 64 + warp * 8 + r;
        const float xi = sx[i], yi = sy[i], zi = sz[i];
        const float sqi = xi*xi + yi*yi + zi*zi;

        float ld[KNN_N];
        int   li[KNN_N];
#pragma unroll
        for (int k = 0; k < KNN_N; k++) { ld[k] = 1e30f; li[k] = 0x7fffffff; }

        for (int j = lane; j < VOX; j += 32) {
            const float xj = sx[j], yj = sy[j], zj = sz[j];
            const float sqj = xj*xj + yj*yj + zj*zj;
            const float dot = xi*xj + yi*yj + zi*zj;
            float d = sqi + sqj - 2.0f * dot;
            if (j == i) d = 1e30f;
            if (d < ld[KNN_N-1] || (d == ld[KNN_N-1] && j < li[KNN_N-1])) {
                float cd = d; int ci = j;
#pragma unroll
                for (int k = 0; k < KNN_N; k++) {
                    const bool better = (cd < ld[k]) || (cd == ld[k] && ci < li[k]);
                    const float td = better ? ld[k] : cd;
                    const int   ti = better ? li[k] : ci;
                    ld[k] = better ? cd : ld[k];
                    li[k] = better ? ci : li[k];
                    cd = td; ci = ti;
                }
            }
        }

        const int out_base = ((b << 12) + i) * KNN_N;
        for (int rr = 0; rr < KNN_N; rr++) {
            const float myd = ld[0];
            const int   myi = li[0];
            float bd = myd; int bi = myi;
#pragma unroll
            for (int off = 16; off; off >>= 1) {
                const float od = __shfl_xor_sync(0xffffffffu, bd, off);
                const int   oi = __shfl_xor_sync(0xffffffffu, bi, off);
                if (od < bd || (od == bd && oi < bi)) { bd = od; bi = oi; }
            }
            if (bi == myi && bd == myd) {
#pragma unroll
                for (int k = 0; k < KNN_N-1; k++) { ld[k] = ld[k+1]; li[k] = li[k+1]; }
                ld[KNN_N-1] = 1e30f; li[KNN_N-1] = 0x7fffffff;
            }
            if (lane == 0) knn_out[out_base + rr] = bi;
        }
    }
}

// ---------------- fp32 GEMM, register-staged double buffer ----------------
// C[M,N] = A[M,K] @ W[K,N](ld=ldw) + bias ; tile 128x64, 256 thr, micro 8x4
__global__ void __launch_bounds__(256) gemm_kernel(
        const float* __restrict__ A, const float* __restrict__ W,
        const float* __restrict__ bias, float* __restrict__ C,
        int K, int N, int ldw) {
    __shared__ float As[16][132];
    __shared__ float Bs[16][64];

    const int t  = threadIdx.x;
    const int tx = t & 15;
    const int ty = t >> 4;
    const int m0 = blockIdx.x * 128;
    const int n0 = blockIdx.y * 64;

    // staging coords
    const int kq = (t & 3) * 4;    // A: k quad
    const int ma = t >> 2;         // A: row 0..63 (and +64)
    const int kb = t >> 4;         // B: k row 0..15
    const int nb = (t & 15) * 4;   // B: n quad

    const float* Ab = A + (size_t)m0 * K;

    // prologue load (k0 = 0)
    float4 ra0 = *(const float4*)(Ab + (size_t)ma * K + kq);
    float4 ra1 = *(const float4*)(Ab + (size_t)(ma + 64) * K + kq);
    float4 rb  = *(const float4*)(W + (size_t)kb * ldw + n0 + nb);

    float acc[8][4];
#pragma unroll
    for (int i = 0; i < 8; i++)
#pragma unroll
        for (int j = 0; j < 4; j++) acc[i][j] = 0.0f;

    for (int k0 = 0; k0 < K; k0 += 16) {
        // store staged tile
        As[kq+0][ma] = ra0.x; As[kq+1][ma] = ra0.y; As[kq+2][ma] = ra0.z; As[kq+3][ma] = ra0.w;
        As[kq+0][ma+64] = ra1.x; As[kq+1][ma+64] = ra1.y; As[kq+2][ma+64] = ra1.z; As[kq+3][ma+64] = ra1.w;
        *(float4*)&Bs[kb][nb] = rb;
        __syncthreads();

        // prefetch next tile (latency overlapped with compute below)
        if (k0 + 16 < K) {
            ra0 = *(const float4*)(Ab + (size_t)ma * K + k0 + 16 + kq);
            ra1 = *(const float4*)(Ab + (size_t)(ma + 64) * K + k0 + 16 + kq);
            rb  = *(const float4*)(W + (size_t)(k0 + 16 + kb) * ldw + n0 + nb);
        }

#pragma unroll
        for (int k = 0; k < 16; k++) {
            float ra[8], rbv[4];
            float4 a0 = *(const float4*)&As[k][ty*8];
            float4 a1 = *(const float4*)&As[k][ty*8+4];
            ra[0]=a0.x; ra[1]=a0.y; ra[2]=a0.z; ra[3]=a0.w;
            ra[4]=a1.x; ra[5]=a1.y; ra[6]=a1.z; ra[7]=a1.w;
            float4 b4 = *(const float4*)&Bs[k][tx*4];
            rbv[0]=b4.x; rbv[1]=b4.y; rbv[2]=b4.z; rbv[3]=b4.w;
#pragma unroll
            for (int i = 0; i < 8; i++)
#pragma unroll
                for (int j = 0; j < 4; j++)
                    acc[i][j] += ra[i] * rbv[j];
        }
        __syncthreads();
    }

    float4 bv = make_float4(0.f, 0.f, 0.f, 0.f);
    if (bias) bv = *(const float4*)(bias + n0 + tx*4);
#pragma unroll
    for (int i = 0; i < 8; i++) {
        const int row = m0 + ty*8 + i;
        float4 o;
        o.x = acc[i][0] + bv.x;
        o.y = acc[i][1] + bv.y;
        o.z = acc[i][2] + bv.z;
        o.w = acc[i][3] + bv.w;
        *(float4*)(C + (size_t)row * N + n0 + tx*4) = o;
    }
}

// ---------------- fused score + top-4 select + attention ----------------
// warp per voxel; grid 2048 x 256 threads
__global__ void score_attn_kernel(const float* __restrict__ coords,
                                  const float* __restrict__ W1,   // [515,64]
                                  const float* __restrict__ W2,   // [64,1]
                                  const int* __restrict__ knn,
                                  const float* __restrict__ gA,
                                  const float* __restrict__ gB,
                                  const float* __restrict__ gQ,
                                  const float* __restrict__ gK,
                                  const float* __restrict__ gV,
                                  float* __restrict__ gctx) {
    __shared__ float sW1c[3][64];
    __shared__ float sW2[64];
    const int t = threadIdx.x;
    if (t < 64) {
        sW2[t]     = W2[t];
        sW1c[0][t] = W1[512*64 + t];
        sW1c[1][t] = W1[513*64 + t];
        sW1c[2][t] = W1[514*64 + t];
    }
    __syncthreads();

    const int warp = t >> 5, lane = t & 31;
    const int g = blockIdx.x * 8 + warp;           // 0..16383
    const int b = g >> 12;
    const int i = g & 4095;
    const float* coo = coords + (size_t)b * VOX * 3;
    const float xi = coo[3*i+0], yi = coo[3*i+1], zi = coo[3*i+2];

    const float a0  = gA[(size_t)g*64 + lane];
    const float a1  = gA[(size_t)g*64 + lane + 32];
    const float w2a = sW2[lane], w2b = sW2[lane + 32];
    const float c0a = sW1c[0][lane], c0b = sW1c[0][lane+32];
    const float c1a = sW1c[1][lane], c1b = sW1c[1][lane+32];
    const float c2a = sW1c[2][lane], c2b = sW1c[2][lane+32];

    float bs[TOPK_N] = {-1e30f, -1e30f, -1e30f, -1e30f};
    int   bp[TOPK_N] = {0, 0, 0, 0};
    int nbr_idx[KNN_N];

    for (int nb = 0; nb < KNN_N; nb++) {
        const int j = knn[g*KNN_N + nb];
        nbr_idx[nb] = j;
        const float rx = coo[3*j+0] - xi;
        const float ry = coo[3*j+1] - yi;
        const float rz = coo[3*j+2] - zi;
        const float* Bj = gB + ((size_t)(b << 12) + j) * 64;
        float h0 = a0 + Bj[lane]      + rx*c0a + ry*c1a + rz*c2a;
        float h1 = a1 + Bj[lane + 32] + rx*c0b + ry*c1b + rz*c2b;
        h0 = fmaxf(h0, 0.0f);
        h1 = fmaxf(h1, 0.0f);
        float p = h0 * w2a + h1 * w2b;
#pragma unroll
        for (int off = 16; off; off >>= 1) p += __shfl_xor_sync(0xffffffffu, p, off);
        // insert (p, nb), descending, strict > (later ties lose, matching top_k)
        float cs = p; int cp = nb;
#pragma unroll
        for (int k = 0; k < TOPK_N; k++) {
            const bool better = cs > bs[k];
            const float ts = better ? bs[k] : cs;
            const int   tp = better ? bp[k] : cp;
            bs[k] = better ? cs : bs[k];
            bp[k] = better ? cp : bp[k];
            cs = ts; cp = tp;
        }
    }

    // selected global token indices (same value in all lanes: bs/bp identical per lane
    // since p was full-warp reduced)
    int js[TOPK_N];
#pragma unroll
    for (int s = 0; s < TOPK_N; s++)
        js[s] = (b << 12) + nbr_idx[bp[s]];

    // ---- attention: lane l handles channels [8l, 8l+8), head = l/8 ----
    const size_t base = (size_t)g * DIM + lane * 8;
    const float4 q0 = *(const float4*)(gQ + base);
    const float4 q1 = *(const float4*)(gQ + base + 4);

    float att[TOPK_N];
#pragma unroll
    for (int s = 0; s < TOPK_N; s++) {
        const float4* Kp = (const float4*)(gK + (size_t)js[s] * DIM + lane * 8);
        const float4 k0 = Kp[0], k1 = Kp[1];
        float p = q0.x*k0.x + q0.y*k0.y + q0.z*k0.z + q0.w*k0.w
                + q1.x*k1.x + q1.y*k1.y + q1.z*k1.z + q1.w*k1.w;
        p += __shfl_xor_sync(0xffffffffu, p, 4);
        p += __shfl_xor_sync(0xffffffffu, p, 2);
        p += __shfl_xor_sync(0xffffffffu, p, 1);
        att[s] = p * 0.125f;    // 1/sqrt(64)
    }
    float m = fmaxf(fmaxf(att[0], att[1]), fmaxf(att[2], att[3]));
    float e[TOPK_N], ssum = 0.0f;
#pragma unroll
    for (int s = 0; s < TOPK_N; s++) { e[s] = expf(att[s] - m); ssum += e[s]; }
    const float inv = 1.0f / ssum;

    float4 c0 = make_float4(0.f,0.f,0.f,0.f);
    float4 c1 = make_float4(0.f,0.f,0.f,0.f);
#pragma unroll
    for (int s = 0; s < TOPK_N; s++) {
        const float w = e[s] * inv;
        const float4* Vp = (const float4*)(gV + (size_t)js[s] * DIM + lane * 8);
        const float4 v0 = Vp[0], v1 = Vp[1];
        c0.x += w*v0.x; c0.y += w*v0.y; c0.z += w*v0.z; c0.w += w*v0.w;
        c1.x += w*v1.x; c1.y += w*v1.y; c1.z += w*v1.z; c1.w += w*v1.w;
    }
    *(float4*)(gctx + base)     = c0;
    *(float4*)(gctx + base + 4) = c1;
}

// ---------------- launch ----------------
extern "C" void kernel_launch(void* const* d_in, const int* in_sizes, int n_in,
                              void* d_out, int out_size) {
    const float* tok    = (const float*)d_in[0];
    const float* coords = (const float*)d_in[1];
    const float* W1 = (const float*)d_in[3];
    const float* b1 = (const float*)d_in[4];
    const float* W2 = (const float*)d_in[5];
    const float* Wq = (const float*)d_in[7];
    const float* bq = (const float*)d_in[8];
    const float* Wk = (const float*)d_in[9];
    const float* bk = (const float*)d_in[10];
    const float* Wv = (const float*)d_in[11];
    const float* bv = (const float*)d_in[12];
    const float* Wo = (const float*)d_in[13];
    const float* bo = (const float*)d_in[14];
    float* out = (float*)d_out;

    void* bufp = nullptr;
    cudaGetSymbolAddress(&bufp, g_buf);
    float* buf = (float*)bufp;
    float* gA   = buf + OFF_A;
    float* gB   = buf + OFF_B;
    float* gQ   = buf + OFF_Q;
    float* gK   = buf + OFF_K;
    float* gV   = buf + OFF_V;
    float* gctx = buf + OFF_CTX;
    int*   gknn = (int*)(buf + OFF_KNN);

    // launches 1-5: gemms (independent of knn)
    gemm_kernel<<<dim3(GTOT/128, 1), 256>>>(tok, W1,            b1,      gA, DIM, HIDN, HIDN);
    gemm_kernel<<<dim3(GTOT/128, 1), 256>>>(tok, W1 + 256*HIDN, nullptr, gB, DIM, HIDN, HIDN);
    gemm_kernel<<<dim3(GTOT/128, DIM/64), 256>>>(tok, Wq, bq, gQ, DIM, DIM, DIM);
    gemm_kernel<<<dim3(GTOT/128, DIM/64), 256>>>(tok, Wk, bk, gK, DIM, DIM, DIM);
    gemm_kernel<<<dim3(GTOT/128, DIM/64), 256>>>(tok, Wv, bv, gV, DIM, DIM, DIM);

    // launch 6: knn  (ncu -s 5 -c 1 captures this one)
    knn_kernel<<<dim3(64, 4), 256>>>(coords, gknn);

    // launch 7: fused score + select + attention
    score_attn_kernel<<<GTOT/8, 256>>>(coords, W1, W2, gknn, gA, gB, gQ, gK, gV, gctx);

    // launch 8: output projection
    gemm_kernel<<<dim3(GTOT/128, DIM/64), 256>>>(gctx, Wo, bo, out, DIM, DIM, DIM);
}

// round 3
// speedup vs baseline: 1.2025x; 1.1696x over previous
#include <cuda_runtime.h>
#include <cstdint>

#define BATCH 4
#define VOX   4096
#define DIM   256
#define HIDN  64
#define KNN_N 10
#define TOPK_N 4
#define GTOT  (BATCH*VOX)   // 16384

// ---------------- device scratch ----------------
#define OFF_A    0
#define OFF_B    1048576
#define OFF_Q    2097152
#define OFF_K    6291456
#define OFF_V    10485760
#define OFF_CTX  14680064
#define OFF_KNN  18874368
#define BUF_TOTAL 19038208

static __device__ float g_buf[BUF_TOTAL];

// ---------------- KNN kernel ----------------
// grid (128,4), 256 threads; warp handles 4 rows; coords staged in 48KB smem
__global__ void knn_kernel(const float* __restrict__ coords, int* __restrict__ knn_out) {
    __shared__ float sx[VOX], sy[VOX], sz[VOX];
    const int b = blockIdx.y;
    const float* coo = coords + (size_t)b * VOX * 3;
    for (int j = threadIdx.x; j < VOX; j += blockDim.x) {
        sx[j] = coo[3*j+0];
        sy[j] = coo[3*j+1];
        sz[j] = coo[3*j+2];
    }
    __syncthreads();

    const int warp = threadIdx.x >> 5;
    const int lane = threadIdx.x & 31;

    for (int r = 0; r < 4; r++) {
        const int i = blockIdx.x * 32 + warp * 4 + r;
        const float xi = sx[i], yi = sy[i], zi = sz[i];
        const float sqi = xi*xi + yi*yi + zi*zi;

        float ld[KNN_N];
        int   li[KNN_N];
#pragma unroll
        for (int k = 0; k < KNN_N; k++) { ld[k] = 1e30f; li[k] = 0x7fffffff; }

        for (int j = lane; j < VOX; j += 32) {
            const float xj = sx[j], yj = sy[j], zj = sz[j];
            const float sqj = xj*xj + yj*yj + zj*zj;
            const float dot = xi*xj + yi*yj + zi*zj;
            float d = sqi + sqj - 2.0f * dot;
            if (j == i) d = 1e30f;
            if (d < ld[KNN_N-1] || (d == ld[KNN_N-1] && j < li[KNN_N-1])) {
                float cd = d; int ci = j;
#pragma unroll
                for (int k = 0; k < KNN_N; k++) {
                    const bool better = (cd < ld[k]) || (cd == ld[k] && ci < li[k]);
                    const float td = better ? ld[k] : cd;
                    const int   ti = better ? li[k] : ci;
                    ld[k] = better ? cd : ld[k];
                    li[k] = better ? ci : li[k];
                    cd = td; ci = ti;
                }
            }
        }

        const int out_base = ((b << 12) + i) * KNN_N;
        for (int rr = 0; rr < KNN_N; rr++) {
            const float myd = ld[0];
            const int   myi = li[0];
            float bd = myd; int bi = myi;
#pragma unroll
            for (int off = 16; off; off >>= 1) {
                const float od = __shfl_xor_sync(0xffffffffu, bd, off);
                const int   oi = __shfl_xor_sync(0xffffffffu, bi, off);
                if (od < bd || (od == bd && oi < bi)) { bd = od; bi = oi; }
            }
            if (bi == myi && bd == myd) {
#pragma unroll
                for (int k = 0; k < KNN_N-1; k++) { ld[k] = ld[k+1]; li[k] = li[k+1]; }
                ld[KNN_N-1] = 1e30f; li[KNN_N-1] = 0x7fffffff;
            }
            if (lane == 0) knn_out[out_base + rr] = bi;
        }
    }
}

// ---------------- fp32 GEMM tile body: K=256 fixed, ping-pong smem ----------------
// C[.,N] tile at (blockIdx.x*128, blockIdx.y*64); 256 thr, micro 8x4
__device__ __forceinline__ void gemm_tile(const float* __restrict__ A,
        const float* __restrict__ W, const float* __restrict__ bias,
        float* __restrict__ C, int N, int ldw) {
    __shared__ float As[2][16][132];
    __shared__ float Bs[2][16][64];

    const int t  = threadIdx.x;
    const int tx = t & 15;
    const int ty = t >> 4;
    const int m0 = blockIdx.x * 128;
    const int n0 = blockIdx.y * 64;

    const int kq = (t & 3) * 4;    // A: k quad
    const int ma = t >> 2;         // A: row 0..63 (and +64)
    const int kb = t >> 4;         // B: k row 0..15
    const int nb = (t & 15) * 4;   // B: n quad

    const float* Ab = A + (size_t)m0 * 256;

    float4 ra0 = *(const float4*)(Ab + (size_t)ma * 256 + kq);
    float4 ra1 = *(const float4*)(Ab + (size_t)(ma + 64) * 256 + kq);
    float4 rb  = *(const float4*)(W + (size_t)kb * ldw + n0 + nb);

    float acc[8][4];
#pragma unroll
    for (int i = 0; i < 8; i++)
#pragma unroll
        for (int j = 0; j < 4; j++) acc[i][j] = 0.0f;

    // store first tile
    As[0][kq+0][ma] = ra0.x; As[0][kq+1][ma] = ra0.y; As[0][kq+2][ma] = ra0.z; As[0][kq+3][ma] = ra0.w;
    As[0][kq+0][ma+64] = ra1.x; As[0][kq+1][ma+64] = ra1.y; As[0][kq+2][ma+64] = ra1.z; As[0][kq+3][ma+64] = ra1.w;
    *(float4*)&Bs[0][kb][nb] = rb;
    __syncthreads();

    int cur = 0;
#pragma unroll
    for (int k0 = 0; k0 < 256; k0 += 16) {
        const bool more = (k0 + 16) < 256;
        if (more) {
            ra0 = *(const float4*)(Ab + (size_t)ma * 256 + k0 + 16 + kq);
            ra1 = *(const float4*)(Ab + (size_t)(ma + 64) * 256 + k0 + 16 + kq);
            rb  = *(const float4*)(W + (size_t)(k0 + 16 + kb) * ldw + n0 + nb);
        }
#pragma unroll
        for (int k = 0; k < 16; k++) {
            float ra[8], rbv[4];
            float4 a0 = *(const float4*)&As[cur][k][ty*8];
            float4 a1 = *(const float4*)&As[cur][k][ty*8+4];
            ra[0]=a0.x; ra[1]=a0.y; ra[2]=a0.z; ra[3]=a0.w;
            ra[4]=a1.x; ra[5]=a1.y; ra[6]=a1.z; ra[7]=a1.w;
            float4 b4 = *(const float4*)&Bs[cur][k][tx*4];
            rbv[0]=b4.x; rbv[1]=b4.y; rbv[2]=b4.z; rbv[3]=b4.w;
#pragma unroll
            for (int i = 0; i < 8; i++)
#pragma unroll
                for (int j = 0; j < 4; j++)
                    acc[i][j] += ra[i] * rbv[j];
        }
        if (more) {
            const int nx = cur ^ 1;
            As[nx][kq+0][ma] = ra0.x; As[nx][kq+1][ma] = ra0.y; As[nx][kq+2][ma] = ra0.z; As[nx][kq+3][ma] = ra0.w;
            As[nx][kq+0][ma+64] = ra1.x; As[nx][kq+1][ma+64] = ra1.y; As[nx][kq+2][ma+64] = ra1.z; As[nx][kq+3][ma+64] = ra1.w;
            *(float4*)&Bs[nx][kb][nb] = rb;
        }
        __syncthreads();
        cur ^= 1;
    }

    float4 bv = make_float4(0.f, 0.f, 0.f, 0.f);
    if (bias) bv = *(const float4*)(bias + n0 + tx*4);
#pragma unroll
    for (int i = 0; i < 8; i++) {
        const int row = m0 + ty*8 + i;
        float4 o;
        o.x = acc[i][0] + bv.x;
        o.y = acc[i][1] + bv.y;
        o.z = acc[i][2] + bv.z;
        o.w = acc[i][3] + bv.w;
        *(float4*)(C + (size_t)row * N + n0 + tx*4) = o;
    }
}

__global__ void __launch_bounds__(256) gemm_kernel(
        const float* __restrict__ A, const float* __restrict__ W,
        const float* __restrict__ bias, float* __restrict__ C,
        int N, int ldw) {
    gemm_tile(A, W, bias, C, N, ldw);
}

// merged Q/K/V projection: blockIdx.z selects which matrix
__global__ void __launch_bounds__(256) gemm_qkv_kernel(
        const float* __restrict__ tok,
        const float* __restrict__ Wq, const float* __restrict__ bq, float* __restrict__ gQ,
        const float* __restrict__ Wk, const float* __restrict__ bk, float* __restrict__ gK,
        const float* __restrict__ Wv, const float* __restrict__ bv, float* __restrict__ gV) {
    const int z = blockIdx.z;
    const float* W    = (z == 0) ? Wq : (z == 1) ? Wk : Wv;
    const float* bias = (z == 0) ? bq : (z == 1) ? bk : bv;
    float*       C    = (z == 0) ? gQ : (z == 1) ? gK : gV;
    gemm_tile(tok, W, bias, C, DIM, DIM);
}

// ---------------- fused score + top-4 select + attention ----------------
// warp per voxel; grid 2048 x 256 threads
__global__ void score_attn_kernel(const float* __restrict__ coords,
                                  const float* __restrict__ W1,   // [515,64]
                                  const float* __restrict__ W2,   // [64,1]
                                  const int* __restrict__ knn,
                                  const float* __restrict__ gA,
                                  const float* __restrict__ gB,
                                  const float* __restrict__ gQ,
                                  const float* __restrict__ gK,
                                  const float* __restrict__ gV,
                                  float* __restrict__ gctx) {
    __shared__ float sW1c[3][64];
    __shared__ float sW2[64];
    const int t = threadIdx.x;
    if (t < 64) {
        sW2[t]     = W2[t];
        sW1c[0][t] = W1[512*64 + t];
        sW1c[1][t] = W1[513*64 + t];
        sW1c[2][t] = W1[514*64 + t];
    }
    __syncthreads();

    const int warp = t >> 5, lane = t & 31;
    const int g = blockIdx.x * 8 + warp;           // 0..16383
    const int b = g >> 12;
    const int i = g & 4095;
    const float* coo = coords + (size_t)b * VOX * 3;
    const float xi = coo[3*i+0], yi = coo[3*i+1], zi = coo[3*i+2];

    const float a0  = gA[(size_t)g*64 + lane];
    const float a1  = gA[(size_t)g*64 + lane + 32];
    const float w2a = sW2[lane], w2b = sW2[lane + 32];
    const float c0a = sW1c[0][lane], c0b = sW1c[0][lane+32];
    const float c1a = sW1c[1][lane], c1b = sW1c[1][lane+32];
    const float c2a = sW1c[2][lane], c2b = sW1c[2][lane+32];

    float bs[TOPK_N] = {-1e30f, -1e30f, -1e30f, -1e30f};
    int   bj[TOPK_N] = {0, 0, 0, 0};          // selected voxel id directly

#pragma unroll
    for (int nb = 0; nb < KNN_N; nb++) {
        const int j = knn[g*KNN_N + nb];
        const float rx = coo[3*j+0] - xi;
        const float ry = coo[3*j+1] - yi;
        const float rz = coo[3*j+2] - zi;
        const float* Bj = gB + ((size_t)(b << 12) + j) * 64;
        float h0 = a0 + Bj[lane]      + rx*c0a + ry*c1a + rz*c2a;
        float h1 = a1 + Bj[lane + 32] + rx*c0b + ry*c1b + rz*c2b;
        h0 = fmaxf(h0, 0.0f);
        h1 = fmaxf(h1, 0.0f);
        float p = h0 * w2a + h1 * w2b;
#pragma unroll
        for (int off = 16; off; off >>= 1) p += __shfl_xor_sync(0xffffffffu, p, off);
        // insert (p, j), descending; strict > so later ties lose (matches top_k)
        float cs = p; int cj = j;
#pragma unroll
        for (int k = 0; k < TOPK_N; k++) {
            const bool better = cs > bs[k];
            const float ts = better ? bs[k] : cs;
            const int   tj = better ? bj[k] : cj;
            bs[k] = better ? cs : bs[k];
            bj[k] = better ? cj : bj[k];
            cs = ts; cj = tj;
        }
    }

    // ---- attention: lane l handles channels [8l, 8l+8), head = l/8 ----
    const size_t base = (size_t)g * DIM + lane * 8;
    const float4 q0 = *(const float4*)(gQ + base);
    const float4 q1 = *(const float4*)(gQ + base + 4);

    float att[TOPK_N];
#pragma unroll
    for (int s = 0; s < TOPK_N; s++) {
        const size_t jb = ((size_t)(b << 12) + bj[s]) * DIM + lane * 8;
        const float4* Kp = (const float4*)(gK + jb);
        const float4 k0 = Kp[0], k1 = Kp[1];
        float p = q0.x*k0.x + q0.y*k0.y + q0.z*k0.z + q0.w*k0.w
                + q1.x*k1.x + q1.y*k1.y + q1.z*k1.z + q1.w*k1.w;
        p += __shfl_xor_sync(0xffffffffu, p, 4);
        p += __shfl_xor_sync(0xffffffffu, p, 2);
        p += __shfl_xor_sync(0xffffffffu, p, 1);
        att[s] = p * 0.125f;    // 1/sqrt(64)
    }
    float m = fmaxf(fmaxf(att[0], att[1]), fmaxf(att[2], att[3]));
    float e[TOPK_N], ssum = 0.0f;
#pragma unroll
    for (int s = 0; s < TOPK_N; s++) { e[s] = expf(att[s] - m); ssum += e[s]; }
    const float inv = 1.0f / ssum;

    float4 c0 = make_float4(0.f,0.f,0.f,0.f);
    float4 c1 = make_float4(0.f,0.f,0.f,0.f);
#pragma unroll
    for (int s = 0; s < TOPK_N; s++) {
        const float w = e[s] * inv;
        const size_t jb = ((size_t)(b << 12) + bj[s]) * DIM + lane * 8;
        const float4* Vp = (const float4*)(gV + jb);
        const float4 v0 = Vp[0], v1 = Vp[1];
        c0.x += w*v0.x; c0.y += w*v0.y; c0.z += w*v0.z; c0.w += w*v0.w;
        c1.x += w*v1.x; c1.y += w*v1.y; c1.z += w*v1.z; c1.w += w*v1.w;
    }
    *(float4*)(gctx + base)     = c0;
    *(float4*)(gctx + base + 4) = c1;
}

// ---------------- launch ----------------
extern "C" void kernel_launch(void* const* d_in, const int* in_sizes, int n_in,
                              void* d_out, int out_size) {
    const float* tok    = (const float*)d_in[0];
    const float* coords = (const float*)d_in[1];
    const float* W1 = (const float*)d_in[3];
    const float* b1 = (const float*)d_in[4];
    const float* W2 = (const float*)d_in[5];
    const float* Wq = (const float*)d_in[7];
    const float* bq = (const float*)d_in[8];
    const float* Wk = (const float*)d_in[9];
    const float* bk = (const float*)d_in[10];
    const float* Wv = (const float*)d_in[11];
    const float* bv = (const float*)d_in[12];
    const float* Wo = (const float*)d_in[13];
    const float* bo = (const float*)d_in[14];
    float* out = (float*)d_out;

    void* bufp = nullptr;
    cudaGetSymbolAddress(&bufp, g_buf);
    float* buf = (float*)bufp;
    float* gA   = buf + OFF_A;
    float* gB   = buf + OFF_B;
    float* gQ   = buf + OFF_Q;
    float* gK   = buf + OFF_K;
    float* gV   = buf + OFF_V;
    float* gctx = buf + OFF_CTX;
    int*   gknn = (int*)(buf + OFF_KNN);

    // my launch #1
    knn_kernel<<<dim3(128, 4), 256>>>(coords, gknn);
    // #2, #3
    gemm_kernel<<<dim3(GTOT/128, 1), 256>>>(tok, W1,            b1,      gA, HIDN, HIDN);
    gemm_kernel<<<dim3(GTOT/128, 1), 256>>>(tok, W1 + 256*HIDN, nullptr, gB, HIDN, HIDN);
    // #4 : merged Q/K/V
    gemm_qkv_kernel<<<dim3(GTOT/128, DIM/64, 3), 256>>>(tok, Wq, bq, gQ, Wk, bk, gK, Wv, bv, gV);
    // #5 : score+attention  (ncu capture slot)
    score_attn_kernel<<<GTOT/8, 256>>>(coords, W1, W2, gknn, gA, gB, gQ, gK, gV, gctx);
    // #6 : output projection
    gemm_kernel<<<dim3(GTOT/128, DIM/64), 256>>>(gctx, Wo, bo, out, DIM, DIM);
}

// round 4
// speedup vs baseline: 1.2677x; 1.0542x over previous
#include <cuda_runtime.h>
#include <cuda_bf16.h>
#include <cstdint>

#define BATCH 4
#define VOX   4096
#define DIM   256
#define HIDN  64
#define KNN_N 10
#define TOPK_N 4
#define GTOT  (BATCH*VOX)   // 16384

// ---------------- device scratch ----------------
#define OFF_A    0
#define OFF_B    1048576
#define OFF_Q    2097152
#define OFF_K    6291456
#define OFF_V    10485760
#define OFF_CTX  14680064
#define OFF_KNN  18874368
#define BUF_TOTAL 19038208

static __device__ float g_buf[BUF_TOTAL];

// ---------------- KNN kernel ----------------
__global__ void knn_kernel(const float* __restrict__ coords, int* __restrict__ knn_out) {
    __shared__ float sx[VOX], sy[VOX], sz[VOX];
    const int b = blockIdx.y;
    const float* coo = coords + (size_t)b * VOX * 3;
    for (int j = threadIdx.x; j < VOX; j += blockDim.x) {
        sx[j] = coo[3*j+0];
        sy[j] = coo[3*j+1];
        sz[j] = coo[3*j+2];
    }
    __syncthreads();

    const int warp = threadIdx.x >> 5;
    const int lane = threadIdx.x & 31;

    for (int r = 0; r < 4; r++) {
        const int i = blockIdx.x * 32 + warp * 4 + r;
        const float xi = sx[i], yi = sy[i], zi = sz[i];
        const float sqi = xi*xi + yi*yi + zi*zi;

        float ld[KNN_N];
        int   li[KNN_N];
#pragma unroll
        for (int k = 0; k < KNN_N; k++) { ld[k] = 1e30f; li[k] = 0x7fffffff; }

        for (int j = lane; j < VOX; j += 32) {
            const float xj = sx[j], yj = sy[j], zj = sz[j];
            const float sqj = xj*xj + yj*yj + zj*zj;
            const float dot = xi*xj + yi*yj + zi*zj;
            float d = sqi + sqj - 2.0f * dot;
            if (j == i) d = 1e30f;
            if (d < ld[KNN_N-1] || (d == ld[KNN_N-1] && j < li[KNN_N-1])) {
                float cd = d; int ci = j;
#pragma unroll
                for (int k = 0; k < KNN_N; k++) {
                    const bool better = (cd < ld[k]) || (cd == ld[k] && ci < li[k]);
                    const float td = better ? ld[k] : cd;
                    const int   ti = better ? li[k] : ci;
                    ld[k] = better ? cd : ld[k];
                    li[k] = better ? ci : li[k];
                    cd = td; ci = ti;
                }
            }
        }

        const int out_base = ((b << 12) + i) * KNN_N;
        for (int rr = 0; rr < KNN_N; rr++) {
            const float myd = ld[0];
            const int   myi = li[0];
            float bd = myd; int bi = myi;
#pragma unroll
            for (int off = 16; off; off >>= 1) {
                const float od = __shfl_xor_sync(0xffffffffu, bd, off);
                const int   oi = __shfl_xor_sync(0xffffffffu, bi, off);
                if (od < bd || (od == bd && oi < bi)) { bd = od; bi = oi; }
            }
            if (bi == myi && bd == myd) {
#pragma unroll
                for (int k = 0; k < KNN_N-1; k++) { ld[k] = ld[k+1]; li[k] = li[k+1]; }
                ld[KNN_N-1] = 1e30f; li[KNN_N-1] = 0x7fffffff;
            }
            if (lane == 0) knn_out[out_base + rr] = bi;
        }
    }
}

// ---------------- fp32 GEMM tile body (selection path; kept exact-ish fp32) ----------------
__device__ __forceinline__ void gemm_tile_f32(const float* __restrict__ A,
        const float* __restrict__ W, const float* __restrict__ bias,
        float* __restrict__ C, int N, int ldw, int m0, int n0) {
    __shared__ float As[2][16][132];
    __shared__ float Bs[2][16][64];

    const int t  = threadIdx.x;
    const int tx = t & 15;
    const int ty = t >> 4;

    const int kq = (t & 3) * 4;
    const int ma = t >> 2;
    const int kb = t >> 4;
    const int nb = (t & 15) * 4;

    const float* Ab = A + (size_t)m0 * 256;

    float4 ra0 = *(const float4*)(Ab + (size_t)ma * 256 + kq);
    float4 ra1 = *(const float4*)(Ab + (size_t)(ma + 64) * 256 + kq);
    float4 rb  = *(const float4*)(W + (size_t)kb * ldw + n0 + nb);

    float acc[8][4];
#pragma unroll
    for (int i = 0; i < 8; i++)
#pragma unroll
        for (int j = 0; j < 4; j++) acc[i][j] = 0.0f;

    As[0][kq+0][ma] = ra0.x; As[0][kq+1][ma] = ra0.y; As[0][kq+2][ma] = ra0.z; As[0][kq+3][ma] = ra0.w;
    As[0][kq+0][ma+64] = ra1.x; As[0][kq+1][ma+64] = ra1.y; As[0][kq+2][ma+64] = ra1.z; As[0][kq+3][ma+64] = ra1.w;
    *(float4*)&Bs[0][kb][nb] = rb;
    __syncthreads();

    int cur = 0;
#pragma unroll
    for (int k0 = 0; k0 < 256; k0 += 16) {
        const bool more = (k0 + 16) < 256;
        if (more) {
            ra0 = *(const float4*)(Ab + (size_t)ma * 256 + k0 + 16 + kq);
            ra1 = *(const float4*)(Ab + (size_t)(ma + 64) * 256 + k0 + 16 + kq);
            rb  = *(const float4*)(W + (size_t)(k0 + 16 + kb) * ldw + n0 + nb);
        }
#pragma unroll
        for (int k = 0; k < 16; k++) {
            float ra[8], rbv[4];
            float4 a0 = *(const float4*)&As[cur][k][ty*8];
            float4 a1 = *(const float4*)&As[cur][k][ty*8+4];
            ra[0]=a0.x; ra[1]=a0.y; ra[2]=a0.z; ra[3]=a0.w;
            ra[4]=a1.x; ra[5]=a1.y; ra[6]=a1.z; ra[7]=a1.w;
            float4 b4 = *(const float4*)&Bs[cur][k][tx*4];
            rbv[0]=b4.x; rbv[1]=b4.y; rbv[2]=b4.z; rbv[3]=b4.w;
#pragma unroll
            for (int i = 0; i < 8; i++)
#pragma unroll
                for (int j = 0; j < 4; j++)
                    acc[i][j] += ra[i] * rbv[j];
        }
        if (more) {
            const int nx = cur ^ 1;
            As[nx][kq+0][ma] = ra0.x; As[nx][kq+1][ma] = ra0.y; As[nx][kq+2][ma] = ra0.z; As[nx][kq+3][ma] = ra0.w;
            As[nx][kq+0][ma+64] = ra1.x; As[nx][kq+1][ma+64] = ra1.y; As[nx][kq+2][ma+64] = ra1.z; As[nx][kq+3][ma+64] = ra1.w;
            *(float4*)&Bs[nx][kb][nb] = rb;
        }
        __syncthreads();
        cur ^= 1;
    }

    float4 bv = make_float4(0.f, 0.f, 0.f, 0.f);
    if (bias) bv = *(const float4*)(bias + n0 + tx*4);
#pragma unroll
    for (int i = 0; i < 8; i++) {
        const int row = m0 + ty*8 + i;
        float4 o;
        o.x = acc[i][0] + bv.x;
        o.y = acc[i][1] + bv.y;
        o.z = acc[i][2] + bv.z;
        o.w = acc[i][3] + bv.w;
        *(float4*)(C + (size_t)row * N + n0 + tx*4) = o;
    }
}

// merged A/B (score-MLP precompute): blockIdx.y = 0 -> A(tok@W1a+b1), 1 -> B(tok@W1b)
__global__ void __launch_bounds__(256) gemm_ab_kernel(
        const float* __restrict__ tok, const float* __restrict__ W1,
        const float* __restrict__ b1, float* __restrict__ gA, float* __restrict__ gB) {
    const int z = blockIdx.y;
    const float* W    = z ? (W1 + 256*HIDN) : W1;
    const float* bias = z ? nullptr : b1;
    float*       C    = z ? gB : gA;
    gemm_tile_f32(tok, W, bias, C, HIDN, HIDN, blockIdx.x * 128, 0);
}

// ---------------- split-bf16 tensor-core GEMM ----------------
// C[M,N] = A[M,256] @ W[256,N] + bias, via 3x bf16 mma (hi*hi + hi*lo + lo*hi)
// block: 256 thr (8 warps), tile 128m x 64n, K chunk 32.
__device__ __forceinline__ void mma_bf16(float* c, const uint32_t* a, const uint32_t* b) {
    asm volatile(
        "mma.sync.aligned.m16n8k16.row.col.f32.bf16.bf16.f32 "
        "{%0,%1,%2,%3}, {%4,%5,%6,%7}, {%8,%9}, {%0,%1,%2,%3};\n"
        : "+f"(c[0]), "+f"(c[1]), "+f"(c[2]), "+f"(c[3])
        : "r"(a[0]), "r"(a[1]), "r"(a[2]), "r"(a[3]), "r"(b[0]), "r"(b[1]));
}

#define ASTRIDE 40   // halves; 80B row stride -> conflict-free fragment loads

__device__ __forceinline__ void tc_gemm_tile(const float* __restrict__ A,
        const float* __restrict__ W, const float* __restrict__ bias,
        float* __restrict__ C, int N, int ldw, int m0, int n0) {
    __shared__ __nv_bfloat16 Ah[128][ASTRIDE], Al[128][ASTRIDE];
    __shared__ __nv_bfloat16 Bh[64][ASTRIDE],  Bl[64][ASTRIDE];

    const int t    = threadIdx.x;
    const int warp = t >> 5;
    const int lane = t & 31;
    const int g    = lane >> 2;
    const int tg   = lane & 3;
    const int mw   = warp & 3;      // 4 m-warps x 32 rows
    const int nw   = warp >> 2;     // 2 n-warps x 32 cols

    // A staging: thread -> row t>>1, half-chunk (t&1)*16
    const int am = t >> 1;
    const int aks = (t & 1) * 16;
    // W staging: thread -> k row t>>3, n oct (t&7)*8
    const int wk = t >> 3;
    const int wn = (t & 7) * 8;

    float acc[2][4][4];
#pragma unroll
    for (int mt = 0; mt < 2; mt++)
#pragma unroll
        for (int nt = 0; nt < 4; nt++)
#pragma unroll
            for (int e = 0; e < 4; e++) acc[mt][nt][e] = 0.0f;

    for (int k0 = 0; k0 < 256; k0 += 32) {
        // ---- stage + convert A (128x32) ----
        {
            const float* src = A + (size_t)(m0 + am) * 256 + k0 + aks;
#pragma unroll
            for (int q = 0; q < 4; q++) {
                float4 v = *(const float4*)(src + q*4);
                __nv_bfloat162 h01 = __floats2bfloat162_rn(v.x, v.y);
                float2 hf01 = __bfloat1622float2(h01);
                __nv_bfloat162 l01 = __floats2bfloat162_rn(v.x - hf01.x, v.y - hf01.y);
                __nv_bfloat162 h23 = __floats2bfloat162_rn(v.z, v.w);
                float2 hf23 = __bfloat1622float2(h23);
                __nv_bfloat162 l23 = __floats2bfloat162_rn(v.z - hf23.x, v.w - hf23.y);
                *(__nv_bfloat162*)&Ah[am][aks + q*4]     = h01;
                *(__nv_bfloat162*)&Al[am][aks + q*4]     = l01;
                *(__nv_bfloat162*)&Ah[am][aks + q*4 + 2] = h23;
                *(__nv_bfloat162*)&Al[am][aks + q*4 + 2] = l23;
            }
        }
        // ---- stage + convert W (32k x 64n), transposed to [n][k] ----
        {
            const float* src = W + (size_t)(k0 + wk) * ldw + n0 + wn;
            float4 v0 = *(const float4*)(src);
            float4 v1 = *(const float4*)(src + 4);
            float vv[8] = {v0.x, v0.y, v0.z, v0.w, v1.x, v1.y, v1.z, v1.w};
#pragma unroll
            for (int e = 0; e < 8; e++) {
                __nv_bfloat16 h = __float2bfloat16(vv[e]);
                Bh[wn + e][wk] = h;
                Bl[wn + e][wk] = __float2bfloat16(vv[e] - __bfloat162float(h));
            }
        }
        __syncthreads();

        // ---- mma on the chunk ----
#pragma unroll
        for (int ks = 0; ks < 32; ks += 16) {
            uint32_t ah[2][4], al[2][4];
#pragma unroll
            for (int mt = 0; mt < 2; mt++) {
                const int r = mw*32 + mt*16 + g;
                ah[mt][0] = *(const uint32_t*)&Ah[r][ks + 2*tg];
                ah[mt][1] = *(const uint32_t*)&Ah[r+8][ks + 2*tg];
                ah[mt][2] = *(const uint32_t*)&Ah[r][ks + 8 + 2*tg];
                ah[mt][3] = *(const uint32_t*)&Ah[r+8][ks + 8 + 2*tg];
                al[mt][0] = *(const uint32_t*)&Al[r][ks + 2*tg];
                al[mt][1] = *(const uint32_t*)&Al[r+8][ks + 2*tg];
                al[mt][2] = *(const uint32_t*)&Al[r][ks + 8 + 2*tg];
                al[mt][3] = *(const uint32_t*)&Al[r+8][ks + 8 + 2*tg];
            }
            uint32_t bh[4][2], bl[4][2];
#pragma unroll
            for (int nt = 0; nt < 4; nt++) {
                const int n = nw*32 + nt*8 + g;
                bh[nt][0] = *(const uint32_t*)&Bh[n][ks + 2*tg];
                bh[nt][1] = *(const uint32_t*)&Bh[n][ks + 8 + 2*tg];
                bl[nt][0] = *(const uint32_t*)&Bl[n][ks + 2*tg];
                bl[nt][1] = *(const uint32_t*)&Bl[n][ks + 8 + 2*tg];
            }
#pragma unroll
            for (int mt = 0; mt < 2; mt++)
#pragma unroll
                for (int nt = 0; nt < 4; nt++) {
                    mma_bf16(acc[mt][nt], ah[mt], bh[nt]);
                    mma_bf16(acc[mt][nt], ah[mt], bl[nt]);
                    mma_bf16(acc[mt][nt], al[mt], bh[nt]);
                }
        }
        __syncthreads();
    }

    // ---- epilogue ----
#pragma unroll
    for (int nt = 0; nt < 4; nt++) {
        const int c = n0 + nw*32 + nt*8 + 2*tg;
        float bx = 0.f, by = 0.f;
        if (bias) { bx = bias[c]; by = bias[c+1]; }
#pragma unroll
        for (int mt = 0; mt < 2; mt++) {
            const int r = m0 + mw*32 + mt*16 + g;
            float* Cp = C + (size_t)r * N + c;
            Cp[0] = acc[mt][nt][0] + bx;
            Cp[1] = acc[mt][nt][1] + by;
            Cp[(size_t)8*N]     = acc[mt][nt][2] + bx;
            Cp[(size_t)8*N + 1] = acc[mt][nt][3] + by;
        }
    }
}

// merged Q/K/V projection on tensor cores
__global__ void __launch_bounds__(256) tc_qkv_kernel(
        const float* __restrict__ tok,
        const float* __restrict__ Wq, const float* __restrict__ bq, float* __restrict__ gQ,
        const float* __restrict__ Wk, const float* __restrict__ bk, float* __restrict__ gK,
        const float* __restrict__ Wv, const float* __restrict__ bv, float* __restrict__ gV) {
    const int z = blockIdx.z;
    const float* W    = (z == 0) ? Wq : (z == 1) ? Wk : Wv;
    const float* bias = (z == 0) ? bq : (z == 1) ? bk : bv;
    float*       C    = (z == 0) ? gQ : (z == 1) ? gK : gV;
    tc_gemm_tile(tok, W, bias, C, DIM, DIM, blockIdx.x * 128, blockIdx.y * 64);
}

__global__ void __launch_bounds__(256) tc_gemm_kernel(
        const float* __restrict__ A, const float* __restrict__ W,
        const float* __restrict__ bias, float* __restrict__ C) {
    tc_gemm_tile(A, W, bias, C, DIM, DIM, blockIdx.x * 128, blockIdx.y * 64);
}

// ---------------- fused score + top-4 select + attention ----------------
__global__ void score_attn_kernel(const float* __restrict__ coords,
                                  const float* __restrict__ W1,
                                  const float* __restrict__ W2,
                                  const int* __restrict__ knn,
                                  const float* __restrict__ gA,
                                  const float* __restrict__ gB,
                                  const float* __restrict__ gQ,
                                  const float* __restrict__ gK,
                                  const float* __restrict__ gV,
                                  float* __restrict__ gctx) {
    __shared__ float sW1c[3][64];
    __shared__ float sW2[64];
    const int t = threadIdx.x;
    if (t < 64) {
        sW2[t]     = W2[t];
        sW1c[0][t] = W1[512*64 + t];
        sW1c[1][t] = W1[513*64 + t];
        sW1c[2][t] = W1[514*64 + t];
    }
    __syncthreads();

    const int warp = t >> 5, lane = t & 31;
    const int g = blockIdx.x * 8 + warp;
    const int b = g >> 12;
    const int i = g & 4095;
    const float* coo = coords + (size_t)b * VOX * 3;
    const float xi = coo[3*i+0], yi = coo[3*i+1], zi = coo[3*i+2];

    const float a0  = gA[(size_t)g*64 + lane];
    const float a1  = gA[(size_t)g*64 + lane + 32];
    const float w2a = sW2[lane], w2b = sW2[lane + 32];
    const float c0a = sW1c[0][lane], c0b = sW1c[0][lane+32];
    const float c1a = sW1c[1][lane], c1b = sW1c[1][lane+32];
    const float c2a = sW1c[2][lane], c2b = sW1c[2][lane+32];

    float bs[TOPK_N] = {-1e30f, -1e30f, -1e30f, -1e30f};
    int   bj[TOPK_N] = {0, 0, 0, 0};

#pragma unroll
    for (int nb = 0; nb < KNN_N; nb++) {
        const int j = knn[g*KNN_N + nb];
        const float rx = coo[3*j+0] - xi;
        const float ry = coo[3*j+1] - yi;
        const float rz = coo[3*j+2] - zi;
        const float* Bj = gB + ((size_t)(b << 12) + j) * 64;
        float h0 = a0 + Bj[lane]      + rx*c0a + ry*c1a + rz*c2a;
        float h1 = a1 + Bj[lane + 32] + rx*c0b + ry*c1b + rz*c2b;
        h0 = fmaxf(h0, 0.0f);
        h1 = fmaxf(h1, 0.0f);
        float p = h0 * w2a + h1 * w2b;
#pragma unroll
        for (int off = 16; off; off >>= 1) p += __shfl_xor_sync(0xffffffffu, p, off);
        float cs = p; int cj = j;
#pragma unroll
        for (int k = 0; k < TOPK_N; k++) {
            const bool better = cs > bs[k];
            const float ts = better ? bs[k] : cs;
            const int   tj = better ? bj[k] : cj;
            bs[k] = better ? cs : bs[k];
            bj[k] = better ? cj : bj[k];
            cs = ts; cj = tj;
        }
    }

    const size_t base = (size_t)g * DIM + lane * 8;
    const float4 q0 = *(const float4*)(gQ + base);
    const float4 q1 = *(const float4*)(gQ + base + 4);

    float att[TOPK_N];
#pragma unroll
    for (int s = 0; s < TOPK_N; s++) {
        const size_t jb = ((size_t)(b << 12) + bj[s]) * DIM + lane * 8;
        const float4* Kp = (const float4*)(gK + jb);
        const float4 k0 = Kp[0], k1 = Kp[1];
        float p = q0.x*k0.x + q0.y*k0.y + q0.z*k0.z + q0.w*k0.w
                + q1.x*k1.x + q1.y*k1.y + q1.z*k1.z + q1.w*k1.w;
        p += __shfl_xor_sync(0xffffffffu, p, 4);
        p += __shfl_xor_sync(0xffffffffu, p, 2);
        p += __shfl_xor_sync(0xffffffffu, p, 1);
        att[s] = p * 0.125f;
    }
    float m = fmaxf(fmaxf(att[0], att[1]), fmaxf(att[2], att[3]));
    float e[TOPK_N], ssum = 0.0f;
#pragma unroll
    for (int s = 0; s < TOPK_N; s++) { e[s] = expf(att[s] - m); ssum += e[s]; }
    const float inv = 1.0f / ssum;

    float4 c0 = make_float4(0.f,0.f,0.f,0.f);
    float4 c1 = make_float4(0.f,0.f,0.f,0.f);
#pragma unroll
    for (int s = 0; s < TOPK_N; s++) {
        const float w = e[s] * inv;
        const size_t jb = ((size_t)(b << 12) + bj[s]) * DIM + lane * 8;
        const float4* Vp = (const float4*)(gV + jb);
        const float4 v0 = Vp[0], v1 = Vp[1];
        c0.x += w*v0.x; c0.y += w*v0.y; c0.z += w*v0.z; c0.w += w*v0.w;
        c1.x += w*v1.x; c1.y += w*v1.y; c1.z += w*v1.z; c1.w += w*v1.w;
    }
    *(float4*)(gctx + base)     = c0;
    *(float4*)(gctx + base + 4) = c1;
}

// ---------------- launch ----------------
extern "C" void kernel_launch(void* const* d_in, const int* in_sizes, int n_in,
                              void* d_out, int out_size) {
    const float* tok    = (const float*)d_in[0];
    const float* coords = (const float*)d_in[1];
    const float* W1 = (const float*)d_in[3];
    const float* b1 = (const float*)d_in[4];
    const float* W2 = (const float*)d_in[5];
    const float* Wq = (const float*)d_in[7];
    const float* bq = (const float*)d_in[8];
    const float* Wk = (const float*)d_in[9];
    const float* bk = (const float*)d_in[10];
    const float* Wv = (const float*)d_in[11];
    const float* bv = (const float*)d_in[12];
    const float* Wo = (const float*)d_in[13];
    const float* bo = (const float*)d_in[14];
    float* out = (float*)d_out;

    void* bufp = nullptr;
    cudaGetSymbolAddress(&bufp, g_buf);
    float* buf = (float*)bufp;
    float* gA   = buf + OFF_A;
    float* gB   = buf + OFF_B;
    float* gQ   = buf + OFF_Q;
    float* gK   = buf + OFF_K;
    float* gV   = buf + OFF_V;
    float* gctx = buf + OFF_CTX;
    int*   gknn = (int*)(buf + OFF_KNN);

    // #0: knn
    knn_kernel<<<dim3(128, 4), 256>>>(coords, gknn);
    // #1: A+B merged (fp32, selection path)
    gemm_ab_kernel<<<dim3(GTOT/128, 2), 256>>>(tok, W1, b1, gA, gB);
    // #2: Q/K/V merged tensor-core gemm
    tc_qkv_kernel<<<dim3(GTOT/128, DIM/64, 3), 256>>>(tok, Wq, bq, gQ, Wk, bk, gK, Wv, bv, gV);
    // #3: fused score + select + attention  (ncu capture slot = launch index 3)
    score_attn_kernel<<<GTOT/8, 256>>>(coords, W1, W2, gknn, gA, gB, gQ, gK, gV, gctx);
    // #4: output projection tensor-core gemm
    tc_gemm_kernel<<<dim3(GTOT/128, DIM/64), 256>>>(gctx, Wo, bo, out);
}

// round 5
// speedup vs baseline: 1.9769x; 1.5594x over previous
#include <cuda_runtime.h>
#include <cuda_bf16.h>
#include <cstdint>

#define BATCH 4
#define VOX   4096
#define DIM   256
#define HIDN  64
#define KNN_N 10
#define TOPK_N 4
#define GTOT  (BATCH*VOX)   // 16384

// ---------------- device scratch (float units) ----------------
#define OFF_A    0
#define OFF_B    1048576
#define OFF_Q    2097152
#define OFF_K    6291456
#define OFF_V    10485760
#define OFF_CTXH 14680064              // 16384*256 halves  (2097152 floats)
#define OFF_CTXL 16777216              // 16384*256 halves
#define OFF_KNN  18874368              // 16384*10 ints
#define OFF_TOKH 19038208              // 16384*256 halves
#define OFF_TOKL 21135360
#define OFF_WTH  23232512              // 4*256*256 halves (transposed W's)
#define OFF_WTL  23363584
#define BUF_TOTAL 23494656

static __device__ float g_buf[BUF_TOTAL];

// ---------------- convert: tok -> split bf16 ; W's -> transposed split bf16 ----------------
__global__ void __launch_bounds__(256) convert_kernel(
        const float* __restrict__ tok,
        const float* __restrict__ Wq, const float* __restrict__ Wk,
        const float* __restrict__ Wv, const float* __restrict__ Wo,
        __nv_bfloat16* __restrict__ tokh, __nv_bfloat16* __restrict__ tokl,
        __nv_bfloat16* __restrict__ wth,  __nv_bfloat16* __restrict__ wtl) {
    const int t = threadIdx.x;
    if (blockIdx.x < 4096) {
        const int idx = blockIdx.x * 256 + t;          // float4 index
        const int m = idx >> 6;
        const int c = (idx & 63) * 4;
        float4 v = *(const float4*)(tok + (size_t)m * 256 + c);
        __nv_bfloat16* ph = tokh + (size_t)m * 256 + c;
        __nv_bfloat16* pl = tokl + (size_t)m * 256 + c;
        float vv[4] = {v.x, v.y, v.z, v.w};
#pragma unroll
        for (int q = 0; q < 4; q++) {
            __nv_bfloat16 h = __float2bfloat16(vv[q]);
            ph[q] = h;
            pl[q] = __float2bfloat16(vv[q] - __bfloat162float(h));
        }
    } else {
        const int wb = blockIdx.x - 4096;              // 0..255
        const int elem = wb * 1024 + t * 4;
        const int mat = elem >> 16;
        const int rem = elem & 65535;
        const int n = rem >> 8;
        const int k = rem & 255;
        const float* Wm = (mat == 0) ? Wq : (mat == 1) ? Wk : (mat == 2) ? Wv : Wo;
        __nv_bfloat16* oh = wth + (size_t)mat * 65536 + (size_t)n * 256 + k;
        __nv_bfloat16* ol = wtl + (size_t)mat * 65536 + (size_t)n * 256 + k;
#pragma unroll
        for (int q = 0; q < 4; q++) {
            float v = Wm[(size_t)(k + q) * 256 + n];
            __nv_bfloat16 h = __float2bfloat16(v);
            oh[q] = h;
            ol[q] = __float2bfloat16(v - __bfloat162float(h));
        }
    }
}

// ---------------- KNN kernel ----------------
__global__ void knn_kernel(const float* __restrict__ coords, int* __restrict__ knn_out) {
    __shared__ float sx[VOX], sy[VOX], sz[VOX];
    const int b = blockIdx.y;
    const float* coo = coords + (size_t)b * VOX * 3;
    for (int j = threadIdx.x; j < VOX; j += blockDim.x) {
        sx[j] = coo[3*j+0];
        sy[j] = coo[3*j+1];
        sz[j] = coo[3*j+2];
    }
    __syncthreads();

    const int warp = threadIdx.x >> 5;
    const int lane = threadIdx.x & 31;

    for (int r = 0; r < 4; r++) {
        const int i = blockIdx.x * 32 + warp * 4 + r;
        const float xi = sx[i], yi = sy[i], zi = sz[i];
        const float sqi = xi*xi + yi*yi + zi*zi;

        float ld[KNN_N];
        int   li[KNN_N];
#pragma unroll
        for (int k = 0; k < KNN_N; k++) { ld[k] = 1e30f; li[k] = 0x7fffffff; }

#pragma unroll 2
        for (int j = lane; j < VOX; j += 32) {
            const float xj = sx[j], yj = sy[j], zj = sz[j];
            const float sqj = xj*xj + yj*yj + zj*zj;
            const float dot = xi*xj + yi*yj + zi*zj;
            float d = sqi + sqj - 2.0f * dot;
            if (j == i) d = 1e30f;
            // per-lane: candidates arrive j-ascending, so strict < keeps
            // earlier (smaller) index above on exact ties — matches top_k.
            if (d < ld[KNN_N-1]) {
                float cd = d; int ci = j;
#pragma unroll
                for (int k = 0; k < KNN_N; k++) {
                    const bool better = cd < ld[k];
                    const float td = better ? ld[k] : cd;
                    const int   ti = better ? li[k] : ci;
                    ld[k] = better ? cd : ld[k];
                    li[k] = better ? ci : li[k];
                    cd = td; ci = ti;
                }
            }
        }

        const int out_base = ((b << 12) + i) * KNN_N;
        for (int rr = 0; rr < KNN_N; rr++) {
            const float myd = ld[0];
            const int   myi = li[0];
            float bd = myd; int bi = myi;
#pragma unroll
            for (int off = 16; off; off >>= 1) {
                const float od = __shfl_xor_sync(0xffffffffu, bd, off);
                const int   oi = __shfl_xor_sync(0xffffffffu, bi, off);
                if (od < bd || (od == bd && oi < bi)) { bd = od; bi = oi; }
            }
            if (bi == myi && bd == myd) {
#pragma unroll
                for (int k = 0; k < KNN_N-1; k++) { ld[k] = ld[k+1]; li[k] = li[k+1]; }
                ld[KNN_N-1] = 1e30f; li[KNN_N-1] = 0x7fffffff;
            }
            if (lane == 0) knn_out[out_base + rr] = bi;
        }
    }
}

// ---------------- fp32 GEMM tile (selection path) ----------------
__device__ __forceinline__ void gemm_tile_f32(const float* __restrict__ A,
        const float* __restrict__ W, const float* __restrict__ bias,
        float* __restrict__ C, int N, int ldw, int m0, int n0) {
    __shared__ float As[2][16][132];
    __shared__ float Bs[2][16][64];

    const int t  = threadIdx.x;
    const int tx = t & 15;
    const int ty = t >> 4;

    const int kq = (t & 3) * 4;
    const int ma = t >> 2;
    const int kb = t >> 4;
    const int nb = (t & 15) * 4;

    const float* Ab = A + (size_t)m0 * 256;

    float4 ra0 = *(const float4*)(Ab + (size_t)ma * 256 + kq);
    float4 ra1 = *(const float4*)(Ab + (size_t)(ma + 64) * 256 + kq);
    float4 rb  = *(const float4*)(W + (size_t)kb * ldw + n0 + nb);

    float acc[8][4];
#pragma unroll
    for (int i = 0; i < 8; i++)
#pragma unroll
        for (int j = 0; j < 4; j++) acc[i][j] = 0.0f;

    As[0][kq+0][ma] = ra0.x; As[0][kq+1][ma] = ra0.y; As[0][kq+2][ma] = ra0.z; As[0][kq+3][ma] = ra0.w;
    As[0][kq+0][ma+64] = ra1.x; As[0][kq+1][ma+64] = ra1.y; As[0][kq+2][ma+64] = ra1.z; As[0][kq+3][ma+64] = ra1.w;
    *(float4*)&Bs[0][kb][nb] = rb;
    __syncthreads();

    int cur = 0;
#pragma unroll
    for (int k0 = 0; k0 < 256; k0 += 16) {
        const bool more = (k0 + 16) < 256;
        if (more) {
            ra0 = *(const float4*)(Ab + (size_t)ma * 256 + k0 + 16 + kq);
            ra1 = *(const float4*)(Ab + (size_t)(ma + 64) * 256 + k0 + 16 + kq);
            rb  = *(const float4*)(W + (size_t)(k0 + 16 + kb) * ldw + n0 + nb);
        }
#pragma unroll
        for (int k = 0; k < 16; k++) {
            float ra[8], rbv[4];
            float4 a0 = *(const float4*)&As[cur][k][ty*8];
            float4 a1 = *(const float4*)&As[cur][k][ty*8+4];
            ra[0]=a0.x; ra[1]=a0.y; ra[2]=a0.z; ra[3]=a0.w;
            ra[4]=a1.x; ra[5]=a1.y; ra[6]=a1.z; ra[7]=a1.w;
            float4 b4 = *(const float4*)&Bs[cur][k][tx*4];
            rbv[0]=b4.x; rbv[1]=b4.y; rbv[2]=b4.z; rbv[3]=b4.w;
#pragma unroll
            for (int i = 0; i < 8; i++)
#pragma unroll
                for (int j = 0; j < 4; j++)
                    acc[i][j] += ra[i] * rbv[j];
        }
        if (more) {
            const int nx = cur ^ 1;
            As[nx][kq+0][ma] = ra0.x; As[nx][kq+1][ma] = ra0.y; As[nx][kq+2][ma] = ra0.z; As[nx][kq+3][ma] = ra0.w;
            As[nx][kq+0][ma+64] = ra1.x; As[nx][kq+1][ma+64] = ra1.y; As[nx][kq+2][ma+64] = ra1.z; As[nx][kq+3][ma+64] = ra1.w;
            *(float4*)&Bs[nx][kb][nb] = rb;
        }
        __syncthreads();
        cur ^= 1;
    }

    float4 bv = make_float4(0.f, 0.f, 0.f, 0.f);
    if (bias) bv = *(const float4*)(bias + n0 + tx*4);
#pragma unroll
    for (int i = 0; i < 8; i++) {
        const int row = m0 + ty*8 + i;
        float4 o;
        o.x = acc[i][0] + bv.x;
        o.y = acc[i][1] + bv.y;
        o.z = acc[i][2] + bv.z;
        o.w = acc[i][3] + bv.w;
        *(float4*)(C + (size_t)row * N + n0 + tx*4) = o;
    }
}

__global__ void __launch_bounds__(256) gemm_ab_kernel(
        const float* __restrict__ tok, const float* __restrict__ W1,
        const float* __restrict__ b1, float* __restrict__ gA, float* __restrict__ gB) {
    const int z = blockIdx.y;
    const float* W    = z ? (W1 + 256*HIDN) : W1;
    const float* bias = z ? nullptr : b1;
    float*       C    = z ? gB : gA;
    gemm_tile_f32(tok, W, bias, C, HIDN, HIDN, blockIdx.x * 128, 0);
}

// ---------------- split-bf16 tensor-core GEMM v2 (pre-converted operands) ----------------
__device__ __forceinline__ void mma_bf16(float* c, const uint32_t* a, const uint32_t* b) {
    asm volatile(
        "mma.sync.aligned.m16n8k16.row.col.f32.bf16.bf16.f32 "
        "{%0,%1,%2,%3}, {%4,%5,%6,%7}, {%8,%9}, {%0,%1,%2,%3};\n"
        : "+f"(c[0]), "+f"(c[1]), "+f"(c[2]), "+f"(c[3])
        : "r"(a[0]), "r"(a[1]), "r"(a[2]), "r"(a[3]), "r"(b[0]), "r"(b[1]));
}

#define ASTRIDE 40   // halves; 80B row stride -> conflict-free fragment loads

// A (hi/lo) in gmem [M][256] bf16; Bt (hi/lo) in gmem [N][256] bf16 (pre-transposed).
// C fp32 [M][256]. Tile 128x64, 256 thr.
__device__ __forceinline__ void tc_gemm_tile_v2(
        const __nv_bfloat16* __restrict__ Ahi, const __nv_bfloat16* __restrict__ Alo,
        const __nv_bfloat16* __restrict__ Bth, const __nv_bfloat16* __restrict__ Btl,
        const float* __restrict__ bias, float* __restrict__ C, int m0, int n0) {
    __shared__ __nv_bfloat16 Ah[128][ASTRIDE], Al[128][ASTRIDE];
    __shared__ __nv_bfloat16 Bh[64][ASTRIDE],  Bl[64][ASTRIDE];

    const int t    = threadIdx.x;
    const int warp = t >> 5;
    const int lane = t & 31;
    const int g    = lane >> 2;
    const int tg   = lane & 3;
    const int mw   = warp & 3;
    const int nw   = warp >> 2;

    // staging coords: 8-half (16B) segments
    const int ar = t >> 2;            // A rows: ar and ar+64
    const int ao = (t & 3) * 8;
    const int br = t >> 2;            // B row 0..63
    const int bo = (t & 3) * 8;

    const __nv_bfloat16* Ah_g = Ahi + (size_t)(m0 + ar) * 256 + ao;
    const __nv_bfloat16* Al_g = Alo + (size_t)(m0 + ar) * 256 + ao;
    const __nv_bfloat16* Bh_g = Bth + (size_t)(n0 + br) * 256 + bo;
    const __nv_bfloat16* Bl_g = Btl + (size_t)(n0 + br) * 256 + bo;

    float acc[2][4][4];
#pragma unroll
    for (int mt = 0; mt < 2; mt++)
#pragma unroll
        for (int nt = 0; nt < 4; nt++)
#pragma unroll
            for (int e = 0; e < 4; e++) acc[mt][nt][e] = 0.0f;

    // prologue loads (k0 = 0)
    uint4 rAh0 = *(const uint4*)(Ah_g);
    uint4 rAh1 = *(const uint4*)(Ah_g + (size_t)64 * 256);
    uint4 rAl0 = *(const uint4*)(Al_g);
    uint4 rAl1 = *(const uint4*)(Al_g + (size_t)64 * 256);
    uint4 rBh  = *(const uint4*)(Bh_g);
    uint4 rBl  = *(const uint4*)(Bl_g);

#pragma unroll
    for (int k0 = 0; k0 < 256; k0 += 32) {
        // store staged regs
        *(uint4*)&Ah[ar][ao]      = rAh0;
        *(uint4*)&Ah[ar + 64][ao] = rAh1;
        *(uint4*)&Al[ar][ao]      = rAl0;
        *(uint4*)&Al[ar + 64][ao] = rAl1;
        *(uint4*)&Bh[br][bo]      = rBh;
        *(uint4*)&Bl[br][bo]      = rBl;
        __syncthreads();

        if (k0 + 32 < 256) {
            const int kn = k0 + 32;
            rAh0 = *(const uint4*)(Ah_g + kn);
            rAh1 = *(const uint4*)(Ah_g + (size_t)64 * 256 + kn);
            rAl0 = *(const uint4*)(Al_g + kn);
            rAl1 = *(const uint4*)(Al_g + (size_t)64 * 256 + kn);
            rBh  = *(const uint4*)(Bh_g + kn);
            rBl  = *(const uint4*)(Bl_g + kn);
        }

#pragma unroll
        for (int ks = 0; ks < 32; ks += 16) {
            uint32_t ah[2][4], al[2][4];
#pragma unroll
            for (int mt = 0; mt < 2; mt++) {
                const int r = mw*32 + mt*16 + g;
                ah[mt][0] = *(const uint32_t*)&Ah[r][ks + 2*tg];
                ah[mt][1] = *(const uint32_t*)&Ah[r+8][ks + 2*tg];
                ah[mt][2] = *(const uint32_t*)&Ah[r][ks + 8 + 2*tg];
                ah[mt][3] = *(const uint32_t*)&Ah[r+8][ks + 8 + 2*tg];
                al[mt][0] = *(const uint32_t*)&Al[r][ks + 2*tg];
                al[mt][1] = *(const uint32_t*)&Al[r+8][ks + 2*tg];
                al[mt][2] = *(const uint32_t*)&Al[r][ks + 8 + 2*tg];
                al[mt][3] = *(const uint32_t*)&Al[r+8][ks + 8 + 2*tg];
            }
            uint32_t bh[4][2], bl[4][2];
#pragma unroll
            for (int nt = 0; nt < 4; nt++) {
                const int n = nw*32 + nt*8 + g;
                bh[nt][0] = *(const uint32_t*)&Bh[n][ks + 2*tg];
                bh[nt][1] = *(const uint32_t*)&Bh[n][ks + 8 + 2*tg];
                bl[nt][0] = *(const uint32_t*)&Bl[n][ks + 2*tg];
                bl[nt][1] = *(const uint32_t*)&Bl[n][ks + 8 + 2*tg];
            }
#pragma unroll
            for (int mt = 0; mt < 2; mt++)
#pragma unroll
                for (int nt = 0; nt < 4; nt++) {
                    mma_bf16(acc[mt][nt], ah[mt], bh[nt]);
                    mma_bf16(acc[mt][nt], ah[mt], bl[nt]);
                    mma_bf16(acc[mt][nt], al[mt], bh[nt]);
                }
        }
        __syncthreads();
    }

#pragma unroll
    for (int nt = 0; nt < 4; nt++) {
        const int c = n0 + nw*32 + nt*8 + 2*tg;
        float bx = 0.f, by = 0.f;
        if (bias) { bx = bias[c]; by = bias[c+1]; }
#pragma unroll
        for (int mt = 0; mt < 2; mt++) {
            const int r = m0 + mw*32 + mt*16 + g;
            float* Cp = C + (size_t)r * 256 + c;
            Cp[0] = acc[mt][nt][0] + bx;
            Cp[1] = acc[mt][nt][1] + by;
            Cp[(size_t)8*256]     = acc[mt][nt][2] + bx;
            Cp[(size_t)8*256 + 1] = acc[mt][nt][3] + by;
        }
    }
}

__global__ void __launch_bounds__(256) tc_qkv_kernel(
        const __nv_bfloat16* __restrict__ tokh, const __nv_bfloat16* __restrict__ tokl,
        const __nv_bfloat16* __restrict__ wth,  const __nv_bfloat16* __restrict__ wtl,
        const float* __restrict__ bq, const float* __restrict__ bk, const float* __restrict__ bv,
        float* __restrict__ gQ, float* __restrict__ gK, float* __restrict__ gV) {
    const int z = blockIdx.z;
    const float* bias = (z == 0) ? bq : (z == 1) ? bk : bv;
    float*       C    = (z == 0) ? gQ : (z == 1) ? gK : gV;
    tc_gemm_tile_v2(tokh, tokl, wth + (size_t)z * 65536, wtl + (size_t)z * 65536,
                    bias, C, blockIdx.x * 128, blockIdx.y * 64);
}

__global__ void __launch_bounds__(256) tc_o_kernel(
        const __nv_bfloat16* __restrict__ ctxh, const __nv_bfloat16* __restrict__ ctxl,
        const __nv_bfloat16* __restrict__ wth,  const __nv_bfloat16* __restrict__ wtl,
        const float* __restrict__ bo, float* __restrict__ out) {
    tc_gemm_tile_v2(ctxh, ctxl, wth + (size_t)3 * 65536, wtl + (size_t)3 * 65536,
                    bo, out, blockIdx.x * 128, blockIdx.y * 64);
}

// ---------------- fused score + top-4 select + attention ----------------
__global__ void score_attn_kernel(const float* __restrict__ coords,
                                  const float* __restrict__ W1,
                                  const float* __restrict__ W2,
                                  const int* __restrict__ knn,
                                  const float* __restrict__ gA,
                                  const float* __restrict__ gB,
                                  const float* __restrict__ gQ,
                                  const float* __restrict__ gK,
                                  const float* __restrict__ gV,
                                  __nv_bfloat16* __restrict__ ctxh,
                                  __nv_bfloat16* __restrict__ ctxl) {
    __shared__ float sW1c[3][64];
    __shared__ float sW2[64];
    const int t = threadIdx.x;
    if (t < 64) {
        sW2[t]     = W2[t];
        sW1c[0][t] = W1[512*64 + t];
        sW1c[1][t] = W1[513*64 + t];
        sW1c[2][t] = W1[514*64 + t];
    }
    __syncthreads();

    const int warp = t >> 5, lane = t & 31;
    const int g = blockIdx.x * 8 + warp;
    const int b = g >> 12;
    const int i = g & 4095;
    const float* coo = coords + (size_t)b * VOX * 3;
    const float xi = coo[3*i+0], yi = coo[3*i+1], zi = coo[3*i+2];

    const float a0  = gA[(size_t)g*64 + lane];
    const float a1  = gA[(size_t)g*64 + lane + 32];
    const float w2a = sW2[lane], w2b = sW2[lane + 32];
    const float c0a = sW1c[0][lane], c0b = sW1c[0][lane+32];
    const float c1a = sW1c[1][lane], c1b = sW1c[1][lane+32];
    const float c2a = sW1c[2][lane], c2b = sW1c[2][lane+32];

    float bs[TOPK_N] = {-1e30f, -1e30f, -1e30f, -1e30f};
    int   bj[TOPK_N] = {0, 0, 0, 0};

#pragma unroll
    for (int nb = 0; nb < KNN_N; nb++) {
        const int j = knn[g*KNN_N + nb];
        const float rx = coo[3*j+0] - xi;
        const float ry = coo[3*j+1] - yi;
        const float rz = coo[3*j+2] - zi;
        const float* Bj = gB + ((size_t)(b << 12) + j) * 64;
        float h0 = a0 + Bj[lane]      + rx*c0a + ry*c1a + rz*c2a;
        float h1 = a1 + Bj[lane + 32] + rx*c0b + ry*c1b + rz*c2b;
        h0 = fmaxf(h0, 0.0f);
        h1 = fmaxf(h1, 0.0f);
        float p = h0 * w2a + h1 * w2b;
#pragma unroll
        for (int off = 16; off; off >>= 1) p += __shfl_xor_sync(0xffffffffu, p, off);
        float cs = p; int cj = j;
#pragma unroll
        for (int k = 0; k < TOPK_N; k++) {
            const bool better = cs > bs[k];
            const float ts = better ? bs[k] : cs;
            const int   tj = better ? bj[k] : cj;
            bs[k] = better ? cs : bs[k];
            bj[k] = better ? cj : bj[k];
            cs = ts; cj = tj;
        }
    }

    const size_t base = (size_t)g * DIM + lane * 8;
    const float4 q0 = *(const float4*)(gQ + base);
    const float4 q1 = *(const float4*)(gQ + base + 4);

    float att[TOPK_N];
#pragma unroll
    for (int s = 0; s < TOPK_N; s++) {
        const size_t jb = ((size_t)(b << 12) + bj[s]) * DIM + lane * 8;
        const float4* Kp = (const float4*)(gK + jb);
        const float4 k0 = Kp[0], k1 = Kp[1];
        float p = q0.x*k0.x + q0.y*k0.y + q0.z*k0.z + q0.w*k0.w
                + q1.x*k1.x + q1.y*k1.y + q1.z*k1.z + q1.w*k1.w;
        p += __shfl_xor_sync(0xffffffffu, p, 4);
        p += __shfl_xor_sync(0xffffffffu, p, 2);
        p += __shfl_xor_sync(0xffffffffu, p, 1);
        att[s] = p * 0.125f;
    }
    float m = fmaxf(fmaxf(att[0], att[1]), fmaxf(att[2], att[3]));
    float e[TOPK_N], ssum = 0.0f;
#pragma unroll
    for (int s = 0; s < TOPK_N; s++) { e[s] = expf(att[s] - m); ssum += e[s]; }
    const float inv = 1.0f / ssum;

    float cv[8] = {0.f,0.f,0.f,0.f,0.f,0.f,0.f,0.f};
#pragma unroll
    for (int s = 0; s < TOPK_N; s++) {
        const float w = e[s] * inv;
        const size_t jb = ((size_t)(b << 12) + bj[s]) * DIM + lane * 8;
        const float4* Vp = (const float4*)(gV + jb);
        const float4 v0 = Vp[0], v1 = Vp[1];
        cv[0] += w*v0.x; cv[1] += w*v0.y; cv[2] += w*v0.z; cv[3] += w*v0.w;
        cv[4] += w*v1.x; cv[5] += w*v1.y; cv[6] += w*v1.z; cv[7] += w*v1.w;
    }
    // split bf16 write (feeds O gemm)
    uint32_t uh[4], ul[4];
#pragma unroll
    for (int q = 0; q < 4; q++) {
        __nv_bfloat16 h0 = __float2bfloat16(cv[2*q]);
        __nv_bfloat16 h1 = __float2bfloat16(cv[2*q+1]);
        __nv_bfloat16 l0 = __float2bfloat16(cv[2*q]   - __bfloat162float(h0));
        __nv_bfloat16 l1 = __float2bfloat16(cv[2*q+1] - __bfloat162float(h1));
        __nv_bfloat162 ph(h0, h1), pl(l0, l1);
        uh[q] = *(uint32_t*)&ph;
        ul[q] = *(uint32_t*)&pl;
    }
    *(uint4*)(ctxh + base) = make_uint4(uh[0], uh[1], uh[2], uh[3]);
    *(uint4*)(ctxl + base) = make_uint4(ul[0], ul[1], ul[2], ul[3]);
}

// ---------------- launch ----------------
extern "C" void kernel_launch(void* const* d_in, const int* in_sizes, int n_in,
                              void* d_out, int out_size) {
    const float* tok    = (const float*)d_in[0];
    const float* coords = (const float*)d_in[1];
    const float* W1 = (const float*)d_in[3];
    const float* b1 = (const float*)d_in[4];
    const float* W2 = (const float*)d_in[5];
    const float* Wq = (const float*)d_in[7];
    const float* bq = (const float*)d_in[8];
    const float* Wk = (const float*)d_in[9];
    const float* bk = (const float*)d_in[10];
    const float* Wv = (const float*)d_in[11];
    const float* bv = (const float*)d_in[12];
    const float* Wo = (const float*)d_in[13];
    const float* bo = (const float*)d_in[14];
    float* out = (float*)d_out;

    void* bufp = nullptr;
    cudaGetSymbolAddress(&bufp, g_buf);
    float* buf = (float*)bufp;
    float* gA   = buf + OFF_A;
    float* gB   = buf + OFF_B;
    float* gQ   = buf + OFF_Q;
    float* gK   = buf + OFF_K;
    float* gV   = buf + OFF_V;
    int*   gknn = (int*)(buf + OFF_KNN);
    __nv_bfloat16* ctxh = (__nv_bfloat16*)(buf + OFF_CTXH);
    __nv_bfloat16* ctxl = (__nv_bfloat16*)(buf + OFF_CTXL);
    __nv_bfloat16* tokh = (__nv_bfloat16*)(buf + OFF_TOKH);
    __nv_bfloat16* tokl = (__nv_bfloat16*)(buf + OFF_TOKL);
    __nv_bfloat16* wth  = (__nv_bfloat16*)(buf + OFF_WTH);
    __nv_bfloat16* wtl  = (__nv_bfloat16*)(buf + OFF_WTL);

    // #0: split-convert tok and weights
    convert_kernel<<<4352, 256>>>(tok, Wq, Wk, Wv, Wo, tokh, tokl, wth, wtl);
    // #1: A+B (fp32, selection path)
    gemm_ab_kernel<<<dim3(GTOT/128, 2), 256>>>(tok, W1, b1, gA, gB);
    // #2: Q/K/V tensor-core gemm (pre-converted)
    tc_qkv_kernel<<<dim3(GTOT/128, DIM/64, 3), 256>>>(tokh, tokl, wth, wtl, bq, bk, bv, gQ, gK, gV);
    // #3: knn  <-- ncu capture slot (launch index 3)
    knn_kernel<<<dim3(128, 4), 256>>>(coords, gknn);
    // #4: fused score + select + attention (writes split ctx)
    score_attn_kernel<<<GTOT/8, 256>>>(coords, W1, W2, gknn, gA, gB, gQ, gK, gV, ctxh, ctxl);
    // #5: output projection
    tc_o_kernel<<<dim3(GTOT/128, DIM/64), 256>>>(ctxh, ctxl, wth, wtl, bo, out);
}

// round 7
// speedup vs baseline: 2.0099x; 1.0167x over previous
#include <cuda_runtime.h>
#include <cuda_bf16.h>
#include <cstdint>

#define BATCH 4
#define VOX   4096
#define DIM   256
#define HIDN  64
#define KNN_N 10
#define TOPK_N 4
#define GTOT  (BATCH*VOX)   // 16384

// ---------------- device scratch (float units) ----------------
#define OFF_A    0
#define OFF_B    1048576
#define OFF_Q    2097152
#define OFF_K    6291456
#define OFF_V    10485760
#define OFF_CTXH 14680064              // 16384*256 halves  (2097152 floats)
#define OFF_CTXL 16777216              // 16384*256 halves
#define OFF_KNN  18874368              // 16384*10 ints
#define OFF_TOKH 19038208              // 16384*256 halves
#define OFF_TOKL 21135360
#define OFF_WTH  23232512              // 4*256*256 halves (transposed W's)
#define OFF_WTL  23363584
#define BUF_TOTAL 23494656

static __device__ float g_buf[BUF_TOTAL];

// ---------------- convert: tok -> split bf16 ; W's -> transposed split bf16 ----------------
__global__ void __launch_bounds__(256) convert_kernel(
        const float* __restrict__ tok,
        const float* __restrict__ Wq, const float* __restrict__ Wk,
        const float* __restrict__ Wv, const float* __restrict__ Wo,
        __nv_bfloat16* __restrict__ tokh, __nv_bfloat16* __restrict__ tokl,
        __nv_bfloat16* __restrict__ wth,  __nv_bfloat16* __restrict__ wtl) {
    const int t = threadIdx.x;
    if (blockIdx.x < 4096) {
        const int idx = blockIdx.x * 256 + t;          // float4 index
        const int m = idx >> 6;
        const int c = (idx & 63) * 4;
        float4 v = *(const float4*)(tok + (size_t)m * 256 + c);
        __nv_bfloat16* ph = tokh + (size_t)m * 256 + c;
        __nv_bfloat16* pl = tokl + (size_t)m * 256 + c;
        float vv[4] = {v.x, v.y, v.z, v.w};
#pragma unroll
        for (int q = 0; q < 4; q++) {
            __nv_bfloat16 h = __float2bfloat16(vv[q]);
            ph[q] = h;
            pl[q] = __float2bfloat16(vv[q] - __bfloat162float(h));
        }
    } else {
        const int wb = blockIdx.x - 4096;              // 0..255
        const int elem = wb * 1024 + t * 4;
        const int mat = elem >> 16;
        const int rem = elem & 65535;
        const int n = rem >> 8;
        const int k = rem & 255;
        const float* Wm = (mat == 0) ? Wq : (mat == 1) ? Wk : (mat == 2) ? Wv : Wo;
        __nv_bfloat16* oh = wth + (size_t)mat * 65536 + (size_t)n * 256 + k;
        __nv_bfloat16* ol = wtl + (size_t)mat * 65536 + (size_t)n * 256 + k;
#pragma unroll
        for (int q = 0; q < 4; q++) {
            float v = Wm[(size_t)(k + q) * 256 + n];
            __nv_bfloat16 h = __float2bfloat16(v);
            oh[q] = h;
            ol[q] = __float2bfloat16(v - __bfloat162float(h));
        }
    }
}

// ---------------- KNN kernel v3 ----------------
// grid (128,4), 256 thr. Warp handles 4 rows as 2 pairs; candidates staged in
// 16KB chunks as float4 (x,y,z,|p|^2). Ranking value is the FULL squared
// distance d = (sqi + sqj) - 2*dot — same expression as the passing R5 kernel
// (the shifted 0.5|pj|^2 - pi.pj form cancels catastrophically; do not use).
#define KCHUNK 1024
__global__ void __launch_bounds__(256) knn_kernel(const float* __restrict__ coords,
                                                  int* __restrict__ knn_out) {
    __shared__ float4 sp[KCHUNK];
    const int b = blockIdx.y;
    const float* coo = coords + (size_t)b * VOX * 3;
    const int warp = threadIdx.x >> 5;
    const int lane = threadIdx.x & 31;

    for (int pair = 0; pair < 2; pair++) {
        const int i0 = blockIdx.x * 32 + warp * 4 + pair * 2;
        const int i1 = i0 + 1;
        const float x0 = coo[3*i0], y0 = coo[3*i0+1], z0 = coo[3*i0+2];
        const float x1 = coo[3*i1], y1 = coo[3*i1+1], z1 = coo[3*i1+2];
        const float sq0 = x0*x0 + y0*y0 + z0*z0;
        const float sq1 = x1*x1 + y1*y1 + z1*z1;

        float ld0[KNN_N], ld1[KNN_N];
        int   li0[KNN_N], li1[KNN_N];
#pragma unroll
        for (int k = 0; k < KNN_N; k++) {
            ld0[k] = 1e30f; li0[k] = 0x7fffffff;
            ld1[k] = 1e30f; li1[k] = 0x7fffffff;
        }

        for (int c = 0; c < VOX / KCHUNK; c++) {
            __syncthreads();
            for (int j = threadIdx.x; j < KCHUNK; j += 256) {
                const int jj = c * KCHUNK + j;
                const float xx = coo[3*jj], yy = coo[3*jj+1], zz = coo[3*jj+2];
                sp[j] = make_float4(xx, yy, zz, xx*xx + yy*yy + zz*zz);
            }
            __syncthreads();

            const int jbase = c * KCHUNK;
            for (int j = lane; j < KCHUNK; j += 32) {
                const float4 p = sp[j];
                const int jj = jbase + j;
                const float dot0 = x0*p.x + y0*p.y + z0*p.z;
                const float dot1 = x1*p.x + y1*p.y + z1*p.z;
                float e0 = sq0 + p.w - 2.0f*dot0;
                float e1 = sq1 + p.w - 2.0f*dot1;
                if (jj == i0) e0 = 1e30f;
                if (jj == i1) e1 = 1e30f;
                // per-lane: candidates arrive j-ascending, strict < keeps the
                // earlier (smaller) index above on exact ties — matches top_k.
                if (e0 < ld0[KNN_N-1]) {
                    float cd = e0; int ci = jj;
#pragma unroll
                    for (int k = 0; k < KNN_N; k++) {
                        const bool better = cd < ld0[k];
                        const float td = better ? ld0[k] : cd;
                        const int   ti = better ? li0[k] : ci;
                        ld0[k] = better ? cd : ld0[k];
                        li0[k] = better ? ci : li0[k];
                        cd = td; ci = ti;
                    }
                }
                if (e1 < ld1[KNN_N-1]) {
                    float cd = e1; int ci = jj;
#pragma unroll
                    for (int k = 0; k < KNN_N; k++) {
                        const bool better = cd < ld1[k];
                        const float td = better ? ld1[k] : cd;
                        const int   ti = better ? li1[k] : ci;
                        ld1[k] = better ? cd : ld1[k];
                        li1[k] = better ? ci : li1[k];
                        cd = td; ci = ti;
                    }
                }
            }
        }

        // warp merge per row: 10 rounds of argmin + shift in winning lane
#pragma unroll
        for (int row = 0; row < 2; row++) {
            float* ld = row ? ld1 : ld0;
            int*   li = row ? li1 : li0;
            const int out_base = ((b << 12) + (row ? i1 : i0)) * KNN_N;
            for (int rr = 0; rr < KNN_N; rr++) {
                const float myd = ld[0];
                const int   myi = li[0];
                float bd = myd; int bi = myi;
#pragma unroll
                for (int off = 16; off; off >>= 1) {
                    const float od = __shfl_xor_sync(0xffffffffu, bd, off);
                    const int   oi = __shfl_xor_sync(0xffffffffu, bi, off);
                    if (od < bd || (od == bd && oi < bi)) { bd = od; bi = oi; }
                }
                if (bi == myi) {
#pragma unroll
                    for (int k = 0; k < KNN_N-1; k++) { ld[k] = ld[k+1]; li[k] = li[k+1]; }
                    ld[KNN_N-1] = 1e30f; li[KNN_N-1] = 0x7fffffff;
                }
                if (lane == 0) knn_out[out_base + rr] = bi;
            }
        }
    }
}

// ---------------- fp32 GEMM tile (selection path) ----------------
__device__ __forceinline__ void gemm_tile_f32(const float* __restrict__ A,
        const float* __restrict__ W, const float* __restrict__ bias,
        float* __restrict__ C, int N, int ldw, int m0, int n0) {
    __shared__ float As[2][16][132];
    __shared__ float Bs[2][16][64];

    const int t  = threadIdx.x;
    const int tx = t & 15;
    const int ty = t >> 4;

    const int kq = (t & 3) * 4;
    const int ma = t >> 2;
    const int kb = t >> 4;
    const int nb = (t & 15) * 4;

    const float* Ab = A + (size_t)m0 * 256;

    float4 ra0 = *(const float4*)(Ab + (size_t)ma * 256 + kq);
    float4 ra1 = *(const float4*)(Ab + (size_t)(ma + 64) * 256 + kq);
    float4 rb  = *(const float4*)(W + (size_t)kb * ldw + n0 + nb);

    float acc[8][4];
#pragma unroll
    for (int i = 0; i < 8; i++)
#pragma unroll
        for (int j = 0; j < 4; j++) acc[i][j] = 0.0f;

    As[0][kq+0][ma] = ra0.x; As[0][kq+1][ma] = ra0.y; As[0][kq+2][ma] = ra0.z; As[0][kq+3][ma] = ra0.w;
    As[0][kq+0][ma+64] = ra1.x; As[0][kq+1][ma+64] = ra1.y; As[0][kq+2][ma+64] = ra1.z; As[0][kq+3][ma+64] = ra1.w;
    *(float4*)&Bs[0][kb][nb] = rb;
    __syncthreads();

    int cur = 0;
#pragma unroll
    for (int k0 = 0; k0 < 256; k0 += 16) {
        const bool more = (k0 + 16) < 256;
        if (more) {
            ra0 = *(const float4*)(Ab + (size_t)ma * 256 + k0 + 16 + kq);
            ra1 = *(const float4*)(Ab + (size_t)(ma + 64) * 256 + k0 + 16 + kq);
            rb  = *(const float4*)(W + (size_t)(k0 + 16 + kb) * ldw + n0 + nb);
        }
#pragma unroll
        for (int k = 0; k < 16; k++) {
            float ra[8], rbv[4];
            float4 a0 = *(const float4*)&As[cur][k][ty*8];
            float4 a1 = *(const float4*)&As[cur][k][ty*8+4];
            ra[0]=a0.x; ra[1]=a0.y; ra[2]=a0.z; ra[3]=a0.w;
            ra[4]=a1.x; ra[5]=a1.y; ra[6]=a1.z; ra[7]=a1.w;
            float4 b4 = *(const float4*)&Bs[cur][k][tx*4];
            rbv[0]=b4.x; rbv[1]=b4.y; rbv[2]=b4.z; rbv[3]=b4.w;
#pragma unroll
            for (int i = 0; i < 8; i++)
#pragma unroll
                for (int j = 0; j < 4; j++)
                    acc[i][j] += ra[i] * rbv[j];
        }
        if (more) {
            const int nx = cur ^ 1;
            As[nx][kq+0][ma] = ra0.x; As[nx][kq+1][ma] = ra0.y; As[nx][kq+2][ma] = ra0.z; As[nx][kq+3][ma] = ra0.w;
            As[nx][kq+0][ma+64] = ra1.x; As[nx][kq+1][ma+64] = ra1.y; As[nx][kq+2][ma+64] = ra1.z; As[nx][kq+3][ma+64] = ra1.w;
            *(float4*)&Bs[nx][kb][nb] = rb;
        }
        __syncthreads();
        cur ^= 1;
    }

    float4 bv = make_float4(0.f, 0.f, 0.f, 0.f);
    if (bias) bv = *(const float4*)(bias + n0 + tx*4);
#pragma unroll
    for (int i = 0; i < 8; i++) {
        const int row = m0 + ty*8 + i;
        float4 o;
        o.x = acc[i][0] + bv.x;
        o.y = acc[i][1] + bv.y;
        o.z = acc[i][2] + bv.z;
        o.w = acc[i][3] + bv.w;
        *(float4*)(C + (size_t)row * N + n0 + tx*4) = o;
    }
}

__global__ void __launch_bounds__(256) gemm_ab_kernel(
        const float* __restrict__ tok, const float* __restrict__ W1,
        const float* __restrict__ b1, float* __restrict__ gA, float* __restrict__ gB) {
    const int z = blockIdx.y;
    const float* W    = z ? (W1 + 256*HIDN) : W1;
    const float* bias = z ? nullptr : b1;
    float*       C    = z ? gB : gA;
    gemm_tile_f32(tok, W, bias, C, HIDN, HIDN, blockIdx.x * 128, 0);
}

// ---------------- split-bf16 tensor-core GEMM v2 (pre-converted operands) ----------------
__device__ __forceinline__ void mma_bf16(float* c, const uint32_t* a, const uint32_t* b) {
    asm volatile(
        "mma.sync.aligned.m16n8k16.row.col.f32.bf16.bf16.f32 "
        "{%0,%1,%2,%3}, {%4,%5,%6,%7}, {%8,%9}, {%0,%1,%2,%3};\n"
        : "+f"(c[0]), "+f"(c[1]), "+f"(c[2]), "+f"(c[3])
        : "r"(a[0]), "r"(a[1]), "r"(a[2]), "r"(a[3]), "r"(b[0]), "r"(b[1]));
}

#define ASTRIDE 40   // halves; 80B row stride -> conflict-free fragment loads

__device__ __forceinline__ void tc_gemm_tile_v2(
        const __nv_bfloat16* __restrict__ Ahi, const __nv_bfloat16* __restrict__ Alo,
        const __nv_bfloat16* __restrict__ Bth, const __nv_bfloat16* __restrict__ Btl,
        const float* __restrict__ bias, float* __restrict__ C, int m0, int n0) {
    __shared__ __nv_bfloat16 Ah[128][ASTRIDE], Al[128][ASTRIDE];
    __shared__ __nv_bfloat16 Bh[64][ASTRIDE],  Bl[64][ASTRIDE];

    const int t    = threadIdx.x;
    const int warp = t >> 5;
    const int lane = t & 31;
    const int g    = lane >> 2;
    const int tg   = lane & 3;
    const int mw   = warp & 3;
    const int nw   = warp >> 2;

    const int ar = t >> 2;
    const int ao = (t & 3) * 8;
    const int br = t >> 2;
    const int bo = (t & 3) * 8;

    const __nv_bfloat16* Ah_g = Ahi + (size_t)(m0 + ar) * 256 + ao;
    const __nv_bfloat16* Al_g = Alo + (size_t)(m0 + ar) * 256 + ao;
    const __nv_bfloat16* Bh_g = Bth + (size_t)(n0 + br) * 256 + bo;
    const __nv_bfloat16* Bl_g = Btl + (size_t)(n0 + br) * 256 + bo;

    float acc[2][4][4];
#pragma unroll
    for (int mt = 0; mt < 2; mt++)
#pragma unroll
        for (int nt = 0; nt < 4; nt++)
#pragma unroll
            for (int e = 0; e < 4; e++) acc[mt][nt][e] = 0.0f;

    uint4 rAh0 = *(const uint4*)(Ah_g);
    uint4 rAh1 = *(const uint4*)(Ah_g + (size_t)64 * 256);
    uint4 rAl0 = *(const uint4*)(Al_g);
    uint4 rAl1 = *(const uint4*)(Al_g + (size_t)64 * 256);
    uint4 rBh  = *(const uint4*)(Bh_g);
    uint4 rBl  = *(const uint4*)(Bl_g);

#pragma unroll
    for (int k0 = 0; k0 < 256; k0 += 32) {
        *(uint4*)&Ah[ar][ao]      = rAh0;
        *(uint4*)&Ah[ar + 64][ao] = rAh1;
        *(uint4*)&Al[ar][ao]      = rAl0;
        *(uint4*)&Al[ar + 64][ao] = rAl1;
        *(uint4*)&Bh[br][bo]      = rBh;
        *(uint4*)&Bl[br][bo]      = rBl;
        __syncthreads();

        if (k0 + 32 < 256) {
            const int kn = k0 + 32;
            rAh0 = *(const uint4*)(Ah_g + kn);
            rAh1 = *(const uint4*)(Ah_g + (size_t)64 * 256 + kn);
            rAl0 = *(const uint4*)(Al_g + kn);
            rAl1 = *(const uint4*)(Al_g + (size_t)64 * 256 + kn);
            rBh  = *(const uint4*)(Bh_g + kn);
            rBl  = *(const uint4*)(Bl_g + kn);
        }

#pragma unroll
        for (int ks = 0; ks < 32; ks += 16) {
            uint32_t ah[2][4], al[2][4];
#pragma unroll
            for (int mt = 0; mt < 2; mt++) {
                const int r = mw*32 + mt*16 + g;
                ah[mt][0] = *(const uint32_t*)&Ah[r][ks + 2*tg];
                ah[mt][1] = *(const uint32_t*)&Ah[r+8][ks + 2*tg];
                ah[mt][2] = *(const uint32_t*)&Ah[r][ks + 8 + 2*tg];
                ah[mt][3] = *(const uint32_t*)&Ah[r+8][ks + 8 + 2*tg];
                al[mt][0] = *(const uint32_t*)&Al[r][ks + 2*tg];
                al[mt][1] = *(const uint32_t*)&Al[r+8][ks + 2*tg];
                al[mt][2] = *(const uint32_t*)&Al[r][ks + 8 + 2*tg];
                al[mt][3] = *(const uint32_t*)&Al[r+8][ks + 8 + 2*tg];
            }
            uint32_t bh[4][2], bl[4][2];
#pragma unroll
            for (int nt = 0; nt < 4; nt++) {
                const int n = nw*32 + nt*8 + g;
                bh[nt][0] = *(const uint32_t*)&Bh[n][ks + 2*tg];
                bh[nt][1] = *(const uint32_t*)&Bh[n][ks + 8 + 2*tg];
                bl[nt][0] = *(const uint32_t*)&Bl[n][ks + 2*tg];
                bl[nt][1] = *(const uint32_t*)&Bl[n][ks + 8 + 2*tg];
            }
#pragma unroll
            for (int mt = 0; mt < 2; mt++)
#pragma unroll
                for (int nt = 0; nt < 4; nt++) {
                    mma_bf16(acc[mt][nt], ah[mt], bh[nt]);
                    mma_bf16(acc[mt][nt], ah[mt], bl[nt]);
                    mma_bf16(acc[mt][nt], al[mt], bh[nt]);
                }
        }
        __syncthreads();
    }

#pragma unroll
    for (int nt = 0; nt < 4; nt++) {
        const int c = n0 + nw*32 + nt*8 + 2*tg;
        float bx = 0.f, by = 0.f;
        if (bias) { bx = bias[c]; by = bias[c+1]; }
#pragma unroll
        for (int mt = 0; mt < 2; mt++) {
            const int r = m0 + mw*32 + mt*16 + g;
            float* Cp = C + (size_t)r * 256 + c;
            Cp[0] = acc[mt][nt][0] + bx;
            Cp[1] = acc[mt][nt][1] + by;
            Cp[(size_t)8*256]     = acc[mt][nt][2] + bx;
            Cp[(size_t)8*256 + 1] = acc[mt][nt][3] + by;
        }
    }
}

__global__ void __launch_bounds__(256) tc_qkv_kernel(
        const __nv_bfloat16* __restrict__ tokh, const __nv_bfloat16* __restrict__ tokl,
        const __nv_bfloat16* __restrict__ wth,  const __nv_bfloat16* __restrict__ wtl,
        const float* __restrict__ bq, const float* __restrict__ bk, const float* __restrict__ bv,
        float* __restrict__ gQ, float* __restrict__ gK, float* __restrict__ gV) {
    const int z = blockIdx.z;
    const float* bias = (z == 0) ? bq : (z == 1) ? bk : bv;
    float*       C    = (z == 0) ? gQ : (z == 1) ? gK : gV;
    tc_gemm_tile_v2(tokh, tokl, wth + (size_t)z * 65536, wtl + (size_t)z * 65536,
                    bias, C, blockIdx.x * 128, blockIdx.y * 64);
}

__global__ void __launch_bounds__(256) tc_o_kernel(
        const __nv_bfloat16* __restrict__ ctxh, const __nv_bfloat16* __restrict__ ctxl,
        const __nv_bfloat16* __restrict__ wth,  const __nv_bfloat16* __restrict__ wtl,
        const float* __restrict__ bo, float* __restrict__ out) {
    tc_gemm_tile_v2(ctxh, ctxl, wth + (size_t)3 * 65536, wtl + (size_t)3 * 65536,
                    bo, out, blockIdx.x * 128, blockIdx.y * 64);
}

// ---------------- fused score + top-4 select + attention ----------------
__global__ void score_attn_kernel(const float* __restrict__ coords,
                                  const float* __restrict__ W1,
                                  const float* __restrict__ W2,
                                  const int* __restrict__ knn,
                                  const float* __restrict__ gA,
                                  const float* __restrict__ gB,
                                  const float* __restrict__ gQ,
                                  const float* __restrict__ gK,
                                  const float* __restrict__ gV,
                                  __nv_bfloat16* __restrict__ ctxh,
                                  __nv_bfloat16* __restrict__ ctxl) {
    __shared__ float sW1c[3][64];
    __shared__ float sW2[64];
    const int t = threadIdx.x;
    if (t < 64) {
        sW2[t]     = W2[t];
        sW1c[0][t] = W1[512*64 + t];
        sW1c[1][t] = W1[513*64 + t];
        sW1c[2][t] = W1[514*64 + t];
    }
    __syncthreads();

    const int warp = t >> 5, lane = t & 31;
    const int g = blockIdx.x * 8 + warp;
    const int b = g >> 12;
    const int i = g & 4095;
    const float* coo = coords + (size_t)b * VOX * 3;
    const float xi = coo[3*i+0], yi = coo[3*i+1], zi = coo[3*i+2];

    const float a0  = gA[(size_t)g*64 + lane];
    const float a1  = gA[(size_t)g*64 + lane + 32];
    const float w2a = sW2[lane], w2b = sW2[lane + 32];
    const float c0a = sW1c[0][lane], c0b = sW1c[0][lane+32];
    const float c1a = sW1c[1][lane], c1b = sW1c[1][lane+32];
    const float c2a = sW1c[2][lane], c2b = sW1c[2][lane+32];

    float bs[TOPK_N] = {-1e30f, -1e30f, -1e30f, -1e30f};
    int   bj[TOPK_N] = {0, 0, 0, 0};

#pragma unroll
    for (int nb = 0; nb < KNN_N; nb++) {
        const int j = knn[g*KNN_N + nb];
        const float rx = coo[3*j+0] - xi;
        const float ry = coo[3*j+1] - yi;
        const float rz = coo[3*j+2] - zi;
        const float* Bj = gB + ((size_t)(b << 12) + j) * 64;
        float h0 = a0 + Bj[lane]      + rx*c0a + ry*c1a + rz*c2a;
        float h1 = a1 + Bj[lane + 32] + rx*c0b + ry*c1b + rz*c2b;
        h0 = fmaxf(h0, 0.0f);
        h1 = fmaxf(h1, 0.0f);
        float p = h0 * w2a + h1 * w2b;
#pragma unroll
        for (int off = 16; off; off >>= 1) p += __shfl_xor_sync(0xffffffffu, p, off);
        float cs = p; int cj = j;
#pragma unroll
        for (int k = 0; k < TOPK_N; k++) {
            const bool better = cs > bs[k];
            const float ts = better ? bs[k] : cs;
            const int   tj = better ? bj[k] : cj;
            bs[k] = better ? cs : bs[k];
            bj[k] = better ? cj : bj[k];
            cs = ts; cj = tj;
        }
    }

    const size_t base = (size_t)g * DIM + lane * 8;
    const float4 q0 = *(const float4*)(gQ + base);
    const float4 q1 = *(const float4*)(gQ + base + 4);

    float att[TOPK_N];
#pragma unroll
    for (int s = 0; s < TOPK_N; s++) {
        const size_t jb = ((size_t)(b << 12) + bj[s]) * DIM + lane * 8;
        const float4* Kp = (const float4*)(gK + jb);
        const float4 k0 = Kp[0], k1 = Kp[1];
        float p = q0.x*k0.x + q0.y*k0.y + q0.z*k0.z + q0.w*k0.w
                + q1.x*k1.x + q1.y*k1.y + q1.z*k1.z + q1.w*k1.w;
        p += __shfl_xor_sync(0xffffffffu, p, 4);
        p += __shfl_xor_sync(0xffffffffu, p, 2);
        p += __shfl_xor_sync(0xffffffffu, p, 1);
        att[s] = p * 0.125f;
    }
    float m = fmaxf(fmaxf(att[0], att[1]), fmaxf(att[2], att[3]));
    float e[TOPK_N], ssum = 0.0f;
#pragma unroll
    for (int s = 0; s < TOPK_N; s++) { e[s] = expf(att[s] - m); ssum += e[s]; }
    const float inv = 1.0f / ssum;

    float cv[8] = {0.f,0.f,0.f,0.f,0.f,0.f,0.f,0.f};
#pragma unroll
    for (int s = 0; s < TOPK_N; s++) {
        const float w = e[s] * inv;
        const size_t jb = ((size_t)(b << 12) + bj[s]) * DIM + lane * 8;
        const float4* Vp = (const float4*)(gV + jb);
        const float4 v0 = Vp[0], v1 = Vp[1];
        cv[0] += w*v0.x; cv[1] += w*v0.y; cv[2] += w*v0.z; cv[3] += w*v0.w;
        cv[4] += w*v1.x; cv[5] += w*v1.y; cv[6] += w*v1.z; cv[7] += w*v1.w;
    }
    uint32_t uh[4], ul[4];
#pragma unroll
    for (int q = 0; q < 4; q++) {
        __nv_bfloat16 h0 = __float2bfloat16(cv[2*q]);
        __nv_bfloat16 h1 = __float2bfloat16(cv[2*q+1]);
        __nv_bfloat16 l0 = __float2bfloat16(cv[2*q]   - __bfloat162float(h0));
        __nv_bfloat16 l1 = __float2bfloat16(cv[2*q+1] - __bfloat162float(h1));
        __nv_bfloat162 ph(h0, h1), pl(l0, l1);
        uh[q] = *(uint32_t*)&ph;
        ul[q] = *(uint32_t*)&pl;
    }
    *(uint4*)(ctxh + base) = make_uint4(uh[0], uh[1], uh[2], uh[3]);
    *(uint4*)(ctxl + base) = make_uint4(ul[0], ul[1], ul[2], ul[3]);
}

// ---------------- launch ----------------
extern "C" void kernel_launch(void* const* d_in, const int* in_sizes, int n_in,
                              void* d_out, int out_size) {
    const float* tok    = (const float*)d_in[0];
    const float* coords = (const float*)d_in[1];
    const float* W1 = (const float*)d_in[3];
    const float* b1 = (const float*)d_in[4];
    const float* W2 = (const float*)d_in[5];
    const float* Wq = (const float*)d_in[7];
    const float* bq = (const float*)d_in[8];
    const float* Wk = (const float*)d_in[9];
    const float* bk = (const float*)d_in[10];
    const float* Wv = (const float*)d_in[11];
    const float* bv = (const float*)d_in[12];
    const float* Wo = (const float*)d_in[13];
    const float* bo = (const float*)d_in[14];
    float* out = (float*)d_out;

    void* bufp = nullptr;
    cudaGetSymbolAddress(&bufp, g_buf);
    float* buf = (float*)bufp;
    float* gA   = buf + OFF_A;
    float* gB   = buf + OFF_B;
    float* gQ   = buf + OFF_Q;
    float* gK   = buf + OFF_K;
    float* gV   = buf + OFF_V;
    int*   gknn = (int*)(buf + OFF_KNN);
    __nv_bfloat16* ctxh = (__nv_bfloat16*)(buf + OFF_CTXH);
    __nv_bfloat16* ctxl = (__nv_bfloat16*)(buf + OFF_CTXL);
    __nv_bfloat16* tokh = (__nv_bfloat16*)(buf + OFF_TOKH);
    __nv_bfloat16* tokl = (__nv_bfloat16*)(buf + OFF_TOKL);
    __nv_bfloat16* wth  = (__nv_bfloat16*)(buf + OFF_WTH);
    __nv_bfloat16* wtl  = (__nv_bfloat16*)(buf + OFF_WTL);

    // #0: split-convert tok and weights
    convert_kernel<<<4352, 256>>>(tok, Wq, Wk, Wv, Wo, tokh, tokl, wth, wtl);
    // #1: A+B (fp32, selection path)
    gemm_ab_kernel<<<dim3(GTOT/128, 2), 256>>>(tok, W1, b1, gA, gB);
    // #2: Q/K/V tensor-core gemm (pre-converted)
    tc_qkv_kernel<<<dim3(GTOT/128, DIM/64, 3), 256>>>(tokh, tokl, wth, wtl, bq, bk, bv, gQ, gK, gV);
    // #3: knn v3  <-- ncu capture slot (launch index 3)
    knn_kernel<<<dim3(128, 4), 256>>>(coords, gknn);
    // #4: fused score + select + attention (writes split ctx)
    score_attn_kernel<<<GTOT/8, 256>>>(coords, W1, W2, gknn, gA, gB, gQ, gK, gV, ctxh, ctxl);
    // #5: output projection
    tc_o_kernel<<<dim3(GTOT/128, DIM/64), 256>>>(ctxh, ctxl, wth, wtl, bo, out);
}

// round 9
// speedup vs baseline: 2.6386x; 1.3128x over previous
#include <cuda_runtime.h>
#include <cuda_bf16.h>
#include <cstdint>

#define BATCH 4
#define VOX   4096
#define DIM   256
#define HIDN  64
#define KNN_N 10
#define TOPK_N 4
#define GTOT  (BATCH*VOX)   // 16384

// ---------------- device scratch (float units) ----------------
#define OFF_A    0
#define OFF_B    1048576
#define OFF_Q    2097152
#define OFF_K    6291456
#define OFF_V    10485760
#define OFF_CTXH 14680064              // 16384*256 halves  (2097152 floats)
#define OFF_CTXL 16777216              // 16384*256 halves
#define OFF_KNN  18874368              // 16384*10 ints
#define OFF_TOKH 19038208              // 16384*256 halves
#define OFF_TOKL 21135360
#define OFF_WTH  23232512              // 4*256*256 halves (transposed W's)
#define OFF_WTL  23363584
#define BUF_TOTAL 23494656

static __device__ float g_buf[BUF_TOTAL];

// ---------------- convert: tok -> split bf16 ; W's -> transposed split bf16 ----------------
__global__ void __launch_bounds__(256) convert_kernel(
        const float* __restrict__ tok,
        const float* __restrict__ Wq, const float* __restrict__ Wk,
        const float* __restrict__ Wv, const float* __restrict__ Wo,
        __nv_bfloat16* __restrict__ tokh, __nv_bfloat16* __restrict__ tokl,
        __nv_bfloat16* __restrict__ wth,  __nv_bfloat16* __restrict__ wtl) {
    const int t = threadIdx.x;
    if (blockIdx.x < 4096) {
        const int idx = blockIdx.x * 256 + t;          // float4 index
        const int m = idx >> 6;
        const int c = (idx & 63) * 4;
        float4 v = *(const float4*)(tok + (size_t)m * 256 + c);
        __nv_bfloat16* ph = tokh + (size_t)m * 256 + c;
        __nv_bfloat16* pl = tokl + (size_t)m * 256 + c;
        float vv[4] = {v.x, v.y, v.z, v.w};
#pragma unroll
        for (int q = 0; q < 4; q++) {
            __nv_bfloat16 h = __float2bfloat16(vv[q]);
            ph[q] = h;
            pl[q] = __float2bfloat16(vv[q] - __bfloat162float(h));
        }
    } else {
        const int wb = blockIdx.x - 4096;              // 0..255
        const int elem = wb * 1024 + t * 4;
        const int mat = elem >> 16;
        const int rem = elem & 65535;
        const int n = rem >> 8;
        const int k = rem & 255;
        const float* Wm = (mat == 0) ? Wq : (mat == 1) ? Wk : (mat == 2) ? Wv : Wo;
        __nv_bfloat16* oh = wth + (size_t)mat * 65536 + (size_t)n * 256 + k;
        __nv_bfloat16* ol = wtl + (size_t)mat * 65536 + (size_t)n * 256 + k;
#pragma unroll
        for (int q = 0; q < 4; q++) {
            float v = Wm[(size_t)(k + q) * 256 + n];
            __nv_bfloat16 h = __float2bfloat16(v);
            oh[q] = h;
            ol[q] = __float2bfloat16(v - __bfloat162float(h));
        }
    }
}

// ---------------- KNN kernel v4: warp-cooperative top-10 ----------------
// grid (128,4), 256 thr; warp handles 4 rows as 2 pairs. The top-10 list for
// each row lives ACROSS lanes 0..9 (sorted ascending). Scan tests d < tau
// (tau = rank-9 value, warp-uniform); insert events (~70/row) do a
// ballot-position insert with shfl_up shift. Distance uses the FULL
// d = sqi + |pj|^2 - 2*dot (the shifted form cancels catastrophically).
#define KCHUNK 1024
__global__ void __launch_bounds__(256) knn_kernel(const float* __restrict__ coords,
                                                  int* __restrict__ knn_out) {
    __shared__ float4 sp[KCHUNK];
    const int b = blockIdx.y;
    const float* coo = coords + (size_t)b * VOX * 3;
    const int warp = threadIdx.x >> 5;
    const int lane = threadIdx.x & 31;
    const unsigned FULL = 0xffffffffu;

    for (int pair = 0; pair < 2; pair++) {
        const int i0 = blockIdx.x * 32 + warp * 4 + pair * 2;
        const int i1 = i0 + 1;
        const float x0 = coo[3*i0], y0 = coo[3*i0+1], z0 = coo[3*i0+2];
        const float x1 = coo[3*i1], y1 = coo[3*i1+1], z1 = coo[3*i1+2];
        const float sq0 = x0*x0 + y0*y0 + z0*z0;
        const float sq1 = x1*x1 + y1*y1 + z1*z1;

        // cross-lane sorted list: lane k (k<10) holds rank-k (value, index)
        float v0 = 1e30f, v1 = 1e30f;
        int  iv0 = 0x7fffffff, iv1 = 0x7fffffff;
        float tau0 = 1e30f, tau1 = 1e30f;

        for (int c = 0; c < VOX / KCHUNK; c++) {
            __syncthreads();
            for (int j = threadIdx.x; j < KCHUNK; j += 256) {
                const int jj = c * KCHUNK + j;
                const float xx = coo[3*jj], yy = coo[3*jj+1], zz = coo[3*jj+2];
                sp[j] = make_float4(xx, yy, zz, xx*xx + yy*yy + zz*zz);
            }
            __syncthreads();

            const int jbase = c * KCHUNK;
            for (int j = lane; j < KCHUNK; j += 32) {
                const float4 p = sp[j];
                const int jj = jbase + j;
                float e0 = sq0 + p.w - 2.0f*(x0*p.x + y0*p.y + z0*p.z);
                float e1 = sq1 + p.w - 2.0f*(x1*p.x + y1*p.y + z1*p.z);
                if (jj == i0) e0 = 1e30f;
                if (jj == i1) e1 = 1e30f;

                // ---- row 0 events ----
                unsigned m0 = __ballot_sync(FULL, e0 < tau0);
                while (m0) {
                    const int s = __ffs(m0) - 1; m0 &= m0 - 1;   // ascending j
                    const float bd = __shfl_sync(FULL, e0, s);
                    const int   bj = jj - lane + s;              // lane s's jj
                    if (bd < tau0) {   // re-check: tau tightens within batch;
                                       // guarantees ballot bit 9 set => p <= 9
                        const unsigned bal = __ballot_sync(FULL, bd < v0);
                        const int pp = __ffs(bal) - 1;
                        const float pv = __shfl_up_sync(FULL, v0, 1);
                        const int   pi = __shfl_up_sync(FULL, iv0, 1);
                        if (lane > pp)  { v0 = pv; iv0 = pi; }
                        if (lane == pp) { v0 = bd; iv0 = bj; }
                        tau0 = __shfl_sync(FULL, v0, 9);
                    }
                }
                // ---- row 1 events ----
                unsigned m1 = __ballot_sync(FULL, e1 < tau1);
                while (m1) {
                    const int s = __ffs(m1) - 1; m1 &= m1 - 1;
                    const float bd = __shfl_sync(FULL, e1, s);
                    const int   bj = jj - lane + s;
                    if (bd < tau1) {
                        const unsigned bal = __ballot_sync(FULL, bd < v1);
                        const int pp = __ffs(bal) - 1;
                        const float pv = __shfl_up_sync(FULL, v1, 1);
                        const int   pi = __shfl_up_sync(FULL, iv1, 1);
                        if (lane > pp)  { v1 = pv; iv1 = pi; }
                        if (lane == pp) { v1 = bd; iv1 = bj; }
                        tau1 = __shfl_sync(FULL, v1, 9);
                    }
                }
            }
        }

        if (lane < KNN_N) {
            knn_out[((b << 12) + i0) * KNN_N + lane] = iv0;
            knn_out[((b << 12) + i1) * KNN_N + lane] = iv1;
        }
    }
}

// ---------------- fp32 GEMM tile (selection path) ----------------
__device__ __forceinline__ void gemm_tile_f32(const float* __restrict__ A,
        const float* __restrict__ W, const float* __restrict__ bias,
        float* __restrict__ C, int N, int ldw, int m0, int n0) {
    __shared__ float As[2][16][132];
    __shared__ float Bs[2][16][64];

    const int t  = threadIdx.x;
    const int tx = t & 15;
    const int ty = t >> 4;

    const int kq = (t & 3) * 4;
    const int ma = t >> 2;
    const int kb = t >> 4;
    const int nb = (t & 15) * 4;

    const float* Ab = A + (size_t)m0 * 256;

    float4 ra0 = *(const float4*)(Ab + (size_t)ma * 256 + kq);
    float4 ra1 = *(const float4*)(Ab + (size_t)(ma + 64) * 256 + kq);
    float4 rb  = *(const float4*)(W + (size_t)kb * ldw + n0 + nb);

    float acc[8][4];
#pragma unroll
    for (int i = 0; i < 8; i++)
#pragma unroll
        for (int j = 0; j < 4; j++) acc[i][j] = 0.0f;

    As[0][kq+0][ma] = ra0.x; As[0][kq+1][ma] = ra0.y; As[0][kq+2][ma] = ra0.z; As[0][kq+3][ma] = ra0.w;
    As[0][kq+0][ma+64] = ra1.x; As[0][kq+1][ma+64] = ra1.y; As[0][kq+2][ma+64] = ra1.z; As[0][kq+3][ma+64] = ra1.w;
    *(float4*)&Bs[0][kb][nb] = rb;
    __syncthreads();

    int cur = 0;
#pragma unroll
    for (int k0 = 0; k0 < 256; k0 += 16) {
        const bool more = (k0 + 16) < 256;
        if (more) {
            ra0 = *(const float4*)(Ab + (size_t)ma * 256 + k0 + 16 + kq);
            ra1 = *(const float4*)(Ab + (size_t)(ma + 64) * 256 + k0 + 16 + kq);
            rb  = *(const float4*)(W + (size_t)(k0 + 16 + kb) * ldw + n0 + nb);
        }
#pragma unroll
        for (int k = 0; k < 16; k++) {
            float ra[8], rbv[4];
            float4 a0 = *(const float4*)&As[cur][k][ty*8];
            float4 a1 = *(const float4*)&As[cur][k][ty*8+4];
            ra[0]=a0.x; ra[1]=a0.y; ra[2]=a0.z; ra[3]=a0.w;
            ra[4]=a1.x; ra[5]=a1.y; ra[6]=a1.z; ra[7]=a1.w;
            float4 b4 = *(const float4*)&Bs[cur][k][tx*4];
            rbv[0]=b4.x; rbv[1]=b4.y; rbv[2]=b4.z; rbv[3]=b4.w;
#pragma unroll
            for (int i = 0; i < 8; i++)
#pragma unroll
                for (int j = 0; j < 4; j++)
                    acc[i][j] += ra[i] * rbv[j];
        }
        if (more) {
            const int nx = cur ^ 1;
            As[nx][kq+0][ma] = ra0.x; As[nx][kq+1][ma] = ra0.y; As[nx][kq+2][ma] = ra0.z; As[nx][kq+3][ma] = ra0.w;
            As[nx][kq+0][ma+64] = ra1.x; As[nx][kq+1][ma+64] = ra1.y; As[nx][kq+2][ma+64] = ra1.z; As[nx][kq+3][ma+64] = ra1.w;
            *(float4*)&Bs[nx][kb][nb] = rb;
        }
        __syncthreads();
        cur ^= 1;
    }

    float4 bv = make_float4(0.f, 0.f, 0.f, 0.f);
    if (bias) bv = *(const float4*)(bias + n0 + tx*4);
#pragma unroll
    for (int i = 0; i < 8; i++) {
        const int row = m0 + ty*8 + i;
        float4 o;
        o.x = acc[i][0] + bv.x;
        o.y = acc[i][1] + bv.y;
        o.z = acc[i][2] + bv.z;
        o.w = acc[i][3] + bv.w;
        *(float4*)(C + (size_t)row * N + n0 + tx*4) = o;
    }
}

__global__ void __launch_bounds__(256) gemm_ab_kernel(
        const float* __restrict__ tok, const float* __restrict__ W1,
        const float* __restrict__ b1, float* __restrict__ gA, float* __restrict__ gB) {
    const int z = blockIdx.y;
    const float* W    = z ? (W1 + 256*HIDN) : W1;
    const float* bias = z ? nullptr : b1;
    float*       C    = z ? gB : gA;
    gemm_tile_f32(tok, W, bias, C, HIDN, HIDN, blockIdx.x * 128, 0);
}

// ---------------- split-bf16 tensor-core GEMM v2 (pre-converted operands) ----------------
__device__ __forceinline__ void mma_bf16(float* c, const uint32_t* a, const uint32_t* b) {
    asm volatile(
        "mma.sync.aligned.m16n8k16.row.col.f32.bf16.bf16.f32 "
        "{%0,%1,%2,%3}, {%4,%5,%6,%7}, {%8,%9}, {%0,%1,%2,%3};\n"
        : "+f"(c[0]), "+f"(c[1]), "+f"(c[2]), "+f"(c[3])
        : "r"(a[0]), "r"(a[1]), "r"(a[2]), "r"(a[3]), "r"(b[0]), "r"(b[1]));
}

#define ASTRIDE 40   // halves; 80B row stride -> conflict-free fragment loads

__device__ __forceinline__ void tc_gemm_tile_v2(
        const __nv_bfloat16* __restrict__ Ahi, const __nv_bfloat16* __restrict__ Alo,
        const __nv_bfloat16* __restrict__ Bth, const __nv_bfloat16* __restrict__ Btl,
        const float* __restrict__ bias, float* __restrict__ C, int m0, int n0) {
    __shared__ __nv_bfloat16 Ah[128][ASTRIDE], Al[128][ASTRIDE];
    __shared__ __nv_bfloat16 Bh[64][ASTRIDE],  Bl[64][ASTRIDE];

    const int t    = threadIdx.x;
    const int warp = t >> 5;
    const int lane = t & 31;
    const int g    = lane >> 2;
    const int tg   = lane & 3;
    const int mw   = warp & 3;
    const int nw   = warp >> 2;

    const int ar = t >> 2;
    const int ao = (t & 3) * 8;
    const int br = t >> 2;
    const int bo = (t & 3) * 8;

    const __nv_bfloat16* Ah_g = Ahi + (size_t)(m0 + ar) * 256 + ao;
    const __nv_bfloat16* Al_g = Alo + (size_t)(m0 + ar) * 256 + ao;
    const __nv_bfloat16* Bh_g = Bth + (size_t)(n0 + br) * 256 + bo;
    const __nv_bfloat16* Bl_g = Btl + (size_t)(n0 + br) * 256 + bo;

    float acc[2][4][4];
#pragma unroll
    for (int mt = 0; mt < 2; mt++)
#pragma unroll
        for (int nt = 0; nt < 4; nt++)
#pragma unroll
            for (int e = 0; e < 4; e++) acc[mt][nt][e] = 0.0f;

    uint4 rAh0 = *(const uint4*)(Ah_g);
    uint4 rAh1 = *(const uint4*)(Ah_g + (size_t)64 * 256);
    uint4 rAl0 = *(const uint4*)(Al_g);
    uint4 rAl1 = *(const uint4*)(Al_g + (size_t)64 * 256);
    uint4 rBh  = *(const uint4*)(Bh_g);
    uint4 rBl  = *(const uint4*)(Bl_g);

#pragma unroll
    for (int k0 = 0; k0 < 256; k0 += 32) {
        *(uint4*)&Ah[ar][ao]      = rAh0;
        *(uint4*)&Ah[ar + 64][ao] = rAh1;
        *(uint4*)&Al[ar][ao]      = rAl0;
        *(uint4*)&Al[ar + 64][ao] = rAl1;
        *(uint4*)&Bh[br][bo]      = rBh;
        *(uint4*)&Bl[br][bo]      = rBl;
        __syncthreads();

        if (k0 + 32 < 256) {
            const int kn = k0 + 32;
            rAh0 = *(const uint4*)(Ah_g + kn);
            rAh1 = *(const uint4*)(Ah_g + (size_t)64 * 256 + kn);
            rAl0 = *(const uint4*)(Al_g + kn);
            rAl1 = *(const uint4*)(Al_g + (size_t)64 * 256 + kn);
            rBh  = *(const uint4*)(Bh_g + kn);
            rBl  = *(const uint4*)(Bl_g + kn);
        }

#pragma unroll
        for (int ks = 0; ks < 32; ks += 16) {
            uint32_t ah[2][4], al[2][4];
#pragma unroll
            for (int mt = 0; mt < 2; mt++) {
                const int r = mw*32 + mt*16 + g;
                ah[mt][0] = *(const uint32_t*)&Ah[r][ks + 2*tg];
                ah[mt][1] = *(const uint32_t*)&Ah[r+8][ks + 2*tg];
                ah[mt][2] = *(const uint32_t*)&Ah[r][ks + 8 + 2*tg];
                ah[mt][3] = *(const uint32_t*)&Ah[r+8][ks + 8 + 2*tg];
                al[mt][0] = *(const uint32_t*)&Al[r][ks + 2*tg];
                al[mt][1] = *(const uint32_t*)&Al[r+8][ks + 2*tg];
                al[mt][2] = *(const uint32_t*)&Al[r][ks + 8 + 2*tg];
                al[mt][3] = *(const uint32_t*)&Al[r+8][ks + 8 + 2*tg];
            }
            uint32_t bh[4][2], bl[4][2];
#pragma unroll
            for (int nt = 0; nt < 4; nt++) {
                const int n = nw*32 + nt*8 + g;
                bh[nt][0] = *(const uint32_t*)&Bh[n][ks + 2*tg];
                bh[nt][1] = *(const uint32_t*)&Bh[n][ks + 8 + 2*tg];
                bl[nt][0] = *(const uint32_t*)&Bl[n][ks + 2*tg];
                bl[nt][1] = *(const uint32_t*)&Bl[n][ks + 8 + 2*tg];
            }
#pragma unroll
            for (int mt = 0; mt < 2; mt++)
#pragma unroll
                for (int nt = 0; nt < 4; nt++) {
                    mma_bf16(acc[mt][nt], ah[mt], bh[nt]);
                    mma_bf16(acc[mt][nt], ah[mt], bl[nt]);
                    mma_bf16(acc[mt][nt], al[mt], bh[nt]);
                }
        }
        __syncthreads();
    }

#pragma unroll
    for (int nt = 0; nt < 4; nt++) {
        const int c = n0 + nw*32 + nt*8 + 2*tg;
        float bx = 0.f, by = 0.f;
        if (bias) { bx = bias[c]; by = bias[c+1]; }
#pragma unroll
        for (int mt = 0; mt < 2; mt++) {
            const int r = m0 + mw*32 + mt*16 + g;
            float* Cp = C + (size_t)r * 256 + c;
            Cp[0] = acc[mt][nt][0] + bx;
            Cp[1] = acc[mt][nt][1] + by;
            Cp[(size_t)8*256]     = acc[mt][nt][2] + bx;
            Cp[(size_t)8*256 + 1] = acc[mt][nt][3] + by;
        }
    }
}

__global__ void __launch_bounds__(256) tc_qkv_kernel(
        const __nv_bfloat16* __restrict__ tokh, const __nv_bfloat16* __restrict__ tokl,
        const __nv_bfloat16* __restrict__ wth,  const __nv_bfloat16* __restrict__ wtl,
        const float* __restrict__ bq, const float* __restrict__ bk, const float* __restrict__ bv,
        float* __restrict__ gQ, float* __restrict__ gK, float* __restrict__ gV) {
    const int z = blockIdx.z;
    const float* bias = (z == 0) ? bq : (z == 1) ? bk : bv;
    float*       C    = (z == 0) ? gQ : (z == 1) ? gK : gV;
    tc_gemm_tile_v2(tokh, tokl, wth + (size_t)z * 65536, wtl + (size_t)z * 65536,
                    bias, C, blockIdx.x * 128, blockIdx.y * 64);
}

__global__ void __launch_bounds__(256) tc_o_kernel(
        const __nv_bfloat16* __restrict__ ctxh, const __nv_bfloat16* __restrict__ ctxl,
        const __nv_bfloat16* __restrict__ wth,  const __nv_bfloat16* __restrict__ wtl,
        const float* __restrict__ bo, float* __restrict__ out) {
    tc_gemm_tile_v2(ctxh, ctxl, wth + (size_t)3 * 65536, wtl + (size_t)3 * 65536,
                    bo, out, blockIdx.x * 128, blockIdx.y * 64);
}

// ---------------- fused score + top-4 select + attention ----------------
__global__ void score_attn_kernel(const float* __restrict__ coords,
                                  const float* __restrict__ W1,
                                  const float* __restrict__ W2,
                                  const int* __restrict__ knn,
                                  const float* __restrict__ gA,
                                  const float* __restrict__ gB,
                                  const float* __restrict__ gQ,
                                  const float* __restrict__ gK,
                                  const float* __restrict__ gV,
                                  __nv_bfloat16* __restrict__ ctxh,
                                  __nv_bfloat16* __restrict__ ctxl) {
    __shared__ float sW1c[3][64];
    __shared__ float sW2[64];
    const int t = threadIdx.x;
    if (t < 64) {
        sW2[t]     = W2[t];
        sW1c[0][t] = W1[512*64 + t];
        sW1c[1][t] = W1[513*64 + t];
        sW1c[2][t] = W1[514*64 + t];
    }
    __syncthreads();

    const int warp = t >> 5, lane = t & 31;
    const int g = blockIdx.x * 8 + warp;
    const int b = g >> 12;
    const int i = g & 4095;
    const float* coo = coords + (size_t)b * VOX * 3;
    const float xi = coo[3*i+0], yi = coo[3*i+1], zi = coo[3*i+2];

    const float a0  = gA[(size_t)g*64 + lane];
    const float a1  = gA[(size_t)g*64 + lane + 32];
    const float w2a = sW2[lane], w2b = sW2[lane + 32];
    const float c0a = sW1c[0][lane], c0b = sW1c[0][lane+32];
    const float c1a = sW1c[1][lane], c1b = sW1c[1][lane+32];
    const float c2a = sW1c[2][lane], c2b = sW1c[2][lane+32];

    float bs[TOPK_N] = {-1e30f, -1e30f, -1e30f, -1e30f};
    int   bj[TOPK_N] = {0, 0, 0, 0};

#pragma unroll
    for (int nb = 0; nb < KNN_N; nb++) {
        const int j = knn[g*KNN_N + nb];
        const float rx = coo[3*j+0] - xi;
        const float ry = coo[3*j+1] - yi;
        const float rz = coo[3*j+2] - zi;
        const float* Bj = gB + ((size_t)(b << 12) + j) * 64;
        float h0 = a0 + Bj[lane]      + rx*c0a + ry*c1a + rz*c2a;
        float h1 = a1 + Bj[lane + 32] + rx*c0b + ry*c1b + rz*c2b;
        h0 = fmaxf(h0, 0.0f);
        h1 = fmaxf(h1, 0.0f);
        float p = h0 * w2a + h1 * w2b;
#pragma unroll
        for (int off = 16; off; off >>= 1) p += __shfl_xor_sync(0xffffffffu, p, off);
        float cs = p; int cj = j;
#pragma unroll
        for (int k = 0; k < TOPK_N; k++) {
            const bool better = cs > bs[k];
            const float ts = better ? bs[k] : cs;
            const int   tj = better ? bj[k] : cj;
            bs[k] = better ? cs : bs[k];
            bj[k] = better ? cj : bj[k];
            cs = ts; cj = tj;
        }
    }

    const size_t base = (size_t)g * DIM + lane * 8;
    const float4 q0 = *(const float4*)(gQ + base);
    const float4 q1 = *(const float4*)(gQ + base + 4);

    float att[TOPK_N];
#pragma unroll
    for (int s = 0; s < TOPK_N; s++) {
        const size_t jb = ((size_t)(b << 12) + bj[s]) * DIM + lane * 8;
        const float4* Kp = (const float4*)(gK + jb);
        const float4 k0 = Kp[0], k1 = Kp[1];
        float p = q0.x*k0.x + q0.y*k0.y + q0.z*k0.z + q0.w*k0.w
                + q1.x*k1.x + q1.y*k1.y + q1.z*k1.z + q1.w*k1.w;
        p += __shfl_xor_sync(0xffffffffu, p, 4);
        p += __shfl_xor_sync(0xffffffffu, p, 2);
        p += __shfl_xor_sync(0xffffffffu, p, 1);
        att[s] = p * 0.125f;
    }
    float m = fmaxf(fmaxf(att[0], att[1]), fmaxf(att[2], att[3]));
    float e[TOPK_N], ssum = 0.0f;
#pragma unroll
    for (int s = 0; s < TOPK_N; s++) { e[s] = expf(att[s] - m); ssum += e[s]; }
    const float inv = 1.0f / ssum;

    float cv[8] = {0.f,0.f,0.f,0.f,0.f,0.f,0.f,0.f};
#pragma unroll
    for (int s = 0; s < TOPK_N; s++) {
        const float w = e[s] * inv;
        const size_t jb = ((size_t)(b << 12) + bj[s]) * DIM + lane * 8;
        const float4* Vp = (const float4*)(gV + jb);
        const float4 v0 = Vp[0], v1 = Vp[1];
        cv[0] += w*v0.x; cv[1] += w*v0.y; cv[2] += w*v0.z; cv[3] += w*v0.w;
        cv[4] += w*v1.x; cv[5] += w*v1.y; cv[6] += w*v1.z; cv[7] += w*v1.w;
    }
    uint32_t uh[4], ul[4];
#pragma unroll
    for (int q = 0; q < 4; q++) {
        __nv_bfloat16 h0 = __float2bfloat16(cv[2*q]);
        __nv_bfloat16 h1 = __float2bfloat16(cv[2*q+1]);
        __nv_bfloat16 l0 = __float2bfloat16(cv[2*q]   - __bfloat162float(h0));
        __nv_bfloat16 l1 = __float2bfloat16(cv[2*q+1] - __bfloat162float(h1));
        __nv_bfloat162 ph(h0, h1), pl(l0, l1);
        uh[q] = *(uint32_t*)&ph;
        ul[q] = *(uint32_t*)&pl;
    }
    *(uint4*)(ctxh + base) = make_uint4(uh[0], uh[1], uh[2], uh[3]);
    *(uint4*)(ctxl + base) = make_uint4(ul[0], ul[1], ul[2], ul[3]);
}

// ---------------- launch ----------------
extern "C" void kernel_launch(void* const* d_in, const int* in_sizes, int n_in,
                              void* d_out, int out_size) {
    const float* tok    = (const float*)d_in[0];
    const float* coords = (const float*)d_in[1];
    const float* W1 = (const float*)d_in[3];
    const float* b1 = (const float*)d_in[4];
    const float* W2 = (const float*)d_in[5];
    const float* Wq = (const float*)d_in[7];
    const float* bq = (const float*)d_in[8];
    const float* Wk = (const float*)d_in[9];
    const float* bk = (const float*)d_in[10];
    const float* Wv = (const float*)d_in[11];
    const float* bv = (const float*)d_in[12];
    const float* Wo = (const float*)d_in[13];
    const float* bo = (const float*)d_in[14];
    float* out = (float*)d_out;

    void* bufp = nullptr;
    cudaGetSymbolAddress(&bufp, g_buf);
    float* buf = (float*)bufp;
    float* gA   = buf + OFF_A;
    float* gB   = buf + OFF_B;
    float* gQ   = buf + OFF_Q;
    float* gK   = buf + OFF_K;
    float* gV   = buf + OFF_V;
    int*   gknn = (int*)(buf + OFF_KNN);
    __nv_bfloat16* ctxh = (__nv_bfloat16*)(buf + OFF_CTXH);
    __nv_bfloat16* ctxl = (__nv_bfloat16*)(buf + OFF_CTXL);
    __nv_bfloat16* tokh = (__nv_bfloat16*)(buf + OFF_TOKH);
    __nv_bfloat16* tokl = (__nv_bfloat16*)(buf + OFF_TOKL);
    __nv_bfloat16* wth  = (__nv_bfloat16*)(buf + OFF_WTH);
    __nv_bfloat16* wtl  = (__nv_bfloat16*)(buf + OFF_WTL);

    // #0: split-convert tok and weights
    convert_kernel<<<4352, 256>>>(tok, Wq, Wk, Wv, Wo, tokh, tokl, wth, wtl);
    // #1: A+B (fp32, selection path)
    gemm_ab_kernel<<<dim3(GTOT/128, 2), 256>>>(tok, W1, b1, gA, gB);
    // #2: Q/K/V tensor-core gemm (pre-converted)
    tc_qkv_kernel<<<dim3(GTOT/128, DIM/64, 3), 256>>>(tokh, tokl, wth, wtl, bq, bk, bv, gQ, gK, gV);
    // #3: knn v4  <-- ncu capture slot (launch index 3)
    knn_kernel<<<dim3(128, 4), 256>>>(coords, gknn);
    // #4: fused score + select + attention (writes split ctx)
    score_attn_kernel<<<GTOT/8, 256>>>(coords, W1, W2, gknn, gA, gB, gQ, gK, gV, ctxh, ctxl);
    // #5: output projection
    tc_o_kernel<<<dim3(GTOT/128, DIM/64), 256>>>(ctxh, ctxl, wth, wtl, bo, out);
}

// round 10
// speedup vs baseline: 2.6756x; 1.0140x over previous
#include <cuda_runtime.h>
#include <cuda_bf16.h>
#include <cstdint>

#define BATCH 4
#define VOX   4096
#define DIM   256
#define HIDN  64
#define KNN_N 10
#define TOPK_N 4
#define GTOT  (BATCH*VOX)   // 16384

// ---------------- device scratch (float units) ----------------
#define OFF_A    0
#define OFF_B    1048576
#define OFF_Q    2097152
#define OFF_K    6291456
#define OFF_V    10485760
#define OFF_CTXH 14680064              // 16384*256 halves
#define OFF_CTXL 16777216
#define OFF_KNN  18874368              // 16384*10 ints
#define OFF_TOKH 19038208              // 16384*256 halves
#define OFF_TOKL 21135360
#define OFF_WTH  23232512              // 4*256*256 halves (transposed W's)
#define OFF_WTL  23363584
#define BUF_TOTAL 23494656

static __device__ float g_buf[BUF_TOTAL];

// ---------------- convert: tok -> split bf16 ----------------
__global__ void __launch_bounds__(256) convert_tok_kernel(
        const float* __restrict__ tok,
        __nv_bfloat16* __restrict__ tokh, __nv_bfloat16* __restrict__ tokl) {
    const int idx = blockIdx.x * 256 + threadIdx.x;    // float4 index
    const int m = idx >> 6;
    const int c = (idx & 63) * 4;
    float4 v = *(const float4*)(tok + (size_t)m * 256 + c);
    __nv_bfloat16* ph = tokh + (size_t)m * 256 + c;
    __nv_bfloat16* pl = tokl + (size_t)m * 256 + c;
    float vv[4] = {v.x, v.y, v.z, v.w};
#pragma unroll
    for (int q = 0; q < 4; q++) {
        __nv_bfloat16 h = __float2bfloat16(vv[q]);
        ph[q] = h;
        pl[q] = __float2bfloat16(vv[q] - __bfloat162float(h));
    }
}

// ---------------- convert: two W's -> transposed split bf16 ----------------
// 128 blocks cover 2 matrices (65536 elems each)
__global__ void __launch_bounds__(256) convert_w_kernel(
        const float* __restrict__ Wa, const float* __restrict__ Wb,
        __nv_bfloat16* __restrict__ oh_base, __nv_bfloat16* __restrict__ ol_base) {
    const int elem = blockIdx.x * 1024 + threadIdx.x * 4;
    const int mat = elem >> 16;            // 0 or 1
    const int rem = elem & 65535;
    const int n = rem >> 8;
    const int k = rem & 255;
    const float* Wm = mat ? Wb : Wa;
    __nv_bfloat16* oh = oh_base + (size_t)mat * 65536 + (size_t)n * 256 + k;
    __nv_bfloat16* ol = ol_base + (size_t)mat * 65536 + (size_t)n * 256 + k;
#pragma unroll
    for (int q = 0; q < 4; q++) {
        float v = Wm[(size_t)(k + q) * 256 + n];
        __nv_bfloat16 h = __float2bfloat16(v);
        oh[q] = h;
        ol[q] = __float2bfloat16(v - __bfloat162float(h));
    }
}

// ================= mega-kernel bodies (share one smem union) =================
#define SMEM_UNION_BYTES 30720

// ---------------- KNN body v5: 4 rows, single scan pass ----------------
// Cross-lane sorted top-10 per row (lane k holds rank-k). Events via ballot +
// shfl_up insert. Full d = sqi + |pj|^2 - 2*dot (shifted form cancels; don't).
#define KCHUNK 1024
#define FULLM 0xffffffffu

#define KNN_EVENTS(e, v, iv, tau)                                          \
    {                                                                      \
        unsigned mm = __ballot_sync(FULLM, (e) < (tau));                   \
        while (mm) {                                                       \
            const int s = __ffs(mm) - 1; mm &= mm - 1;  /* ascending j */  \
            const float bd = __shfl_sync(FULLM, (e), s);                   \
            const int   bjj = jj - lane + s;                               \
            if (bd < (tau)) {  /* tau tightens within batch */             \
                const unsigned bal = __ballot_sync(FULLM, bd < (v));       \
                const int pp = __ffs(bal) - 1;                             \
                const float pv = __shfl_up_sync(FULLM, (v), 1);            \
                const int   pi = __shfl_up_sync(FULLM, (iv), 1);           \
                if (lane > pp)  { (v) = pv; (iv) = pi; }                   \
                if (lane == pp) { (v) = bd; (iv) = bjj; }                  \
                (tau) = __shfl_sync(FULLM, (v), 9);                        \
            }                                                              \
        }                                                                  \
    }

__device__ void knn_body(int bx, int b, const float* __restrict__ coords,
                         int* __restrict__ knn_out, char* smem) {
    float4* sp = (float4*)smem;
    const float* coo = coords + (size_t)b * VOX * 3;
    const int warp = threadIdx.x >> 5;
    const int lane = threadIdx.x & 31;

    const int i0 = bx * 32 + warp * 4;
    const float x0 = coo[3*i0+0], y0 = coo[3*i0+1], z0 = coo[3*i0+2];
    const float x1 = coo[3*i0+3], y1 = coo[3*i0+4], z1 = coo[3*i0+5];
    const float x2 = coo[3*i0+6], y2 = coo[3*i0+7], z2 = coo[3*i0+8];
    const float x3 = coo[3*i0+9], y3 = coo[3*i0+10], z3 = coo[3*i0+11];
    const float sq0 = x0*x0 + y0*y0 + z0*z0;
    const float sq1 = x1*x1 + y1*y1 + z1*z1;
    const float sq2 = x2*x2 + y2*y2 + z2*z2;
    const float sq3 = x3*x3 + y3*y3 + z3*z3;

    float v0 = 1e30f, v1 = 1e30f, v2 = 1e30f, v3 = 1e30f;
    int  iv0 = 0x7fffffff, iv1 = 0x7fffffff, iv2 = 0x7fffffff, iv3 = 0x7fffffff;
    float tau0 = 1e30f, tau1 = 1e30f, tau2 = 1e30f, tau3 = 1e30f;

    for (int c = 0; c < VOX / KCHUNK; c++) {
        __syncthreads();
        for (int j = threadIdx.x; j < KCHUNK; j += 256) {
            const int jj = c * KCHUNK + j;
            const float xx = coo[3*jj], yy = coo[3*jj+1], zz = coo[3*jj+2];
            sp[j] = make_float4(xx, yy, zz, xx*xx + yy*yy + zz*zz);
        }
        __syncthreads();

        const int jbase = c * KCHUNK;
        for (int j = lane; j < KCHUNK; j += 32) {
            const float4 p = sp[j];
            const int jj = jbase + j;
            float e0 = sq0 + p.w - 2.0f*(x0*p.x + y0*p.y + z0*p.z);
            float e1 = sq1 + p.w - 2.0f*(x1*p.x + y1*p.y + z1*p.z);
            float e2 = sq2 + p.w - 2.0f*(x2*p.x + y2*p.y + z2*p.z);
            float e3 = sq3 + p.w - 2.0f*(x3*p.x + y3*p.y + z3*p.z);
            if (jj == i0)     e0 = 1e30f;
            if (jj == i0 + 1) e1 = 1e30f;
            if (jj == i0 + 2) e2 = 1e30f;
            if (jj == i0 + 3) e3 = 1e30f;
            KNN_EVENTS(e0, v0, iv0, tau0)
            KNN_EVENTS(e1, v1, iv1, tau1)
            KNN_EVENTS(e2, v2, iv2, tau2)
            KNN_EVENTS(e3, v3, iv3, tau3)
        }
    }

    if (lane < KNN_N) {
        knn_out[((b << 12) + i0 + 0) * KNN_N + lane] = iv0;
        knn_out[((b << 12) + i0 + 1) * KNN_N + lane] = iv1;
        knn_out[((b << 12) + i0 + 2) * KNN_N + lane] = iv2;
        knn_out[((b << 12) + i0 + 3) * KNN_N + lane] = iv3;
    }
}

// ---------------- fp32 GEMM body (selection path) ----------------
__device__ void gemm_tile_f32(const float* __restrict__ A,
        const float* __restrict__ W, const float* __restrict__ bias,
        float* __restrict__ C, int N, int ldw, int m0, int n0, char* smem) {
    float* As = (float*)smem;        // [2][16][132]
    float* Bs = As + 2*16*132;       // [2][16][64]
#define ASX(buf,k,m) As[((buf)*16 + (k))*132 + (m)]
#define BSX(buf,k,n) Bs[((buf)*16 + (k))*64 + (n)]

    const int t  = threadIdx.x;
    const int tx = t & 15;
    const int ty = t >> 4;

    const int kq = (t & 3) * 4;
    const int ma = t >> 2;
    const int kb = t >> 4;
    const int nb = (t & 15) * 4;

    const float* Ab = A + (size_t)m0 * 256;

    float4 ra0 = *(const float4*)(Ab + (size_t)ma * 256 + kq);
    float4 ra1 = *(const float4*)(Ab + (size_t)(ma + 64) * 256 + kq);
    float4 rb  = *(const float4*)(W + (size_t)kb * ldw + n0 + nb);

    float acc[8][4];
#pragma unroll
    for (int i = 0; i < 8; i++)
#pragma unroll
        for (int j = 0; j < 4; j++) acc[i][j] = 0.0f;

    ASX(0,kq+0,ma) = ra0.x; ASX(0,kq+1,ma) = ra0.y; ASX(0,kq+2,ma) = ra0.z; ASX(0,kq+3,ma) = ra0.w;
    ASX(0,kq+0,ma+64) = ra1.x; ASX(0,kq+1,ma+64) = ra1.y; ASX(0,kq+2,ma+64) = ra1.z; ASX(0,kq+3,ma+64) = ra1.w;
    *(float4*)&BSX(0,kb,nb) = rb;
    __syncthreads();

    int cur = 0;
#pragma unroll
    for (int k0 = 0; k0 < 256; k0 += 16) {
        const bool more = (k0 + 16) < 256;
        if (more) {
            ra0 = *(const float4*)(Ab + (size_t)ma * 256 + k0 + 16 + kq);
            ra1 = *(const float4*)(Ab + (size_t)(ma + 64) * 256 + k0 + 16 + kq);
            rb  = *(const float4*)(W + (size_t)(k0 + 16 + kb) * ldw + n0 + nb);
        }
#pragma unroll
        for (int k = 0; k < 16; k++) {
            float ra[8], rbv[4];
            float4 a0 = *(const float4*)&ASX(cur,k,ty*8);
            float4 a1 = *(const float4*)&ASX(cur,k,ty*8+4);
            ra[0]=a0.x; ra[1]=a0.y; ra[2]=a0.z; ra[3]=a0.w;
            ra[4]=a1.x; ra[5]=a1.y; ra[6]=a1.z; ra[7]=a1.w;
            float4 b4 = *(const float4*)&BSX(cur,k,tx*4);
            rbv[0]=b4.x; rbv[1]=b4.y; rbv[2]=b4.z; rbv[3]=b4.w;
#pragma unroll
            for (int i = 0; i < 8; i++)
#pragma unroll
                for (int j = 0; j < 4; j++)
                    acc[i][j] += ra[i] * rbv[j];
        }
        if (more) {
            const int nx = cur ^ 1;
            ASX(nx,kq+0,ma) = ra0.x; ASX(nx,kq+1,ma) = ra0.y; ASX(nx,kq+2,ma) = ra0.z; ASX(nx,kq+3,ma) = ra0.w;
            ASX(nx,kq+0,ma+64) = ra1.x; ASX(nx,kq+1,ma+64) = ra1.y; ASX(nx,kq+2,ma+64) = ra1.z; ASX(nx,kq+3,ma+64) = ra1.w;
            *(float4*)&BSX(nx,kb,nb) = rb;
        }
        __syncthreads();
        cur ^= 1;
    }

    float4 bv = make_float4(0.f, 0.f, 0.f, 0.f);
    if (bias) bv = *(const float4*)(bias + n0 + tx*4);
#pragma unroll
    for (int i = 0; i < 8; i++) {
        const int row = m0 + ty*8 + i;
        float4 o;
        o.x = acc[i][0] + bv.x;
        o.y = acc[i][1] + bv.y;
        o.z = acc[i][2] + bv.z;
        o.w = acc[i][3] + bv.w;
        *(float4*)(C + (size_t)row * N + n0 + tx*4) = o;
    }
#undef ASX
#undef BSX
}

// ---------------- split-bf16 tensor-core GEMM body ----------------
__device__ __forceinline__ void mma_bf16(float* c, const uint32_t* a, const uint32_t* b) {
    asm volatile(
        "mma.sync.aligned.m16n8k16.row.col.f32.bf16.bf16.f32 "
        "{%0,%1,%2,%3}, {%4,%5,%6,%7}, {%8,%9}, {%0,%1,%2,%3};\n"
        : "+f"(c[0]), "+f"(c[1]), "+f"(c[2]), "+f"(c[3])
        : "r"(a[0]), "r"(a[1]), "r"(a[2]), "r"(a[3]), "r"(b[0]), "r"(b[1]));
}

#define ASTRIDE 40   // halves; 80B row stride -> conflict-free fragment loads

__device__ void tc_gemm_tile_v2(
        const __nv_bfloat16* __restrict__ Ahi, const __nv_bfloat16* __restrict__ Alo,
        const __nv_bfloat16* __restrict__ Bth, const __nv_bfloat16* __restrict__ Btl,
        const float* __restrict__ bias, float* __restrict__ C, int m0, int n0,
        char* smem) {
    __nv_bfloat16* Ah = (__nv_bfloat16*)smem;        // 128*ASTRIDE
    __nv_bfloat16* Al = Ah + 128*ASTRIDE;
    __nv_bfloat16* Bh = Al + 128*ASTRIDE;            // 64*ASTRIDE
    __nv_bfloat16* Bl = Bh + 64*ASTRIDE;

    const int t    = threadIdx.x;
    const int warp = t >> 5;
    const int lane = t & 31;
    const int g    = lane >> 2;
    const int tg   = lane & 3;
    const int mw   = warp & 3;
    const int nw   = warp >> 2;

    const int ar = t >> 2;
    const int ao = (t & 3) * 8;
    const int br = t >> 2;
    const int bo = (t & 3) * 8;

    const __nv_bfloat16* Ah_g = Ahi + (size_t)(m0 + ar) * 256 + ao;
    const __nv_bfloat16* Al_g = Alo + (size_t)(m0 + ar) * 256 + ao;
    const __nv_bfloat16* Bh_g = Bth + (size_t)(n0 + br) * 256 + bo;
    const __nv_bfloat16* Bl_g = Btl + (size_t)(n0 + br) * 256 + bo;

    float acc[2][4][4];
#pragma unroll
    for (int mt = 0; mt < 2; mt++)
#pragma unroll
        for (int nt = 0; nt < 4; nt++)
#pragma unroll
            for (int e = 0; e < 4; e++) acc[mt][nt][e] = 0.0f;

    uint4 rAh0 = *(const uint4*)(Ah_g);
    uint4 rAh1 = *(const uint4*)(Ah_g + (size_t)64 * 256);
    uint4 rAl0 = *(const uint4*)(Al_g);
    uint4 rAl1 = *(const uint4*)(Al_g + (size_t)64 * 256);
    uint4 rBh  = *(const uint4*)(Bh_g);
    uint4 rBl  = *(const uint4*)(Bl_g);

#pragma unroll
    for (int k0 = 0; k0 < 256; k0 += 32) {
        *(uint4*)&Ah[ar*ASTRIDE + ao]        = rAh0;
        *(uint4*)&Ah[(ar + 64)*ASTRIDE + ao] = rAh1;
        *(uint4*)&Al[ar*ASTRIDE + ao]        = rAl0;
        *(uint4*)&Al[(ar + 64)*ASTRIDE + ao] = rAl1;
        *(uint4*)&Bh[br*ASTRIDE + bo]        = rBh;
        *(uint4*)&Bl[br*ASTRIDE + bo]        = rBl;
        __syncthreads();

        if (k0 + 32 < 256) {
            const int kn = k0 + 32;
            rAh0 = *(const uint4*)(Ah_g + kn);
            rAh1 = *(const uint4*)(Ah_g + (size_t)64 * 256 + kn);
            rAl0 = *(const uint4*)(Al_g + kn);
            rAl1 = *(const uint4*)(Al_g + (size_t)64 * 256 + kn);
            rBh  = *(const uint4*)(Bh_g + kn);
            rBl  = *(const uint4*)(Bl_g + kn);
        }

#pragma unroll
        for (int ks = 0; ks < 32; ks += 16) {
            uint32_t ah[2][4], al[2][4];
#pragma unroll
            for (int mt = 0; mt < 2; mt++) {
                const int r = mw*32 + mt*16 + g;
                ah[mt][0] = *(const uint32_t*)&Ah[r*ASTRIDE + ks + 2*tg];
                ah[mt][1] = *(const uint32_t*)&Ah[(r+8)*ASTRIDE + ks + 2*tg];
                ah[mt][2] = *(const uint32_t*)&Ah[r*ASTRIDE + ks + 8 + 2*tg];
                ah[mt][3] = *(const uint32_t*)&Ah[(r+8)*ASTRIDE + ks + 8 + 2*tg];
                al[mt][0] = *(const uint32_t*)&Al[r*ASTRIDE + ks + 2*tg];
                al[mt][1] = *(const uint32_t*)&Al[(r+8)*ASTRIDE + ks + 2*tg];
                al[mt][2] = *(const uint32_t*)&Al[r*ASTRIDE + ks + 8 + 2*tg];
                al[mt][3] = *(const uint32_t*)&Al[(r+8)*ASTRIDE + ks + 8 + 2*tg];
            }
            uint32_t bh[4][2], bl[4][2];
#pragma unroll
            for (int nt = 0; nt < 4; nt++) {
                const int n = nw*32 + nt*8 + g;
                bh[nt][0] = *(const uint32_t*)&Bh[n*ASTRIDE + ks + 2*tg];
                bh[nt][1] = *(const uint32_t*)&Bh[n*ASTRIDE + ks + 8 + 2*tg];
                bl[nt][0] = *(const uint32_t*)&Bl[n*ASTRIDE + ks + 2*tg];
                bl[nt][1] = *(const uint32_t*)&Bl[n*ASTRIDE + ks + 8 + 2*tg];
            }
#pragma unroll
            for (int mt = 0; mt < 2; mt++)
#pragma unroll
                for (int nt = 0; nt < 4; nt++) {
                    mma_bf16(acc[mt][nt], ah[mt], bh[nt]);
                    mma_bf16(acc[mt][nt], ah[mt], bl[nt]);
                    mma_bf16(acc[mt][nt], al[mt], bh[nt]);
                }
        }
        __syncthreads();
    }

#pragma unroll
    for (int nt = 0; nt < 4; nt++) {
        const int c = n0 + nw*32 + nt*8 + 2*tg;
        float bx = 0.f, by = 0.f;
        if (bias) { bx = bias[c]; by = bias[c+1]; }
#pragma unroll
        for (int mt = 0; mt < 2; mt++) {
            const int r = m0 + mw*32 + mt*16 + g;
            float* Cp = C + (size_t)r * 256 + c;
            Cp[0] = acc[mt][nt][0] + bx;
            Cp[1] = acc[mt][nt][1] + by;
            Cp[(size_t)8*256]     = acc[mt][nt][2] + bx;
            Cp[(size_t)8*256 + 1] = acc[mt][nt][3] + by;
        }
    }
}

// ---------------- mega kernel: knn (512) + QKV (1536) + AB (256) ----------------
__global__ void __launch_bounds__(256) mega_kernel(
        const float* __restrict__ coords, int* __restrict__ knn_out,
        const __nv_bfloat16* __restrict__ tokh, const __nv_bfloat16* __restrict__ tokl,
        const __nv_bfloat16* __restrict__ wth,  const __nv_bfloat16* __restrict__ wtl,
        const float* __restrict__ bq, const float* __restrict__ bk, const float* __restrict__ bv,
        float* __restrict__ gQ, float* __restrict__ gK, float* __restrict__ gV,
        const float* __restrict__ tok, const float* __restrict__ W1,
        const float* __restrict__ b1, float* __restrict__ gA, float* __restrict__ gB) {
    __shared__ __align__(16) char smem_u[SMEM_UNION_BYTES];
    const int bid = blockIdx.x;
    if (bid < 512) {
        // knn: the long pole — dispatched first
        knn_body(bid & 127, bid >> 7, coords, knn_out, smem_u);
    } else if (bid < 2048) {
        const int q = bid - 512;            // 0..1535
        const int z = q / 512;              // matrix 0..2
        const int r = q % 512;
        const float* bias = (z == 0) ? bq : (z == 1) ? bk : bv;
        float*       C    = (z == 0) ? gQ : (z == 1) ? gK : gV;
        tc_gemm_tile_v2(tokh, tokl, wth + (size_t)z * 65536, wtl + (size_t)z * 65536,
                        bias, C, (r & 127) * 128, (r >> 7) * 64, smem_u);
    } else {
        const int a = bid - 2048;           // 0..255
        const int z = a >> 7;               // 0 -> A, 1 -> B
        const float* W    = z ? (W1 + 256*HIDN) : W1;
        const float* bias = z ? nullptr : b1;
        float*       C    = z ? gB : gA;
        gemm_tile_f32(tok, W, bias, C, HIDN, HIDN, (a & 127) * 128, 0, smem_u);
    }
}

// ---------------- O projection (separate: needs ctx) ----------------
__global__ void __launch_bounds__(256) tc_o_kernel(
        const __nv_bfloat16* __restrict__ ctxh, const __nv_bfloat16* __restrict__ ctxl,
        const __nv_bfloat16* __restrict__ wth,  const __nv_bfloat16* __restrict__ wtl,
        const float* __restrict__ bo, float* __restrict__ out) {
    __shared__ __align__(16) char smem_u[SMEM_UNION_BYTES];
    tc_gemm_tile_v2(ctxh, ctxl, wth + (size_t)3 * 65536, wtl + (size_t)3 * 65536,
                    bo, out, blockIdx.x * 128, blockIdx.y * 64, smem_u);
}

// ---------------- fused score + top-4 select + attention ----------------
__global__ void score_attn_kernel(const float* __restrict__ coords,
                                  const float* __restrict__ W1,
                                  const float* __restrict__ W2,
                                  const int* __restrict__ knn,
                                  const float* __restrict__ gA,
                                  const float* __restrict__ gB,
                                  const float* __restrict__ gQ,
                                  const float* __restrict__ gK,
                                  const float* __restrict__ gV,
                                  __nv_bfloat16* __restrict__ ctxh,
                                  __nv_bfloat16* __restrict__ ctxl) {
    __shared__ float sW1c[3][64];
    __shared__ float sW2[64];
    const int t = threadIdx.x;
    if (t < 64) {
        sW2[t]     = W2[t];
        sW1c[0][t] = W1[512*64 + t];
        sW1c[1][t] = W1[513*64 + t];
        sW1c[2][t] = W1[514*64 + t];
    }
    __syncthreads();

    const int warp = t >> 5, lane = t & 31;
    const int g = blockIdx.x * 8 + warp;
    const int b = g >> 12;
    const int i = g & 4095;
    const float* coo = coords + (size_t)b * VOX * 3;
    const float xi = coo[3*i+0], yi = coo[3*i+1], zi = coo[3*i+2];

    const float a0  = gA[(size_t)g*64 + lane];
    const float a1  = gA[(size_t)g*64 + lane + 32];
    const float w2a = sW2[lane], w2b = sW2[lane + 32];
    const float c0a = sW1c[0][lane], c0b = sW1c[0][lane+32];
    const float c1a = sW1c[1][lane], c1b = sW1c[1][lane+32];
    const float c2a = sW1c[2][lane], c2b = sW1c[2][lane+32];

    float bs[TOPK_N] = {-1e30f, -1e30f, -1e30f, -1e30f};
    int   bj[TOPK_N] = {0, 0, 0, 0};

#pragma unroll
    for (int nb = 0; nb < KNN_N; nb++) {
        const int j = knn[g*KNN_N + nb];
        const float rx = coo[3*j+0] - xi;
        const float ry = coo[3*j+1] - yi;
        const float rz = coo[3*j+2] - zi;
        const float* Bj = gB + ((size_t)(b << 12) + j) * 64;
        float h0 = a0 + Bj[lane]      + rx*c0a + ry*c1a + rz*c2a;
        float h1 = a1 + Bj[lane + 32] + rx*c0b + ry*c1b + rz*c2b;
        h0 = fmaxf(h0, 0.0f);
        h1 = fmaxf(h1, 0.0f);
        float p = h0 * w2a + h1 * w2b;
#pragma unroll
        for (int off = 16; off; off >>= 1) p += __shfl_xor_sync(0xffffffffu, p, off);
        float cs = p; int cj = j;
#pragma unroll
        for (int k = 0; k < TOPK_N; k++) {
            const bool better = cs > bs[k];
            const float ts = better ? bs[k] : cs;
            const int   tj = better ? bj[k] : cj;
            bs[k] = better ? cs : bs[k];
            bj[k] = better ? cj : bj[k];
            cs = ts; cj = tj;
        }
    }

    const size_t base = (size_t)g * DIM + lane * 8;
    const float4 q0 = *(const float4*)(gQ + base);
    const float4 q1 = *(const float4*)(gQ + base + 4);

    float att[TOPK_N];
#pragma unroll
    for (int s = 0; s < TOPK_N; s++) {
        const size_t jb = ((size_t)(b << 12) + bj[s]) * DIM + lane * 8;
        const float4* Kp = (const float4*)(gK + jb);
        const float4 k0 = Kp[0], k1 = Kp[1];
        float p = q0.x*k0.x + q0.y*k0.y + q0.z*k0.z + q0.w*k0.w
                + q1.x*k1.x + q1.y*k1.y + q1.z*k1.z + q1.w*k1.w;
        p += __shfl_xor_sync(0xffffffffu, p, 4);
        p += __shfl_xor_sync(0xffffffffu, p, 2);
        p += __shfl_xor_sync(0xffffffffu, p, 1);
        att[s] = p * 0.125f;
    }
    float m = fmaxf(fmaxf(att[0], att[1]), fmaxf(att[2], att[3]));
    float e[TOPK_N], ssum = 0.0f;
#pragma unroll
    for (int s = 0; s < TOPK_N; s++) { e[s] = expf(att[s] - m); ssum += e[s]; }
    const float inv = 1.0f / ssum;

    float cv[8] = {0.f,0.f,0.f,0.f,0.f,0.f,0.f,0.f};
#pragma unroll
    for (int s = 0; s < TOPK_N; s++) {
        const float w = e[s] * inv;
        const size_t jb = ((size_t)(b << 12) + bj[s]) * DIM + lane * 8;
        const float4* Vp = (const float4*)(gV + jb);
        const float4 v0 = Vp[0], v1 = Vp[1];
        cv[0] += w*v0.x; cv[1] += w*v0.y; cv[2] += w*v0.z; cv[3] += w*v0.w;
        cv[4] += w*v1.x; cv[5] += w*v1.y; cv[6] += w*v1.z; cv[7] += w*v1.w;
    }
    uint32_t uh[4], ul[4];
#pragma unroll
    for (int q = 0; q < 4; q++) {
        __nv_bfloat16 h0 = __float2bfloat16(cv[2*q]);
        __nv_bfloat16 h1 = __float2bfloat16(cv[2*q+1]);
        __nv_bfloat16 l0 = __float2bfloat16(cv[2*q]   - __bfloat162float(h0));
        __nv_bfloat16 l1 = __float2bfloat16(cv[2*q+1] - __bfloat162float(h1));
        __nv_bfloat162 ph(h0, h1), pl(l0, l1);
        uh[q] = *(uint32_t*)&ph;
        ul[q] = *(uint32_t*)&pl;
    }
    *(uint4*)(ctxh + base) = make_uint4(uh[0], uh[1], uh[2], uh[3]);
    *(uint4*)(ctxl + base) = make_uint4(ul[0], ul[1], ul[2], ul[3]);
}

// ---------------- launch ----------------
extern "C" void kernel_launch(void* const* d_in, const int* in_sizes, int n_in,
                              void* d_out, int out_size) {
    const float* tok    = (const float*)d_in[0];
    const float* coords = (const float*)d_in[1];
    const float* W1 = (const float*)d_in[3];
    const float* b1 = (const float*)d_in[4];
    const float* W2 = (const float*)d_in[5];
    const float* Wq = (const float*)d_in[7];
    const float* bq = (const float*)d_in[8];
    const float* Wk = (const float*)d_in[9];
    const float* bk = (const float*)d_in[10];
    const float* Wv = (const float*)d_in[11];
    const float* bv = (const float*)d_in[12];
    const float* Wo = (const float*)d_in[13];
    const float* bo = (const float*)d_in[14];
    float* out = (float*)d_out;

    void* bufp = nullptr;
    cudaGetSymbolAddress(&bufp, g_buf);
    float* buf = (float*)bufp;
    float* gA   = buf + OFF_A;
    float* gB   = buf + OFF_B;
    float* gQ   = buf + OFF_Q;
    float* gK   = buf + OFF_K;
    float* gV   = buf + OFF_V;
    int*   gknn = (int*)(buf + OFF_KNN);
    __nv_bfloat16* ctxh = (__nv_bfloat16*)(buf + OFF_CTXH);
    __nv_bfloat16* ctxl = (__nv_bfloat16*)(buf + OFF_CTXL);
    __nv_bfloat16* tokh = (__nv_bfloat16*)(buf + OFF_TOKH);
    __nv_bfloat16* tokl = (__nv_bfloat16*)(buf + OFF_TOKL);
    __nv_bfloat16* wth  = (__nv_bfloat16*)(buf + OFF_WTH);
    __nv_bfloat16* wtl  = (__nv_bfloat16*)(buf + OFF_WTL);

    // #0..#2: split-convert (3 small launches so mega lands at ncu slot 3)
    convert_tok_kernel<<<4096, 256>>>(tok, tokh, tokl);
    convert_w_kernel<<<128, 256>>>(Wq, Wk, wth, wtl);
    convert_w_kernel<<<128, 256>>>(Wv, Wo, wth + 2*65536, wtl + 2*65536);
    // #3: mega — knn + Q/K/V + A/B co-resident  <-- ncu capture slot
    mega_kernel<<<2304, 256>>>(coords, gknn, tokh, tokl, wth, wtl,
                               bq, bk, bv, gQ, gK, gV, tok, W1, b1, gA, gB);
    // #4: fused score + select + attention (writes split ctx)
    score_attn_kernel<<<GTOT/8, 256>>>(coords, W1, W2, gknn, gA, gB, gQ, gK, gV, ctxh, ctxl);
    // #5: output projection
    tc_o_kernel<<<dim3(GTOT/128, DIM/64), 256>>>(ctxh, ctxl, wth, wtl, bo, out);
}

// round 11
// speedup vs baseline: 2.9267x; 1.0938x over previous
#include <cuda_runtime.h>
#include <cuda_bf16.h>
#include <cstdint>

#define BATCH 4
#define VOX   4096
#define DIM   256
#define HIDN  64
#define KNN_N 10
#define TOPK_N 4
#define GTOT  (BATCH*VOX)   // 16384

// ---------------- device scratch (float units) ----------------
#define OFF_A    0
#define OFF_B    1048576
#define OFF_Q    2097152
#define OFF_K    6291456
#define OFF_V    10485760
#define OFF_CTXH 14680064              // 16384*256 halves
#define OFF_CTXL 16777216
#define OFF_KNN  18874368              // 16384*10 ints
#define OFF_TOKH 19038208              // 16384*256 halves
#define OFF_TOKL 21135360
#define OFF_WTH  23232512              // 4*256*256 halves (transposed W's)
#define OFF_WTL  23363584
#define BUF_TOTAL 23494656

static __device__ float g_buf[BUF_TOTAL];

// ---------------- cp.async helpers ----------------
__device__ __forceinline__ uint32_t smem_u32(const void* p) {
    return (uint32_t)__cvta_generic_to_shared(p);
}
__device__ __forceinline__ void cp16(uint32_t dst, const void* src) {
    asm volatile("cp.async.cg.shared.global [%0], [%1], 16;\n" :: "r"(dst), "l"(src));
}
__device__ __forceinline__ void cp_commit() {
    asm volatile("cp.async.commit_group;\n" ::: "memory");
}
template<int N> __device__ __forceinline__ void cp_wait() {
    asm volatile("cp.async.wait_group %0;\n" :: "n"(N) : "memory");
}

// ---------------- convert: tok -> split bf16 ----------------
__global__ void __launch_bounds__(256) convert_tok_kernel(
        const float* __restrict__ tok,
        __nv_bfloat16* __restrict__ tokh, __nv_bfloat16* __restrict__ tokl) {
    const int idx = blockIdx.x * 256 + threadIdx.x;    // float4 index
    const int m = idx >> 6;
    const int c = (idx & 63) * 4;
    float4 v = *(const float4*)(tok + (size_t)m * 256 + c);
    __nv_bfloat16* ph = tokh + (size_t)m * 256 + c;
    __nv_bfloat16* pl = tokl + (size_t)m * 256 + c;
    float vv[4] = {v.x, v.y, v.z, v.w};
#pragma unroll
    for (int q = 0; q < 4; q++) {
        __nv_bfloat16 h = __float2bfloat16(vv[q]);
        ph[q] = h;
        pl[q] = __float2bfloat16(vv[q] - __bfloat162float(h));
    }
}

// ---------------- convert: two W's -> transposed split bf16 ----------------
__global__ void __launch_bounds__(256) convert_w_kernel(
        const float* __restrict__ Wa, const float* __restrict__ Wb,
        __nv_bfloat16* __restrict__ oh_base, __nv_bfloat16* __restrict__ ol_base) {
    const int elem = blockIdx.x * 1024 + threadIdx.x * 4;
    const int mat = elem >> 16;            // 0 or 1
    const int rem = elem & 65535;
    const int n = rem >> 8;
    const int k = rem & 255;
    const float* Wm = mat ? Wb : Wa;
    __nv_bfloat16* oh = oh_base + (size_t)mat * 65536 + (size_t)n * 256 + k;
    __nv_bfloat16* ol = ol_base + (size_t)mat * 65536 + (size_t)n * 256 + k;
#pragma unroll
    for (int q = 0; q < 4; q++) {
        float v = Wm[(size_t)(k + q) * 256 + n];
        __nv_bfloat16 h = __float2bfloat16(v);
        oh[q] = h;
        ol[q] = __float2bfloat16(v - __bfloat162float(h));
    }
}

// ---------------- KNN kernel v6: 2 rows/warp, single pass, 1024 blocks ----------------
// Cross-lane sorted top-10 per row (lane k holds rank-k). Events via ballot +
// shfl_up insert. Full d = sqi + |pj|^2 - 2*dot (shifted form cancels; don't).
#define KCHUNK 1024
#define FULLM 0xffffffffu

#define KNN_EVENTS(e, v, iv, tau)                                          \
    {                                                                      \
        unsigned mm = __ballot_sync(FULLM, (e) < (tau));                   \
        while (mm) {                                                       \
            const int s = __ffs(mm) - 1; mm &= mm - 1;  /* ascending j */  \
            const float bd = __shfl_sync(FULLM, (e), s);                   \
            const int   bjj = jj - lane + s;                               \
            if (bd < (tau)) {  /* tau tightens within batch */             \
                const unsigned bal = __ballot_sync(FULLM, bd < (v));       \
                const int pp = __ffs(bal) - 1;                             \
                const float pv = __shfl_up_sync(FULLM, (v), 1);            \
                const int   pi = __shfl_up_sync(FULLM, (iv), 1);           \
                if (lane > pp)  { (v) = pv; (iv) = pi; }                   \
                if (lane == pp) { (v) = bd; (iv) = bjj; }                  \
                (tau) = __shfl_sync(FULLM, (v), 9);                        \
            }                                                              \
        }                                                                  \
    }

__global__ void __launch_bounds__(256) knn_kernel(const float* __restrict__ coords,
                                                  int* __restrict__ knn_out) {
    __shared__ float4 sp[KCHUNK];
    const int b = blockIdx.y;
    const float* coo = coords + (size_t)b * VOX * 3;
    const int warp = threadIdx.x >> 5;
    const int lane = threadIdx.x & 31;

    const int i0 = blockIdx.x * 16 + warp * 2;
    const float x0 = coo[3*i0+0], y0 = coo[3*i0+1], z0 = coo[3*i0+2];
    const float x1 = coo[3*i0+3], y1 = coo[3*i0+4], z1 = coo[3*i0+5];
    const float sq0 = x0*x0 + y0*y0 + z0*z0;
    const float sq1 = x1*x1 + y1*y1 + z1*z1;

    float v0 = 1e30f, v1 = 1e30f;
    int  iv0 = 0x7fffffff, iv1 = 0x7fffffff;
    float tau0 = 1e30f, tau1 = 1e30f;

    for (int c = 0; c < VOX / KCHUNK; c++) {
        __syncthreads();
        for (int j = threadIdx.x; j < KCHUNK; j += 256) {
            const int jj = c * KCHUNK + j;
            const float xx = coo[3*jj], yy = coo[3*jj+1], zz = coo[3*jj+2];
            sp[j] = make_float4(xx, yy, zz, xx*xx + yy*yy + zz*zz);
        }
        __syncthreads();

        const int jbase = c * KCHUNK;
        for (int j = lane; j < KCHUNK; j += 32) {
            const float4 p = sp[j];
            const int jj = jbase + j;
            float e0 = sq0 + p.w - 2.0f*(x0*p.x + y0*p.y + z0*p.z);
            float e1 = sq1 + p.w - 2.0f*(x1*p.x + y1*p.y + z1*p.z);
            if (jj == i0)     e0 = 1e30f;
            if (jj == i0 + 1) e1 = 1e30f;
            KNN_EVENTS(e0, v0, iv0, tau0)
            KNN_EVENTS(e1, v1, iv1, tau1)
        }
    }

    if (lane < KNN_N) {
        knn_out[((b << 12) + i0 + 0) * KNN_N + lane] = iv0;
        knn_out[((b << 12) + i0 + 1) * KNN_N + lane] = iv1;
    }
}

// ---------------- fp32 GEMM body (selection path; dynamic smem) ----------------
__device__ void gemm_tile_f32(const float* __restrict__ A,
        const float* __restrict__ W, const float* __restrict__ bias,
        float* __restrict__ C, int N, int ldw, int m0, int n0, char* smem) {
    float* As = (float*)smem;        // [2][16][132]
    float* Bs = As + 2*16*132;       // [2][16][64]
#define ASX(buf,k,m) As[((buf)*16 + (k))*132 + (m)]
#define BSX(buf,k,n) Bs[((buf)*16 + (k))*64 + (n)]

    const int t  = threadIdx.x;
    const int tx = t & 15;
    const int ty = t >> 4;
    const int kq = (t & 3) * 4;
    const int ma = t >> 2;
    const int kb = t >> 4;
    const int nb = (t & 15) * 4;

    const float* Ab = A + (size_t)m0 * 256;

    float4 ra0 = *(const float4*)(Ab + (size_t)ma * 256 + kq);
    float4 ra1 = *(const float4*)(Ab + (size_t)(ma + 64) * 256 + kq);
    float4 rb  = *(const float4*)(W + (size_t)kb * ldw + n0 + nb);

    float acc[8][4];
#pragma unroll
    for (int i = 0; i < 8; i++)
#pragma unroll
        for (int j = 0; j < 4; j++) acc[i][j] = 0.0f;

    ASX(0,kq+0,ma) = ra0.x; ASX(0,kq+1,ma) = ra0.y; ASX(0,kq+2,ma) = ra0.z; ASX(0,kq+3,ma) = ra0.w;
    ASX(0,kq+0,ma+64) = ra1.x; ASX(0,kq+1,ma+64) = ra1.y; ASX(0,kq+2,ma+64) = ra1.z; ASX(0,kq+3,ma+64) = ra1.w;
    *(float4*)&BSX(0,kb,nb) = rb;
    __syncthreads();

    int cur = 0;
#pragma unroll
    for (int k0 = 0; k0 < 256; k0 += 16) {
        const bool more = (k0 + 16) < 256;
        if (more) {
            ra0 = *(const float4*)(Ab + (size_t)ma * 256 + k0 + 16 + kq);
            ra1 = *(const float4*)(Ab + (size_t)(ma + 64) * 256 + k0 + 16 + kq);
            rb  = *(const float4*)(W + (size_t)(k0 + 16 + kb) * ldw + n0 + nb);
        }
#pragma unroll
        for (int k = 0; k < 16; k++) {
            float ra[8], rbv[4];
            float4 a0 = *(const float4*)&ASX(cur,k,ty*8);
            float4 a1 = *(const float4*)&ASX(cur,k,ty*8+4);
            ra[0]=a0.x; ra[1]=a0.y; ra[2]=a0.z; ra[3]=a0.w;
            ra[4]=a1.x; ra[5]=a1.y; ra[6]=a1.z; ra[7]=a1.w;
            float4 b4 = *(const float4*)&BSX(cur,k,tx*4);
            rbv[0]=b4.x; rbv[1]=b4.y; rbv[2]=b4.z; rbv[3]=b4.w;
#pragma unroll
            for (int i = 0; i < 8; i++)
#pragma unroll
                for (int j = 0; j < 4; j++)
                    acc[i][j] += ra[i] * rbv[j];
        }
        if (more) {
            const int nx = cur ^ 1;
            ASX(nx,kq+0,ma) = ra0.x; ASX(nx,kq+1,ma) = ra0.y; ASX(nx,kq+2,ma) = ra0.z; ASX(nx,kq+3,ma) = ra0.w;
            ASX(nx,kq+0,ma+64) = ra1.x; ASX(nx,kq+1,ma+64) = ra1.y; ASX(nx,kq+2,ma+64) = ra1.z; ASX(nx,kq+3,ma+64) = ra1.w;
            *(float4*)&BSX(nx,kb,nb) = rb;
        }
        __syncthreads();
        cur ^= 1;
    }

    float4 bv = make_float4(0.f, 0.f, 0.f, 0.f);
    if (bias) bv = *(const float4*)(bias + n0 + tx*4);
#pragma unroll
    for (int i = 0; i < 8; i++) {
        const int row = m0 + ty*8 + i;
        float4 o;
        o.x = acc[i][0] + bv.x;
        o.y = acc[i][1] + bv.y;
        o.z = acc[i][2] + bv.z;
        o.w = acc[i][3] + bv.w;
        *(float4*)(C + (size_t)row * N + n0 + tx*4) = o;
    }
#undef ASX
#undef BSX
}

// ---------------- split-bf16 tensor-core GEMM v3: cp.async double-buffer ----------------
__device__ __forceinline__ void mma_bf16(float* c, const uint32_t* a, const uint32_t* b) {
    asm volatile(
        "mma.sync.aligned.m16n8k16.row.col.f32.bf16.bf16.f32 "
        "{%0,%1,%2,%3}, {%4,%5,%6,%7}, {%8,%9}, {%0,%1,%2,%3};\n"
        : "+f"(c[0]), "+f"(c[1]), "+f"(c[2]), "+f"(c[3])
        : "r"(a[0]), "r"(a[1]), "r"(a[2]), "r"(a[3]), "r"(b[0]), "r"(b[1]));
}

#define ASTRIDE 40           // halves; 80B row stride -> conflict-free
#define TCBUF_H 15360        // halves per buffer: Ah 5120 | Al 5120 | Bh 2560 | Bl 2560
#define TC_SMEM_BYTES (2 * TCBUF_H * 2)   // 61440

__device__ void tc_gemm_tile_v3(
        const __nv_bfloat16* __restrict__ Ahi, const __nv_bfloat16* __restrict__ Alo,
        const __nv_bfloat16* __restrict__ Bth, const __nv_bfloat16* __restrict__ Btl,
        const float* __restrict__ bias, float* __restrict__ C, int m0, int n0,
        __nv_bfloat16* smem) {
    const int t    = threadIdx.x;
    const int warp = t >> 5;
    const int lane = t & 31;
    const int g    = lane >> 2;
    const int tg   = lane & 3;
    const int mw   = warp & 3;
    const int nw   = warp >> 2;

    const int ar = t >> 2;            // 0..63 (A rows ar, ar+64; B row ar)
    const int ao = (t & 3) * 8;       // 8-half segment

    const __nv_bfloat16* Ah_g = Ahi + (size_t)(m0 + ar) * 256 + ao;
    const __nv_bfloat16* Al_g = Alo + (size_t)(m0 + ar) * 256 + ao;
    const __nv_bfloat16* Bh_g = Bth + (size_t)(n0 + ar) * 256 + ao;
    const __nv_bfloat16* Bl_g = Btl + (size_t)(n0 + ar) * 256 + ao;

    const uint32_t smem_b = smem_u32(smem);
    const uint32_t dA0 = smem_b + (ar*ASTRIDE + ao)*2;
    const uint32_t dA1 = smem_b + ((ar+64)*ASTRIDE + ao)*2;
    const uint32_t dL0 = smem_b + (5120 + ar*ASTRIDE + ao)*2;
    const uint32_t dL1 = smem_b + (5120 + (ar+64)*ASTRIDE + ao)*2;
    const uint32_t dBh = smem_b + (10240 + ar*ASTRIDE + ao)*2;
    const uint32_t dBl = smem_b + (12800 + ar*ASTRIDE + ao)*2;

    float acc[2][4][4];
#pragma unroll
    for (int mt = 0; mt < 2; mt++)
#pragma unroll
        for (int nt = 0; nt < 4; nt++)
#pragma unroll
            for (int e = 0; e < 4; e++) acc[mt][nt][e] = 0.0f;

#define TC_ISSUE(buf, kk)                                                   \
    {                                                                       \
        const uint32_t bo_ = (buf) * (TCBUF_H * 2);                         \
        cp16(dA0 + bo_, Ah_g + (kk));                                       \
        cp16(dA1 + bo_, Ah_g + (size_t)64*256 + (kk));                      \
        cp16(dL0 + bo_, Al_g + (kk));                                       \
        cp16(dL1 + bo_, Al_g + (size_t)64*256 + (kk));                      \
        cp16(dBh + bo_, Bh_g + (kk));                                       \
        cp16(dBl + bo_, Bl_g + (kk));                                       \
        cp_commit();                                                        \
    }

    TC_ISSUE(0, 0)
    int cur = 0;

#pragma unroll
    for (int k0 = 0; k0 < 256; k0 += 32) {
        const bool more = (k0 + 32) < 256;
        if (more) { TC_ISSUE(cur ^ 1, k0 + 32) cp_wait<1>(); }
        else      { cp_wait<0>(); }
        __syncthreads();

        const __nv_bfloat16* Ah = smem + cur * TCBUF_H;
        const __nv_bfloat16* Al = Ah + 5120;
        const __nv_bfloat16* Bh = Ah + 10240;
        const __nv_bfloat16* Bl = Ah + 12800;

#pragma unroll
        for (int ks = 0; ks < 32; ks += 16) {
            uint32_t ah[2][4], al[2][4];
#pragma unroll
            for (int mt = 0; mt < 2; mt++) {
                const int r = mw*32 + mt*16 + g;
                ah[mt][0] = *(const uint32_t*)&Ah[r*ASTRIDE + ks + 2*tg];
                ah[mt][1] = *(const uint32_t*)&Ah[(r+8)*ASTRIDE + ks + 2*tg];
                ah[mt][2] = *(const uint32_t*)&Ah[r*ASTRIDE + ks + 8 + 2*tg];
                ah[mt][3] = *(const uint32_t*)&Ah[(r+8)*ASTRIDE + ks + 8 + 2*tg];
                al[mt][0] = *(const uint32_t*)&Al[r*ASTRIDE + ks + 2*tg];
                al[mt][1] = *(const uint32_t*)&Al[(r+8)*ASTRIDE + ks + 2*tg];
                al[mt][2] = *(const uint32_t*)&Al[r*ASTRIDE + ks + 8 + 2*tg];
                al[mt][3] = *(const uint32_t*)&Al[(r+8)*ASTRIDE + ks + 8 + 2*tg];
            }
#pragma unroll
            for (int nt = 0; nt < 4; nt++) {
                const int n = nw*32 + nt*8 + g;
                uint32_t bh[2], bl[2];
                bh[0] = *(const uint32_t*)&Bh[n*ASTRIDE + ks + 2*tg];
                bh[1] = *(const uint32_t*)&Bh[n*ASTRIDE + ks + 8 + 2*tg];
                bl[0] = *(const uint32_t*)&Bl[n*ASTRIDE + ks + 2*tg];
                bl[1] = *(const uint32_t*)&Bl[n*ASTRIDE + ks + 8 + 2*tg];
#pragma unroll
                for (int mt = 0; mt < 2; mt++) {
                    mma_bf16(acc[mt][nt], ah[mt], bh);
                    mma_bf16(acc[mt][nt], ah[mt], bl);
                    mma_bf16(acc[mt][nt], al[mt], bh);
                }
            }
        }
        __syncthreads();
        cur ^= 1;
    }
#undef TC_ISSUE

#pragma unroll
    for (int nt = 0; nt < 4; nt++) {
        const int c = n0 + nw*32 + nt*8 + 2*tg;
        float bx = 0.f, by = 0.f;
        if (bias) { bx = bias[c]; by = bias[c+1]; }
#pragma unroll
        for (int mt = 0; mt < 2; mt++) {
            const int r = m0 + mw*32 + mt*16 + g;
            float* Cp = C + (size_t)r * 256 + c;
            Cp[0] = acc[mt][nt][0] + bx;
            Cp[1] = acc[mt][nt][1] + by;
            Cp[(size_t)8*256]     = acc[mt][nt][2] + bx;
            Cp[(size_t)8*256 + 1] = acc[mt][nt][3] + by;
        }
    }
}

// ---------------- QKV (tc) + AB (fp32) merged — matched reg footprints ----------------
__global__ void __launch_bounds__(256, 3) qkv_ab_kernel(
        const __nv_bfloat16* __restrict__ tokh, const __nv_bfloat16* __restrict__ tokl,
        const __nv_bfloat16* __restrict__ wth,  const __nv_bfloat16* __restrict__ wtl,
        const float* __restrict__ bq, const float* __restrict__ bk, const float* __restrict__ bv,
        float* __restrict__ gQ, float* __restrict__ gK, float* __restrict__ gV,
        const float* __restrict__ tok, const float* __restrict__ W1,
        const float* __restrict__ b1, float* __restrict__ gA, float* __restrict__ gB) {
    extern __shared__ __align__(16) char dynsmem[];
    const int bid = blockIdx.x;
    if (bid < 1536) {
        const int z = bid / 512;
        const int r = bid % 512;
        const float* bias = (z == 0) ? bq : (z == 1) ? bk : bv;
        float*       C    = (z == 0) ? gQ : (z == 1) ? gK : gV;
        tc_gemm_tile_v3(tokh, tokl, wth + (size_t)z * 65536, wtl + (size_t)z * 65536,
                        bias, C, (r & 127) * 128, (r >> 7) * 64,
                        (__nv_bfloat16*)dynsmem);
    } else {
        const int a = bid - 1536;           // 0..255
        const int z = a >> 7;               // 0 -> A, 1 -> B
        const float* W    = z ? (W1 + 256*HIDN) : W1;
        const float* bias = z ? nullptr : b1;
        float*       C    = z ? gB : gA;
        gemm_tile_f32(tok, W, bias, C, HIDN, HIDN, (a & 127) * 128, 0, dynsmem);
    }
}

// ---------------- O projection ----------------
__global__ void __launch_bounds__(256, 3) tc_o_kernel(
        const __nv_bfloat16* __restrict__ ctxh, const __nv_bfloat16* __restrict__ ctxl,
        const __nv_bfloat16* __restrict__ wth,  const __nv_bfloat16* __restrict__ wtl,
        const float* __restrict__ bo, float* __restrict__ out) {
    extern __shared__ __align__(16) char dynsmem[];
    tc_gemm_tile_v3(ctxh, ctxl, wth + (size_t)3 * 65536, wtl + (size_t)3 * 65536,
                    bo, out, blockIdx.x * 128, blockIdx.y * 64,
                    (__nv_bfloat16*)dynsmem);
}

// ---------------- fused score + top-4 select + attention ----------------
__global__ void score_attn_kernel(const float* __restrict__ coords,
                                  const float* __restrict__ W1,
                                  const float* __restrict__ W2,
                                  const int* __restrict__ knn,
                                  const float* __restrict__ gA,
                                  const float* __restrict__ gB,
                                  const float* __restrict__ gQ,
                                  const float* __restrict__ gK,
                                  const float* __restrict__ gV,
                                  __nv_bfloat16* __restrict__ ctxh,
                                  __nv_bfloat16* __restrict__ ctxl) {
    __shared__ float sW1c[3][64];
    __shared__ float sW2[64];
    const int t = threadIdx.x;
    if (t < 64) {
        sW2[t]     = W2[t];
        sW1c[0][t] = W1[512*64 + t];
        sW1c[1][t] = W1[513*64 + t];
        sW1c[2][t] = W1[514*64 + t];
    }
    __syncthreads();

    const int warp = t >> 5, lane = t & 31;
    const int g = blockIdx.x * 8 + warp;
    const int b = g >> 12;
    const int i = g & 4095;
    const float* coo = coords + (size_t)b * VOX * 3;
    const float xi = coo[3*i+0], yi = coo[3*i+1], zi = coo[3*i+2];

    const float a0  = gA[(size_t)g*64 + lane];
    const float a1  = gA[(size_t)g*64 + lane + 32];
    const float w2a = sW2[lane], w2b = sW2[lane + 32];
    const float c0a = sW1c[0][lane], c0b = sW1c[0][lane+32];
    const float c1a = sW1c[1][lane], c1b = sW1c[1][lane+32];
    const float c2a = sW1c[2][lane], c2b = sW1c[2][lane+32];

    float bs[TOPK_N] = {-1e30f, -1e30f, -1e30f, -1e30f};
    int   bj[TOPK_N] = {0, 0, 0, 0};

#pragma unroll
    for (int nb = 0; nb < KNN_N; nb++) {
        const int j = knn[g*KNN_N + nb];
        const float rx = coo[3*j+0] - xi;
        const float ry = coo[3*j+1] - yi;
        const float rz = coo[3*j+2] - zi;
        const float* Bj = gB + ((size_t)(b << 12) + j) * 64;
        float h0 = a0 + Bj[lane]      + rx*c0a + ry*c1a + rz*c2a;
        float h1 = a1 + Bj[lane + 32] + rx*c0b + ry*c1b + rz*c2b;
        h0 = fmaxf(h0, 0.0f);
        h1 = fmaxf(h1, 0.0f);
        float p = h0 * w2a + h1 * w2b;
#pragma unroll
        for (int off = 16; off; off >>= 1) p += __shfl_xor_sync(0xffffffffu, p, off);
        float cs = p; int cj = j;
#pragma unroll
        for (int k = 0; k < TOPK_N; k++) {
            const bool better = cs > bs[k];
            const float ts = better ? bs[k] : cs;
            const int   tj = better ? bj[k] : cj;
            bs[k] = better ? cs : bs[k];
            bj[k] = better ? cj : bj[k];
            cs = ts; cj = tj;
        }
    }

    const size_t base = (size_t)g * DIM + lane * 8;
    const float4 q0 = *(const float4*)(gQ + base);
    const float4 q1 = *(const float4*)(gQ + base + 4);

    float att[TOPK_N];
#pragma unroll
    for (int s = 0; s < TOPK_N; s++) {
        const size_t jb = ((size_t)(b << 12) + bj[s]) * DIM + lane * 8;
        const float4* Kp = (const float4*)(gK + jb);
        const float4 k0 = Kp[0], k1 = Kp[1];
        float p = q0.x*k0.x + q0.y*k0.y + q0.z*k0.z + q0.w*k0.w
                + q1.x*k1.x + q1.y*k1.y + q1.z*k1.z + q1.w*k1.w;
        p += __shfl_xor_sync(0xffffffffu, p, 4);
        p += __shfl_xor_sync(0xffffffffu, p, 2);
        p += __shfl_xor_sync(0xffffffffu, p, 1);
        att[s] = p * 0.125f;
    }
    float m = fmaxf(fmaxf(att[0], att[1]), fmaxf(att[2], att[3]));
    float e[TOPK_N], ssum = 0.0f;
#pragma unroll
    for (int s = 0; s < TOPK_N; s++) { e[s] = expf(att[s] - m); ssum += e[s]; }
    const float inv = 1.0f / ssum;

    float cv[8] = {0.f,0.f,0.f,0.f,0.f,0.f,0.f,0.f};
#pragma unroll
    for (int s = 0; s < TOPK_N; s++) {
        const float w = e[s] * inv;
        const size_t jb = ((size_t)(b << 12) + bj[s]) * DIM + lane * 8;
        const float4* Vp = (const float4*)(gV + jb);
        const float4 v0 = Vp[0], v1 = Vp[1];
        cv[0] += w*v0.x; cv[1] += w*v0.y; cv[2] += w*v0.z; cv[3] += w*v0.w;
        cv[4] += w*v1.x; cv[5] += w*v1.y; cv[6] += w*v1.z; cv[7] += w*v1.w;
    }
    uint32_t uh[4], ul[4];
#pragma unroll
    for (int q = 0; q < 4; q++) {
        __nv_bfloat16 h0 = __float2bfloat16(cv[2*q]);
        __nv_bfloat16 h1 = __float2bfloat16(cv[2*q+1]);
        __nv_bfloat16 l0 = __float2bfloat16(cv[2*q]   - __bfloat162float(h0));
        __nv_bfloat16 l1 = __float2bfloat16(cv[2*q+1] - __bfloat162float(h1));
        __nv_bfloat162 ph(h0, h1), pl(l0, l1);
        uh[q] = *(uint32_t*)&ph;
        ul[q] = *(uint32_t*)&pl;
    }
    *(uint4*)(ctxh + base) = make_uint4(uh[0], uh[1], uh[2], uh[3]);
    *(uint4*)(ctxl + base) = make_uint4(ul[0], ul[1], ul[2], ul[3]);
}

// ---------------- launch ----------------
extern "C" void kernel_launch(void* const* d_in, const int* in_sizes, int n_in,
                              void* d_out, int out_size) {
    const float* tok    = (const float*)d_in[0];
    const float* coords = (const float*)d_in[1];
    const float* W1 = (const float*)d_in[3];
    const float* b1 = (const float*)d_in[4];
    const float* W2 = (const float*)d_in[5];
    const float* Wq = (const float*)d_in[7];
    const float* bq = (const float*)d_in[8];
    const float* Wk = (const float*)d_in[9];
    const float* bk = (const float*)d_in[10];
    const float* Wv = (const float*)d_in[11];
    const float* bv = (const float*)d_in[12];
    const float* Wo = (const float*)d_in[13];
    const float* bo = (const float*)d_in[14];
    float* out = (float*)d_out;

    void* bufp = nullptr;
    cudaGetSymbolAddress(&bufp, g_buf);
    float* buf = (float*)bufp;
    float* gA   = buf + OFF_A;
    float* gB   = buf + OFF_B;
    float* gQ   = buf + OFF_Q;
    float* gK   = buf + OFF_K;
    float* gV   = buf + OFF_V;
    int*   gknn = (int*)(buf + OFF_KNN);
    __nv_bfloat16* ctxh = (__nv_bfloat16*)(buf + OFF_CTXH);
    __nv_bfloat16* ctxl = (__nv_bfloat16*)(buf + OFF_CTXL);
    __nv_bfloat16* tokh = (__nv_bfloat16*)(buf + OFF_TOKH);
    __nv_bfloat16* tokl = (__nv_bfloat16*)(buf + OFF_TOKL);
    __nv_bfloat16* wth  = (__nv_bfloat16*)(buf + OFF_WTH);
    __nv_bfloat16* wtl  = (__nv_bfloat16*)(buf + OFF_WTL);

    cudaFuncSetAttribute(qkv_ab_kernel, cudaFuncAttributeMaxDynamicSharedMemorySize, TC_SMEM_BYTES);
    cudaFuncSetAttribute(tc_o_kernel,   cudaFuncAttributeMaxDynamicSharedMemorySize, TC_SMEM_BYTES);

    // #0..#2: split-convert
    convert_tok_kernel<<<4096, 256>>>(tok, tokh, tokl);
    convert_w_kernel<<<128, 256>>>(Wq, Wk, wth, wtl);
    convert_w_kernel<<<128, 256>>>(Wv, Wo, wth + 2*65536, wtl + 2*65536);
    // #3: QKV (tc, cp.async) + AB (fp32) merged  <-- ncu capture slot
    qkv_ab_kernel<<<1792, 256, TC_SMEM_BYTES>>>(tokh, tokl, wth, wtl,
                                                bq, bk, bv, gQ, gK, gV,
                                                tok, W1, b1, gA, gB);
    // #4: knn v6
    knn_kernel<<<dim3(256, 4), 256>>>(coords, gknn);
    // #5: fused score + select + attention (writes split ctx)
    score_attn_kernel<<<GTOT/8, 256>>>(coords, W1, W2, gknn, gA, gB, gQ, gK, gV, ctxh, ctxl);
    // #6: output projection
    tc_o_kernel<<<dim3(GTOT/128, DIM/64), 256, TC_SMEM_BYTES>>>(ctxh, ctxl, wth, wtl, bo, out);
}

// round 12
// speedup vs baseline: 2.9291x; 1.0008x over previous
#include <cuda_runtime.h>
#include <cuda_bf16.h>
#include <cstdint>

#define BATCH 4
#define VOX   4096
#define DIM   256
#define HIDN  64
#define KNN_N 10
#define TOPK_N 4
#define GTOT  (BATCH*VOX)   // 16384

// ---------------- device scratch (float units) ----------------
#define OFF_A    0
#define OFF_B    1048576
#define OFF_Q    2097152
#define OFF_K    6291456
#define OFF_V    10485760
#define OFF_CTXH 14680064              // 16384*256 halves
#define OFF_CTXL 16777216
#define OFF_KNN  18874368              // 16384*10 ints
#define OFF_TOKH 19038208              // 16384*256 halves
#define OFF_TOKL 21135360
#define OFF_WTH  23232512              // 4*256*256 halves (transposed W's)
#define OFF_WTL  23363584
#define BUF_TOTAL 23494656

static __device__ float g_buf[BUF_TOTAL];

// ---------------- cp.async helpers ----------------
__device__ __forceinline__ uint32_t smem_u32(const void* p) {
    return (uint32_t)__cvta_generic_to_shared(p);
}
__device__ __forceinline__ void cp16(uint32_t dst, const void* src) {
    asm volatile("cp.async.cg.shared.global [%0], [%1], 16;\n" :: "r"(dst), "l"(src));
}
__device__ __forceinline__ void cp_commit() {
    asm volatile("cp.async.commit_group;\n" ::: "memory");
}
template<int N> __device__ __forceinline__ void cp_wait() {
    asm volatile("cp.async.wait_group %0;\n" :: "n"(N) : "memory");
}

// ---------------- convert: tok -> split bf16 ----------------
__global__ void __launch_bounds__(256) convert_tok_kernel(
        const float* __restrict__ tok,
        __nv_bfloat16* __restrict__ tokh, __nv_bfloat16* __restrict__ tokl) {
    const int idx = blockIdx.x * 256 + threadIdx.x;    // float4 index
    const int m = idx >> 6;
    const int c = (idx & 63) * 4;
    float4 v = *(const float4*)(tok + (size_t)m * 256 + c);
    __nv_bfloat16* ph = tokh + (size_t)m * 256 + c;
    __nv_bfloat16* pl = tokl + (size_t)m * 256 + c;
    float vv[4] = {v.x, v.y, v.z, v.w};
#pragma unroll
    for (int q = 0; q < 4; q++) {
        __nv_bfloat16 h = __float2bfloat16(vv[q]);
        ph[q] = h;
        pl[q] = __float2bfloat16(vv[q] - __bfloat162float(h));
    }
}

// ---------------- convert: two W's -> transposed split bf16 ----------------
__global__ void __launch_bounds__(256) convert_w_kernel(
        const float* __restrict__ Wa, const float* __restrict__ Wb,
        __nv_bfloat16* __restrict__ oh_base, __nv_bfloat16* __restrict__ ol_base) {
    const int elem = blockIdx.x * 1024 + threadIdx.x * 4;
    const int mat = elem >> 16;            // 0 or 1
    const int rem = elem & 65535;
    const int n = rem >> 8;
    const int k = rem & 255;
    const float* Wm = mat ? Wb : Wa;
    __nv_bfloat16* oh = oh_base + (size_t)mat * 65536 + (size_t)n * 256 + k;
    __nv_bfloat16* ol = ol_base + (size_t)mat * 65536 + (size_t)n * 256 + k;
#pragma unroll
    for (int q = 0; q < 4; q++) {
        float v = Wm[(size_t)(k + q) * 256 + n];
        __nv_bfloat16 h = __float2bfloat16(v);
        oh[q] = h;
        ol[q] = __float2bfloat16(v - __bfloat162float(h));
    }
}

// ---------------- KNN kernel v6: 2 rows/warp, single pass, 1024 blocks ----------------
// Cross-lane sorted top-10 per row (lane k holds rank-k). Events via ballot +
// shfl_up insert. Full d = sqi + |pj|^2 - 2*dot (shifted form cancels; don't).
#define KCHUNK 1024
#define FULLM 0xffffffffu

#define KNN_EVENTS(e, v, iv, tau)                                          \
    {                                                                      \
        unsigned mm = __ballot_sync(FULLM, (e) < (tau));                   \
        while (mm) {                                                       \
            const int s = __ffs(mm) - 1; mm &= mm - 1;  /* ascending j */  \
            const float bd = __shfl_sync(FULLM, (e), s);                   \
            const int   bjj = jj - lane + s;                               \
            if (bd < (tau)) {  /* tau tightens within batch */             \
                const unsigned bal = __ballot_sync(FULLM, bd < (v));       \
                const int pp = __ffs(bal) - 1;                             \
                const float pv = __shfl_up_sync(FULLM, (v), 1);            \
                const int   pi = __shfl_up_sync(FULLM, (iv), 1);           \
                if (lane > pp)  { (v) = pv; (iv) = pi; }                   \
                if (lane == pp) { (v) = bd; (iv) = bjj; }                  \
                (tau) = __shfl_sync(FULLM, (v), 9);                        \
            }                                                              \
        }                                                                  \
    }

__global__ void __launch_bounds__(256) knn_kernel(const float* __restrict__ coords,
                                                  int* __restrict__ knn_out) {
    __shared__ float4 sp[KCHUNK];
    const int b = blockIdx.y;
    const float* coo = coords + (size_t)b * VOX * 3;
    const int warp = threadIdx.x >> 5;
    const int lane = threadIdx.x & 31;

    const int i0 = blockIdx.x * 16 + warp * 2;
    const float x0 = coo[3*i0+0], y0 = coo[3*i0+1], z0 = coo[3*i0+2];
    const float x1 = coo[3*i0+3], y1 = coo[3*i0+4], z1 = coo[3*i0+5];
    const float sq0 = x0*x0 + y0*y0 + z0*z0;
    const float sq1 = x1*x1 + y1*y1 + z1*z1;

    float v0 = 1e30f, v1 = 1e30f;
    int  iv0 = 0x7fffffff, iv1 = 0x7fffffff;
    float tau0 = 1e30f, tau1 = 1e30f;

    for (int c = 0; c < VOX / KCHUNK; c++) {
        __syncthreads();
        for (int j = threadIdx.x; j < KCHUNK; j += 256) {
            const int jj = c * KCHUNK + j;
            const float xx = coo[3*jj], yy = coo[3*jj+1], zz = coo[3*jj+2];
            sp[j] = make_float4(xx, yy, zz, xx*xx + yy*yy + zz*zz);
        }
        __syncthreads();

        const int jbase = c * KCHUNK;
        for (int j = lane; j < KCHUNK; j += 32) {
            const float4 p = sp[j];
            const int jj = jbase + j;
            float e0 = sq0 + p.w - 2.0f*(x0*p.x + y0*p.y + z0*p.z);
            float e1 = sq1 + p.w - 2.0f*(x1*p.x + y1*p.y + z1*p.z);
            if (jj == i0)     e0 = 1e30f;
            if (jj == i0 + 1) e1 = 1e30f;
            KNN_EVENTS(e0, v0, iv0, tau0)
            KNN_EVENTS(e1, v1, iv1, tau1)
        }
    }

    if (lane < KNN_N) {
        knn_out[((b << 12) + i0 + 0) * KNN_N + lane] = iv0;
        knn_out[((b << 12) + i0 + 1) * KNN_N + lane] = iv1;
    }
}

// ---------------- fp32 GEMM body (selection path; dynamic smem) ----------------
__device__ void gemm_tile_f32(const float* __restrict__ A,
        const float* __restrict__ W, const float* __restrict__ bias,
        float* __restrict__ C, int N, int ldw, int m0, int n0, char* smem) {
    float* As = (float*)smem;        // [2][16][132]
    float* Bs = As + 2*16*132;       // [2][16][64]
#define ASX(buf,k,m) As[((buf)*16 + (k))*132 + (m)]
#define BSX(buf,k,n) Bs[((buf)*16 + (k))*64 + (n)]

    const int t  = threadIdx.x;
    const int tx = t & 15;
    const int ty = t >> 4;
    const int kq = (t & 3) * 4;
    const int ma = t >> 2;
    const int kb = t >> 4;
    const int nb = (t & 15) * 4;

    const float* Ab = A + (size_t)m0 * 256;

    float4 ra0 = *(const float4*)(Ab + (size_t)ma * 256 + kq);
    float4 ra1 = *(const float4*)(Ab + (size_t)(ma + 64) * 256 + kq);
    float4 rb  = *(const float4*)(W + (size_t)kb * ldw + n0 + nb);

    float acc[8][4];
#pragma unroll
    for (int i = 0; i < 8; i++)
#pragma unroll
        for (int j = 0; j < 4; j++) acc[i][j] = 0.0f;

    ASX(0,kq+0,ma) = ra0.x; ASX(0,kq+1,ma) = ra0.y; ASX(0,kq+2,ma) = ra0.z; ASX(0,kq+3,ma) = ra0.w;
    ASX(0,kq+0,ma+64) = ra1.x; ASX(0,kq+1,ma+64) = ra1.y; ASX(0,kq+2,ma+64) = ra1.z; ASX(0,kq+3,ma+64) = ra1.w;
    *(float4*)&BSX(0,kb,nb) = rb;
    __syncthreads();

    int cur = 0;
#pragma unroll
    for (int k0 = 0; k0 < 256; k0 += 16) {
        const bool more = (k0 + 16) < 256;
        if (more) {
            ra0 = *(const float4*)(Ab + (size_t)ma * 256 + k0 + 16 + kq);
            ra1 = *(const float4*)(Ab + (size_t)(ma + 64) * 256 + k0 + 16 + kq);
            rb  = *(const float4*)(W + (size_t)(k0 + 16 + kb) * ldw + n0 + nb);
        }
#pragma unroll
        for (int k = 0; k < 16; k++) {
            float ra[8], rbv[4];
            float4 a0 = *(const float4*)&ASX(cur,k,ty*8);
            float4 a1 = *(const float4*)&ASX(cur,k,ty*8+4);
            ra[0]=a0.x; ra[1]=a0.y; ra[2]=a0.z; ra[3]=a0.w;
            ra[4]=a1.x; ra[5]=a1.y; ra[6]=a1.z; ra[7]=a1.w;
            float4 b4 = *(const float4*)&BSX(cur,k,tx*4);
            rbv[0]=b4.x; rbv[1]=b4.y; rbv[2]=b4.z; rbv[3]=b4.w;
#pragma unroll
            for (int i = 0; i < 8; i++)
#pragma unroll
                for (int j = 0; j < 4; j++)
                    acc[i][j] += ra[i] * rbv[j];
        }
        if (more) {
            const int nx = cur ^ 1;
            ASX(nx,kq+0,ma) = ra0.x; ASX(nx,kq+1,ma) = ra0.y; ASX(nx,kq+2,ma) = ra0.z; ASX(nx,kq+3,ma) = ra0.w;
            ASX(nx,kq+0,ma+64) = ra1.x; ASX(nx,kq+1,ma+64) = ra1.y; ASX(nx,kq+2,ma+64) = ra1.z; ASX(nx,kq+3,ma+64) = ra1.w;
            *(float4*)&BSX(nx,kb,nb) = rb;
        }
        __syncthreads();
        cur ^= 1;
    }

    float4 bv = make_float4(0.f, 0.f, 0.f, 0.f);
    if (bias) bv = *(const float4*)(bias + n0 + tx*4);
#pragma unroll
    for (int i = 0; i < 8; i++) {
        const int row = m0 + ty*8 + i;
        float4 o;
        o.x = acc[i][0] + bv.x;
        o.y = acc[i][1] + bv.y;
        o.z = acc[i][2] + bv.z;
        o.w = acc[i][3] + bv.w;
        *(float4*)(C + (size_t)row * N + n0 + tx*4) = o;
    }
#undef ASX
#undef BSX
}

// ---------------- split-bf16 tensor-core GEMM v3: cp.async double-buffer ----------------
__device__ __forceinline__ void mma_bf16(float* c, const uint32_t* a, const uint32_t* b) {
    asm volatile(
        "mma.sync.aligned.m16n8k16.row.col.f32.bf16.bf16.f32 "
        "{%0,%1,%2,%3}, {%4,%5,%6,%7}, {%8,%9}, {%0,%1,%2,%3};\n"
        : "+f"(c[0]), "+f"(c[1]), "+f"(c[2]), "+f"(c[3])
        : "r"(a[0]), "r"(a[1]), "r"(a[2]), "r"(a[3]), "r"(b[0]), "r"(b[1]));
}

#define ASTRIDE 40           // halves; 80B row stride -> conflict-free
#define TCBUF_H 15360        // halves per buffer: Ah 5120 | Al 5120 | Bh 2560 | Bl 2560
#define TC_SMEM_BYTES (2 * TCBUF_H * 2)   // 61440

__device__ void tc_gemm_tile_v3(
        const __nv_bfloat16* __restrict__ Ahi, const __nv_bfloat16* __restrict__ Alo,
        const __nv_bfloat16* __restrict__ Bth, const __nv_bfloat16* __restrict__ Btl,
        const float* __restrict__ bias, float* __restrict__ C, int m0, int n0,
        __nv_bfloat16* smem) {
    const int t    = threadIdx.x;
    const int warp = t >> 5;
    const int lane = t & 31;
    const int g    = lane >> 2;
    const int tg   = lane & 3;
    const int mw   = warp & 3;
    const int nw   = warp >> 2;

    const int ar = t >> 2;            // 0..63 (A rows ar, ar+64; B row ar)
    const int ao = (t & 3) * 8;       // 8-half segment

    const __nv_bfloat16* Ah_g = Ahi + (size_t)(m0 + ar) * 256 + ao;
    const __nv_bfloat16* Al_g = Alo + (size_t)(m0 + ar) * 256 + ao;
    const __nv_bfloat16* Bh_g = Bth + (size_t)(n0 + ar) * 256 + ao;
    const __nv_bfloat16* Bl_g = Btl + (size_t)(n0 + ar) * 256 + ao;

    const uint32_t smem_b = smem_u32(smem);
    const uint32_t dA0 = smem_b + (ar*ASTRIDE + ao)*2;
    const uint32_t dA1 = smem_b + ((ar+64)*ASTRIDE + ao)*2;
    const uint32_t dL0 = smem_b + (5120 + ar*ASTRIDE + ao)*2;
    const uint32_t dL1 = smem_b + (5120 + (ar+64)*ASTRIDE + ao)*2;
    const uint32_t dBh = smem_b + (10240 + ar*ASTRIDE + ao)*2;
    const uint32_t dBl = smem_b + (12800 + ar*ASTRIDE + ao)*2;

    float acc[2][4][4];
#pragma unroll
    for (int mt = 0; mt < 2; mt++)
#pragma unroll
        for (int nt = 0; nt < 4; nt++)
#pragma unroll
            for (int e = 0; e < 4; e++) acc[mt][nt][e] = 0.0f;

#define TC_ISSUE(buf, kk)                                                   \
    {                                                                       \
        const uint32_t bo_ = (buf) * (TCBUF_H * 2);                         \
        cp16(dA0 + bo_, Ah_g + (kk));                                       \
        cp16(dA1 + bo_, Ah_g + (size_t)64*256 + (kk));                      \
        cp16(dL0 + bo_, Al_g + (kk));                                       \
        cp16(dL1 + bo_, Al_g + (size_t)64*256 + (kk));                      \
        cp16(dBh + bo_, Bh_g + (kk));                                       \
        cp16(dBl + bo_, Bl_g + (kk));                                       \
        cp_commit();                                                        \
    }

    TC_ISSUE(0, 0)
    int cur = 0;

#pragma unroll
    for (int k0 = 0; k0 < 256; k0 += 32) {
        const bool more = (k0 + 32) < 256;
        if (more) { TC_ISSUE(cur ^ 1, k0 + 32) cp_wait<1>(); }
        else      { cp_wait<0>(); }
        __syncthreads();

        const __nv_bfloat16* Ah = smem + cur * TCBUF_H;
        const __nv_bfloat16* Al = Ah + 5120;
        const __nv_bfloat16* Bh = Ah + 10240;
        const __nv_bfloat16* Bl = Ah + 12800;

#pragma unroll
        for (int ks = 0; ks < 32; ks += 16) {
            uint32_t ah[2][4], al[2][4];
#pragma unroll
            for (int mt = 0; mt < 2; mt++) {
                const int r = mw*32 + mt*16 + g;
                ah[mt][0] = *(const uint32_t*)&Ah[r*ASTRIDE + ks + 2*tg];
                ah[mt][1] = *(const uint32_t*)&Ah[(r+8)*ASTRIDE + ks + 2*tg];
                ah[mt][2] = *(const uint32_t*)&Ah[r*ASTRIDE + ks + 8 + 2*tg];
                ah[mt][3] = *(const uint32_t*)&Ah[(r+8)*ASTRIDE + ks + 8 + 2*tg];
                al[mt][0] = *(const uint32_t*)&Al[r*ASTRIDE + ks + 2*tg];
                al[mt][1] = *(const uint32_t*)&Al[(r+8)*ASTRIDE + ks + 2*tg];
                al[mt][2] = *(const uint32_t*)&Al[r*ASTRIDE + ks + 8 + 2*tg];
                al[mt][3] = *(const uint32_t*)&Al[(r+8)*ASTRIDE + ks + 8 + 2*tg];
            }
#pragma unroll
            for (int nt = 0; nt < 4; nt++) {
                const int n = nw*32 + nt*8 + g;
                uint32_t bh[2], bl[2];
                bh[0] = *(const uint32_t*)&Bh[n*ASTRIDE + ks + 2*tg];
                bh[1] = *(const uint32_t*)&Bh[n*ASTRIDE + ks + 8 + 2*tg];
                bl[0] = *(const uint32_t*)&Bl[n*ASTRIDE + ks + 2*tg];
                bl[1] = *(const uint32_t*)&Bl[n*ASTRIDE + ks + 8 + 2*tg];
#pragma unroll
                for (int mt = 0; mt < 2; mt++) {
                    mma_bf16(acc[mt][nt], ah[mt], bh);
                    mma_bf16(acc[mt][nt], ah[mt], bl);
                    mma_bf16(acc[mt][nt], al[mt], bh);
                }
            }
        }
        __syncthreads();
        cur ^= 1;
    }
#undef TC_ISSUE

#pragma unroll
    for (int nt = 0; nt < 4; nt++) {
        const int c = n0 + nw*32 + nt*8 + 2*tg;
        float bx = 0.f, by = 0.f;
        if (bias) { bx = bias[c]; by = bias[c+1]; }
#pragma unroll
        for (int mt = 0; mt < 2; mt++) {
            const int r = m0 + mw*32 + mt*16 + g;
            float* Cp = C + (size_t)r * 256 + c;
            Cp[0] = acc[mt][nt][0] + bx;
            Cp[1] = acc[mt][nt][1] + by;
            Cp[(size_t)8*256]     = acc[mt][nt][2] + bx;
            Cp[(size_t)8*256 + 1] = acc[mt][nt][3] + by;
        }
    }
}

// ---------------- QKV (tc) + AB (fp32) merged — matched reg footprints ----------------
__global__ void __launch_bounds__(256, 3) qkv_ab_kernel(
        const __nv_bfloat16* __restrict__ tokh, const __nv_bfloat16* __restrict__ tokl,
        const __nv_bfloat16* __restrict__ wth,  const __nv_bfloat16* __restrict__ wtl,
        const float* __restrict__ bq, const float* __restrict__ bk, const float* __restrict__ bv,
        float* __restrict__ gQ, float* __restrict__ gK, float* __restrict__ gV,
        const float* __restrict__ tok, const float* __restrict__ W1,
        const float* __restrict__ b1, float* __restrict__ gA, float* __restrict__ gB) {
    extern __shared__ __align__(16) char dynsmem[];
    const int bid = blockIdx.x;
    if (bid < 1536) {
        const int z = bid / 512;
        const int r = bid % 512;
        const float* bias = (z == 0) ? bq : (z == 1) ? bk : bv;
        float*       C    = (z == 0) ? gQ : (z == 1) ? gK : gV;
        tc_gemm_tile_v3(tokh, tokl, wth + (size_t)z * 65536, wtl + (size_t)z * 65536,
                        bias, C, (r & 127) * 128, (r >> 7) * 64,
                        (__nv_bfloat16*)dynsmem);
    } else {
        const int a = bid - 1536;           // 0..255
        const int z = a >> 7;               // 0 -> A, 1 -> B
        const float* W    = z ? (W1 + 256*HIDN) : W1;
        const float* bias = z ? nullptr : b1;
        float*       C    = z ? gB : gA;
        gemm_tile_f32(tok, W, bias, C, HIDN, HIDN, (a & 127) * 128, 0, dynsmem);
    }
}

// ---------------- O projection ----------------
__global__ void __launch_bounds__(256, 3) tc_o_kernel(
        const __nv_bfloat16* __restrict__ ctxh, const __nv_bfloat16* __restrict__ ctxl,
        const __nv_bfloat16* __restrict__ wth,  const __nv_bfloat16* __restrict__ wtl,
        const float* __restrict__ bo, float* __restrict__ out) {
    extern __shared__ __align__(16) char dynsmem[];
    tc_gemm_tile_v3(ctxh, ctxl, wth + (size_t)3 * 65536, wtl + (size_t)3 * 65536,
                    bo, out, blockIdx.x * 128, blockIdx.y * 64,
                    (__nv_bfloat16*)dynsmem);
}

// ---------------- fused score + top-4 select + attention ----------------
__global__ void score_attn_kernel(const float* __restrict__ coords,
                                  const float* __restrict__ W1,
                                  const float* __restrict__ W2,
                                  const int* __restrict__ knn,
                                  const float* __restrict__ gA,
                                  const float* __restrict__ gB,
                                  const float* __restrict__ gQ,
                                  const float* __restrict__ gK,
                                  const float* __restrict__ gV,
                                  __nv_bfloat16* __restrict__ ctxh,
                                  __nv_bfloat16* __restrict__ ctxl) {
    __shared__ float sW1c[3][64];
    __shared__ float sW2[64];
    const int t = threadIdx.x;
    if (t < 64) {
        sW2[t]     = W2[t];
        sW1c[0][t] = W1[512*64 + t];
        sW1c[1][t] = W1[513*64 + t];
        sW1c[2][t] = W1[514*64 + t];
    }
    __syncthreads();

    const int warp = t >> 5, lane = t & 31;
    const int g = blockIdx.x * 8 + warp;
    const int b = g >> 12;
    const int i = g & 4095;
    const float* coo = coords + (size_t)b * VOX * 3;
    const float xi = coo[3*i+0], yi = coo[3*i+1], zi = coo[3*i+2];

    const float a0  = gA[(size_t)g*64 + lane];
    const float a1  = gA[(size_t)g*64 + lane + 32];
    const float w2a = sW2[lane], w2b = sW2[lane + 32];
    const float c0a = sW1c[0][lane], c0b = sW1c[0][lane+32];
    const float c1a = sW1c[1][lane], c1b = sW1c[1][lane+32];
    const float c2a = sW1c[2][lane], c2b = sW1c[2][lane+32];

    float bs[TOPK_N] = {-1e30f, -1e30f, -1e30f, -1e30f};
    int   bj[TOPK_N] = {0, 0, 0, 0};

#pragma unroll
    for (int nb = 0; nb < KNN_N; nb++) {
        const int j = knn[g*KNN_N + nb];
        const float rx = coo[3*j+0] - xi;
        const float ry = coo[3*j+1] - yi;
        const float rz = coo[3*j+2] - zi;
        const float* Bj = gB + ((size_t)(b << 12) + j) * 64;
        float h0 = a0 + Bj[lane]      + rx*c0a + ry*c1a + rz*c2a;
        float h1 = a1 + Bj[lane + 32] + rx*c0b + ry*c1b + rz*c2b;
        h0 = fmaxf(h0, 0.0f);
        h1 = fmaxf(h1, 0.0f);
        float p = h0 * w2a + h1 * w2b;
#pragma unroll
        for (int off = 16; off; off >>= 1) p += __shfl_xor_sync(0xffffffffu, p, off);
        float cs = p; int cj = j;
#pragma unroll
        for (int k = 0; k < TOPK_N; k++) {
            const bool better = cs > bs[k];
            const float ts = better ? bs[k] : cs;
            const int   tj = better ? bj[k] : cj;
            bs[k] = better ? cs : bs[k];
            bj[k] = better ? cj : bj[k];
            cs = ts; cj = tj;
        }
    }

    const size_t base = (size_t)g * DIM + lane * 8;
    const float4 q0 = *(const float4*)(gQ + base);
    const float4 q1 = *(const float4*)(gQ + base + 4);

    float att[TOPK_N];
#pragma unroll
    for (int s = 0; s < TOPK_N; s++) {
        const size_t jb = ((size_t)(b << 12) + bj[s]) * DIM + lane * 8;
        const float4* Kp = (const float4*)(gK + jb);
        const float4 k0 = Kp[0], k1 = Kp[1];
        float p = q0.x*k0.x + q0.y*k0.y + q0.z*k0.z + q0.w*k0.w
                + q1.x*k1.x + q1.y*k1.y + q1.z*k1.z + q1.w*k1.w;
        p += __shfl_xor_sync(0xffffffffu, p, 4);
        p += __shfl_xor_sync(0xffffffffu, p, 2);
        p += __shfl_xor_sync(0xffffffffu, p, 1);
        att[s] = p * 0.125f;
    }
    float m = fmaxf(fmaxf(att[0], att[1]), fmaxf(att[2], att[3]));
    float e[TOPK_N], ssum = 0.0f;
#pragma unroll
    for (int s = 0; s < TOPK_N; s++) { e[s] = expf(att[s] - m); ssum += e[s]; }
    const float inv = 1.0f / ssum;

    float cv[8] = {0.f,0.f,0.f,0.f,0.f,0.f,0.f,0.f};
#pragma unroll
    for (int s = 0; s < TOPK_N; s++) {
        const float w = e[s] * inv;
        const size_t jb = ((size_t)(b << 12) + bj[s]) * DIM + lane * 8;
        const float4* Vp = (const float4*)(gV + jb);
        const float4 v0 = Vp[0], v1 = Vp[1];
        cv[0] += w*v0.x; cv[1] += w*v0.y; cv[2] += w*v0.z; cv[3] += w*v0.w;
        cv[4] += w*v1.x; cv[5] += w*v1.y; cv[6] += w*v1.z; cv[7] += w*v1.w;
    }
    uint32_t uh[4], ul[4];
#pragma unroll
    for (int q = 0; q < 4; q++) {
        __nv_bfloat16 h0 = __float2bfloat16(cv[2*q]);
        __nv_bfloat16 h1 = __float2bfloat16(cv[2*q+1]);
        __nv_bfloat16 l0 = __float2bfloat16(cv[2*q]   - __bfloat162float(h0));
        __nv_bfloat16 l1 = __float2bfloat16(cv[2*q+1] - __bfloat162float(h1));
        __nv_bfloat162 ph(h0, h1), pl(l0, l1);
        uh[q] = *(uint32_t*)&ph;
        ul[q] = *(uint32_t*)&pl;
    }
    *(uint4*)(ctxh + base) = make_uint4(uh[0], uh[1], uh[2], uh[3]);
    *(uint4*)(ctxl + base) = make_uint4(ul[0], ul[1], ul[2], ul[3]);
}

// ---------------- launch ----------------
extern "C" void kernel_launch(void* const* d_in, const int* in_sizes, int n_in,
                              void* d_out, int out_size) {
    const float* tok    = (const float*)d_in[0];
    const float* coords = (const float*)d_in[1];
    const float* W1 = (const float*)d_in[3];
    const float* b1 = (const float*)d_in[4];
    const float* W2 = (const float*)d_in[5];
    const float* Wq = (const float*)d_in[7];
    const float* bq = (const float*)d_in[8];
    const float* Wk = (const float*)d_in[9];
    const float* bk = (const float*)d_in[10];
    const float* Wv = (const float*)d_in[11];
    const float* bv = (const float*)d_in[12];
    const float* Wo = (const float*)d_in[13];
    const float* bo = (const float*)d_in[14];
    float* out = (float*)d_out;

    void* bufp = nullptr;
    cudaGetSymbolAddress(&bufp, g_buf);
    float* buf = (float*)bufp;
    float* gA   = buf + OFF_A;
    float* gB   = buf + OFF_B;
    float* gQ   = buf + OFF_Q;
    float* gK   = buf + OFF_K;
    float* gV   = buf + OFF_V;
    int*   gknn = (int*)(buf + OFF_KNN);
    __nv_bfloat16* ctxh = (__nv_bfloat16*)(buf + OFF_CTXH);
    __nv_bfloat16* ctxl = (__nv_bfloat16*)(buf + OFF_CTXL);
    __nv_bfloat16* tokh = (__nv_bfloat16*)(buf + OFF_TOKH);
    __nv_bfloat16* tokl = (__nv_bfloat16*)(buf + OFF_TOKL);
    __nv_bfloat16* wth  = (__nv_bfloat16*)(buf + OFF_WTH);
    __nv_bfloat16* wtl  = (__nv_bfloat16*)(buf + OFF_WTL);

    cudaFuncSetAttribute(qkv_ab_kernel, cudaFuncAttributeMaxDynamicSharedMemorySize, TC_SMEM_BYTES);
    cudaFuncSetAttribute(tc_o_kernel,   cudaFuncAttributeMaxDynamicSharedMemorySize, TC_SMEM_BYTES);

    // #0..#2: split-convert
    convert_tok_kernel<<<4096, 256>>>(tok, tokh, tokl);
    convert_w_kernel<<<128, 256>>>(Wq, Wk, wth, wtl);
    convert_w_kernel<<<128, 256>>>(Wv, Wo, wth + 2*65536, wtl + 2*65536);
    // #3: QKV (tc, cp.async) + AB (fp32) merged  <-- ncu capture slot
    qkv_ab_kernel<<<1792, 256, TC_SMEM_BYTES>>>(tokh, tokl, wth, wtl,
                                                bq, bk, bv, gQ, gK, gV,
                                                tok, W1, b1, gA, gB);
    // #4: knn v6
    knn_kernel<<<dim3(256, 4), 256>>>(coords, gknn);
    // #5: fused score + select + attention (writes split ctx)
    score_attn_kernel<<<GTOT/8, 256>>>(coords, W1, W2, gknn, gA, gB, gQ, gK, gV, ctxh, ctxl);
    // #6: output projection
    tc_o_kernel<<<dim3(GTOT/128, DIM/64), 256, TC_SMEM_BYTES>>>(ctxh, ctxl, wth, wtl, bo, out);
}